// round 6
// baseline (speedup 1.0000x reference)
#include <cuda_runtime.h>
#include <math.h>

#define N_  50000
#define E_  512000
#define IN_ 512
#define H_  128
#define NH_ (N_*H_)
#define DT_   0.1f
#define EPS_  1e-3f
#define TOL_  1e-4f
#define MAXIT_ 20

// ---------------- device scratch ----------------
__device__ __align__(16) float g_h[NH_];
__device__ __align__(16) float g_hs[NH_];
__device__ __align__(16) float g_X[NH_];
__device__ __align__(16) float g_R[NH_];
__device__ __align__(16) float g_P[NH_];
__device__ __align__(16) float g_AP[NH_];
__device__ __align__(16) float g_S[NH_];
__device__ __align__(16) float g_F[NH_];
__device__ float g_wL[E_];
__device__ float g_deg[N_];
__device__ float g_isd[N_];
__device__ int   g_cnt[N_];
__device__ int   g_ptr[N_ + 1];
__device__ int   g_adj[2 * E_];
__device__ float g_adjw[2 * E_];
__device__ int   g_incnt[N_];
__device__ int   g_inptr[N_ + 1];
__device__ int   g_insrc[E_ + N_];
__device__ float g_rs[H_], g_den[H_], g_rsn[H_], g_beta[H_];
__device__ int   g_flag;
__device__ float g_aq[4];
__device__ __align__(16) float g_xw1[N_ * 64];
__device__ float g_es1[N_ * 8], g_ed1[N_ * 8];
__device__ __align__(16) float g_o1[N_ * 64];
__device__ __align__(16) float g_xw2[N_ * 16];
__device__ float g_es2[N_], g_ed2[N_];

// ---------------- GEMM: C = A[M,K] @ B[K,Nc] (+bias) ----------------
__global__ __launch_bounds__(256) void gemm_k(const float* __restrict__ A,
    const float* __restrict__ B, const float* __restrict__ bias,
    float* __restrict__ C, int M, int Nc, int K)
{
    __shared__ float As[16][136];
    __shared__ float Bs[16][128];
    int tid = threadIdx.x, tx = tid & 15, ty = tid >> 4;
    int m0 = blockIdx.x * 128;
    float acc[8][8];
#pragma unroll
    for (int i = 0; i < 8; i++)
#pragma unroll
        for (int j = 0; j < 8; j++) acc[i][j] = 0.f;
    int ar = tid >> 2, ak = (tid & 3) << 2;
    int bk = tid >> 5, bc = (tid & 31) << 2;
    for (int k0 = 0; k0 < K; k0 += 16) {
#pragma unroll
        for (int h = 0; h < 2; h++) {
            int row = m0 + ar + h * 64;
            float4 v = make_float4(0.f, 0.f, 0.f, 0.f);
            if (row < M) v = *(const float4*)(A + (size_t)row * K + k0 + ak);
            As[ak + 0][ar + h * 64] = v.x; As[ak + 1][ar + h * 64] = v.y;
            As[ak + 2][ar + h * 64] = v.z; As[ak + 3][ar + h * 64] = v.w;
        }
#pragma unroll
        for (int h = 0; h < 2; h++) {
            int kk = bk + h * 8;
            float4 v = make_float4(0.f, 0.f, 0.f, 0.f);
            if (bc < Nc) v = *(const float4*)(B + (size_t)(k0 + kk) * Nc + bc);
            *(float4*)&Bs[kk][bc] = v;
        }
        __syncthreads();
#pragma unroll
        for (int k = 0; k < 16; k++) {
            float a[8], b[8];
            *(float4*)&a[0] = *(const float4*)&As[k][ty * 8];
            *(float4*)&a[4] = *(const float4*)&As[k][ty * 8 + 4];
            *(float4*)&b[0] = *(const float4*)&Bs[k][tx * 8];
            *(float4*)&b[4] = *(const float4*)&Bs[k][tx * 8 + 4];
#pragma unroll
            for (int i = 0; i < 8; i++)
#pragma unroll
                for (int j = 0; j < 8; j++) acc[i][j] += a[i] * b[j];
        }
        __syncthreads();
    }
#pragma unroll
    for (int i = 0; i < 8; i++) {
        int row = m0 + ty * 8 + i;
        if (row >= M) continue;
#pragma unroll
        for (int j = 0; j < 8; j++) {
            int cg = tx * 8 + j;
            if (cg < Nc) {
                float v = acc[i][j];
                if (bias) v += bias[cg];
                C[(size_t)row * Nc + cg] = v;
            }
        }
    }
}

// ---------------- LN + sigmoid -> g_h ----------------
__global__ void ln_sig_k(const float* __restrict__ in, const float* __restrict__ g,
                         const float* __restrict__ b)
{
    int row = blockIdx.x * 8 + (threadIdx.x >> 5);
    if (row >= N_) return;
    int lane = threadIdx.x & 31;
    float4 v = *(const float4*)(in + (size_t)row * H_ + lane * 4);
    float s = v.x + v.y + v.z + v.w;
#pragma unroll
    for (int o = 16; o; o >>= 1) s += __shfl_xor_sync(~0u, s, o);
    float mean = s * (1.f / H_);
    float dx = v.x - mean, dy = v.y - mean, dz = v.z - mean, dw = v.w - mean;
    float q = dx * dx + dy * dy + dz * dz + dw * dw;
#pragma unroll
    for (int o = 16; o; o >>= 1) q += __shfl_xor_sync(~0u, q, o);
    float rstd = rsqrtf(q * (1.f / H_) + 1e-5f);
    float4 gg = *(const float4*)(g + lane * 4);
    float4 bb = *(const float4*)(b + lane * 4);
    float4 o4;
    o4.x = 1.f / (1.f + expf(-(dx * rstd * gg.x + bb.x)));
    o4.y = 1.f / (1.f + expf(-(dy * rstd * gg.y + bb.y)));
    o4.z = 1.f / (1.f + expf(-(dz * rstd * gg.z + bb.z)));
    o4.w = 1.f / (1.f + expf(-(dw * rstd * gg.w + bb.w)));
    *(float4*)(g_h + (size_t)row * H_ + lane * 4) = o4;
}

// ---------------- edge weights + degree ----------------
__global__ void edge_w_k(const int* __restrict__ row, const int* __restrict__ col)
{
    int e = blockIdx.x * 8 + (threadIdx.x >> 5);
    if (e >= E_) return;
    int lane = threadIdx.x & 31;
    int r = row[e], c = col[e];
    float4 a = *(const float4*)(g_hs + ((size_t)r << 7) + (lane << 2));
    float4 b = *(const float4*)(g_hs + ((size_t)c << 7) + (lane << 2));
    float d0 = a.x - b.x, d1 = a.y - b.y, d2 = a.z - b.z, d3 = a.w - b.w;
    float sd = d0 * d0 + d1 * d1 + d2 * d2 + d3 * d3;
    float sa = a.x * a.x + a.y * a.y + a.z * a.z + a.w * a.w;
#pragma unroll
    for (int o = 16; o; o >>= 1) {
        sd += __shfl_xor_sync(~0u, sd, o);
        sa += __shfl_xor_sync(~0u, sa, o);
    }
    if (lane == 0) {
        float C  = sd * (1.f / 128.f);
        float ex = expf(-C * (1.f / EPS_));
        float P0 = fminf(fmaxf(ex, 1e-3f), 1.f);
        float Ps = fminf(fmaxf((P0 + 1e-12f) * ex, 1e-3f), 1.f);
        float w  = 0.7f * P0 + 0.3f * Ps;
        float wl = w * w * sa * (1.f / 128.f);
        g_wL[e] = wl;
        atomicAdd(&g_deg[r], wl);
        atomicAdd(&g_deg[c], wl);
    }
}

// ---------------- CSR build ----------------
__global__ void zero_i_k(int* p, int n) { int i = blockIdx.x * blockDim.x + threadIdx.x; if (i < n) p[i] = 0; }
__global__ void zero_f_k(float* p, int n) { int i = blockIdx.x * blockDim.x + threadIdx.x; if (i < n) p[i] = 0.f; }

__global__ void count_adj_k(const int* __restrict__ row, const int* __restrict__ col)
{
    int e = blockIdx.x * blockDim.x + threadIdx.x;
    if (e >= E_) return;
    atomicAdd(&g_cnt[row[e]], 1);
    atomicAdd(&g_cnt[col[e]], 1);
}
__global__ void scan_k(int* __restrict__ cnt, int* __restrict__ ptr, int n)
{
    __shared__ int sh[1024];
    int t = threadIdx.x;
    int chunk = (n + 1023) / 1024;
    int lo = t * chunk, hi = min(lo + chunk, n);
    if (lo > n) lo = n;
    int s = 0;
    for (int i = lo; i < hi; i++) s += cnt[i];
    sh[t] = s;
    __syncthreads();
    for (int off = 1; off < 1024; off <<= 1) {
        int v = (t >= off) ? sh[t - off] : 0;
        __syncthreads();
        sh[t] += v;
        __syncthreads();
    }
    int run = sh[t] - s;
    for (int i = lo; i < hi; i++) {
        int c = cnt[i];
        ptr[i] = run; cnt[i] = run; run += c;
    }
    if (t == 1023) ptr[n] = sh[1023];
}
__global__ void scatter_adj_k(const int* __restrict__ row, const int* __restrict__ col)
{
    int e = blockIdx.x * blockDim.x + threadIdx.x;
    if (e >= E_) return;
    int r = row[e], c = col[e];
    float w = g_wL[e];
    int p = atomicAdd(&g_cnt[r], 1); g_adj[p] = c; g_adjw[p] = w;
    int q = atomicAdd(&g_cnt[c], 1); g_adj[q] = r; g_adjw[q] = w;
}
__global__ void init_incnt_k() { int n = blockIdx.x * blockDim.x + threadIdx.x; if (n < N_) g_incnt[n] = 1; }
__global__ void count_in_k(const int* __restrict__ col)
{
    int e = blockIdx.x * blockDim.x + threadIdx.x;
    if (e < E_) atomicAdd(&g_incnt[col[e]], 1);
}
__global__ void scatter_in_k(const int* __restrict__ row, const int* __restrict__ col)
{
    int e = blockIdx.x * blockDim.x + threadIdx.x;
    if (e >= E_) return;
    int p = atomicAdd(&g_incnt[col[e]], 1);
    g_insrc[p] = row[e];
}
__global__ void scatter_self_k()
{
    int n = blockIdx.x * blockDim.x + threadIdx.x;
    if (n >= N_) return;
    int p = atomicAdd(&g_incnt[n], 1);
    g_insrc[p] = n;
}

// ---------------- CG ----------------
__global__ void vec_init_k()
{
    int i = blockIdx.x * blockDim.x + threadIdx.x;
    if (i < NH_) { float h = g_h[i]; g_X[i] = 0.f; g_R[i] = h; g_P[i] = h; }
}
__global__ void cg_init_k() { int c = threadIdx.x; g_rs[c] = 0.f; if (c == 0) g_flag = 0; }
__global__ void zero128_k() { int c = threadIdx.x; g_den[c] = 0.f; g_rsn[c] = 0.f; }

__global__ void coldot_k(const float* __restrict__ U, const float* __restrict__ V,
                         float* __restrict__ out)
{
    if (g_flag) return;
    int c = threadIdx.x;
    int r0 = blockIdx.x * 128, r1 = min(r0 + 128, N_);
    float acc = 0.f;
    for (int r = r0; r < r1; r++)
        acc += U[(size_t)r * H_ + c] * V[(size_t)r * H_ + c];
    atomicAdd(&out[c], acc);
}
__global__ void cg_spmv_k()
{
    if (g_flag) return;
    int node = blockIdx.x * 8 + (threadIdx.x >> 5);
    if (node >= N_) return;
    int lane = threadIdx.x & 31;
    int j0 = g_ptr[node], j1 = g_ptr[node + 1];
    float4 a0 = make_float4(0.f, 0.f, 0.f, 0.f);
    for (int j = j0; j < j1; j++) {
        int nb = g_adj[j]; float w = g_adjw[j];
        float4 v = *(const float4*)(g_P + ((size_t)nb << 7) + (lane << 2));
        a0.x += w * v.x; a0.y += w * v.y; a0.z += w * v.z; a0.w += w * v.w;
    }
    float c0 = 1.f + DT_ * g_deg[node];
    size_t base = ((size_t)node << 7) + (lane << 2);
    float4 p = *(const float4*)(g_P + base);
    float4 o;
    o.x = c0 * p.x - DT_ * a0.x; o.y = c0 * p.y - DT_ * a0.y;
    o.z = c0 * p.z - DT_ * a0.z; o.w = c0 * p.w - DT_ * a0.w;
    *(float4*)(g_AP + base) = o;
}
__global__ void cg_update_xr_k()
{
    if (g_flag) return;
    int c = threadIdx.x;
    float al = g_rs[c] / (g_den[c] + 1e-16f);
    int r0 = blockIdx.x * 128, r1 = min(r0 + 128, N_);
    float acc = 0.f;
    for (int r = r0; r < r1; r++) {
        size_t i = (size_t)r * H_ + c;
        g_X[i] += al * g_P[i];
        float rr = g_R[i] - al * g_AP[i];
        g_R[i] = rr;
        acc += rr * rr;
    }
    atomicAdd(&g_rsn[c], acc);
}
__global__ void cg_finalize_k()
{
    if (g_flag) return;
    int c = threadIdx.x;
    float rsn = g_rsn[c];
    g_beta[c] = rsn / (g_rs[c] + 1e-16f);
    g_rs[c] = rsn;
    __shared__ float sm[128];
    sm[c] = rsn;
    __syncthreads();
    for (int o = 64; o; o >>= 1) {
        if (c < o) sm[c] = fmaxf(sm[c], sm[c + o]);
        __syncthreads();
    }
    if (c == 0 && sm[0] < TOL_ * TOL_) g_flag = 1;
}
__global__ void cg_update_p_k()
{
    if (g_flag) return;
    int c = threadIdx.x;
    float be = g_beta[c];
    int r0 = blockIdx.x * 128, r1 = min(r0 + 128, N_);
    for (int r = r0; r < r1; r++) {
        size_t i = (size_t)r * H_ + c;
        g_P[i] = g_R[i] + be * g_P[i];
    }
}

// ---------------- AFM ----------------
__global__ void isd_k()
{
    int n = blockIdx.x * blockDim.x + threadIdx.x;
    if (n < N_) g_isd[n] = rsqrtf(fmaxf(g_deg[n], 1e-8f));
}
__global__ void scale_k(const float* __restrict__ M)
{
    int i = blockIdx.x * blockDim.x + threadIdx.x;
    if (i < NH_) g_S[i] = g_isd[i >> 7] * M[i];
}
// out = cA*(M + isd*(deg*S - sum w*S[nbr])) + cB*Mp
__global__ void cheb_k(const float* __restrict__ M, const float* __restrict__ Mp,
                       float* __restrict__ out, float cA, float cB)
{
    int node = blockIdx.x * 8 + (threadIdx.x >> 5);
    if (node >= N_) return;
    int lane = threadIdx.x & 31;
    int j0 = g_ptr[node], j1 = g_ptr[node + 1];
    float4 a0 = make_float4(0.f, 0.f, 0.f, 0.f);
    for (int j = j0; j < j1; j++) {
        int nb = g_adj[j]; float w = g_adjw[j];
        float4 v = *(const float4*)(g_S + ((size_t)nb << 7) + (lane << 2));
        a0.x += w * v.x; a0.y += w * v.y; a0.z += w * v.z; a0.w += w * v.w;
    }
    float is = g_isd[node], dg = g_deg[node];
    size_t base = ((size_t)node << 7) + (lane << 2);
    float4 m  = *(const float4*)(M + base);
    float4 s4 = *(const float4*)(g_S + base);
    float4 mp = *(const float4*)(Mp + base);
    float4 o;
    o.x = cA * (m.x + is * (dg * s4.x - a0.x)) + cB * mp.x;
    o.y = cA * (m.y + is * (dg * s4.y - a0.y)) + cB * mp.y;
    o.z = cA * (m.z + is * (dg * s4.z - a0.z)) + cB * mp.z;
    o.w = cA * (m.w + is * (dg * s4.w - a0.w)) + cB * mp.w;
    *(float4*)(out + base) = o;
}
__global__ void aq_k(const float* __restrict__ gamma)
{
    if (threadIdx.x == 0) {
        float m = gamma[0];
        for (int i = 1; i < 4; i++) m = fmaxf(m, gamma[i]);
        float e[4], s = 0.f;
        for (int i = 0; i < 4; i++) { e[i] = expf(gamma[i] - m); s += e[i]; }
        for (int i = 0; i < 4; i++) g_aq[i] = e[i] / s;
    }
}
__global__ void fuse_k(const float* __restrict__ asvr, const float* __restrict__ aafm)
{
    int i = blockIdx.x * blockDim.x + threadIdx.x;
    if (i >= NH_) return;
    float s1 = 1.f / (1.f + expf(-asvr[0]));
    float s2 = 1.f / (1.f + expf(-aafm[0]));
    float hafm = g_aq[0] * g_h[i] + g_aq[1] * g_R[i] + g_aq[2] * g_P[i] + g_aq[3] * g_AP[i];
    g_F[i] = g_h[i] + s1 * g_X[i] + s2 * hafm;
}

// ---------------- GAT 1 ----------------
__global__ void gat1_coeff_k(const float* __restrict__ a1s, const float* __restrict__ a1d)
{
    int i = blockIdx.x * blockDim.x + threadIdx.x;
    if (i >= N_ * 8) return;
    int n = i >> 3, h = i & 7;
    const float* xw = g_xw1 + (size_t)n * 64 + h * 8;
    float es = 0.f, ed = 0.f;
#pragma unroll
    for (int c = 0; c < 8; c++) { float v = xw[c]; es += v * a1s[h * 8 + c]; ed += v * a1d[h * 8 + c]; }
    g_es1[i] = es; g_ed1[i] = ed;
}
__global__ void gat1_agg_k(const float* __restrict__ b1)
{
    int node = blockIdx.x * 8 + (threadIdx.x >> 5);
    if (node >= N_) return;
    int lane = threadIdx.x & 31;
    int head = lane >> 2;
    int c0 = (lane & 3) * 2;
    float edv = g_ed1[(size_t)node * 8 + head];
    int j0 = g_inptr[node], j1 = g_inptr[node + 1];
    float m = -3.4e38f, den = 0.f, a0 = 0.f, a1 = 0.f;
    for (int j = j0; j < j1; j++) {
        int s = g_insrc[j];
        float e = g_es1[(size_t)s * 8 + head] + edv;
        e = e >= 0.f ? e : 0.2f * e;
        float mn = fmaxf(m, e);
        float sc = expf(m - mn);
        float p  = expf(e - mn);
        const float* xw = g_xw1 + (size_t)s * 64 + head * 8 + c0;
        den = den * sc + p;
        a0  = a0 * sc + p * xw[0];
        a1  = a1 * sc + p * xw[1];
        m = mn;
    }
    float inv = 1.f / (den + 1e-16f);
    float v0 = a0 * inv + b1[head * 8 + c0];
    float v1 = a1 * inv + b1[head * 8 + c0 + 1];
    v0 = v0 > 0.f ? v0 : expm1f(v0);
    v1 = v1 > 0.f ? v1 : expm1f(v1);
    float* o = g_o1 + (size_t)node * 64 + head * 8 + c0;
    o[0] = v0; o[1] = v1;
}

// ---------------- GAT 2 ----------------
__global__ void gat2_coeff_k(const float* __restrict__ a2s, const float* __restrict__ a2d)
{
    int n = blockIdx.x * blockDim.x + threadIdx.x;
    if (n >= N_) return;
    float es = 0.f, ed = 0.f;
#pragma unroll
    for (int c = 0; c < 16; c++) { float v = g_xw2[(size_t)n * 16 + c]; es += v * a2s[c]; ed += v * a2d[c]; }
    g_es2[n] = es; g_ed2[n] = ed;
}
__global__ void gat2_agg_k(const float* __restrict__ b2, float* __restrict__ out)
{
    int node = blockIdx.x * 16 + (threadIdx.x >> 4);
    if (node >= N_) return;
    int ch = threadIdx.x & 15;
    float edv = g_ed2[node];
    int j0 = g_inptr[node], j1 = g_inptr[node + 1];
    float m = -3.4e38f, den = 0.f, acc = 0.f;
    for (int j = j0; j < j1; j++) {
        int s = g_insrc[j];
        float e = g_es2[s] + edv;
        e = e >= 0.f ? e : 0.2f * e;
        float mn = fmaxf(m, e);
        float sc = expf(m - mn);
        float p  = expf(e - mn);
        den = den * sc + p;
        acc = acc * sc + p * g_xw2[(size_t)s * 16 + ch];
        m = mn;
    }
    out[(size_t)node * 16 + ch] = acc / (den + 1e-16f) + b2[ch];
}

// ---------------- host ----------------
#define SYM(p, s) do { void* _t; cudaGetSymbolAddress(&_t, s); p = (decltype(p))_t; } while(0)

extern "C" void kernel_launch(void* const* d_in, const int* in_sizes, int n_in,
                              void* d_out, int out_size)
{
    const float* x      = (const float*)d_in[0];
    const int*   ei     = (const int*)d_in[1];
    const float* W_in   = (const float*)d_in[2];
    const float* b_in   = (const float*)d_in[3];
    const float* ln_g   = (const float*)d_in[4];
    const float* ln_b   = (const float*)d_in[5];
    const float* W_sh   = (const float*)d_in[6];
    const float* gamma  = (const float*)d_in[7];
    const float* asvr   = (const float*)d_in[8];
    const float* aafm   = (const float*)d_in[9];
    const float* W1     = (const float*)d_in[10];
    const float* a1s    = (const float*)d_in[11];
    const float* a1d    = (const float*)d_in[12];
    const float* b1     = (const float*)d_in[13];
    const float* W2     = (const float*)d_in[14];
    const float* a2s    = (const float*)d_in[15];
    const float* a2d    = (const float*)d_in[16];
    const float* b2     = (const float*)d_in[17];
    const int* row = ei, * col = ei + E_;
    float* out = (float*)d_out;

    float *ph, *phs, *pX, *pR, *pP, *pAP, *pF, *pxw1, *po1, *pxw2, *pden, *pdeg, *prs;
    int *pcnt, *pptr, *pincnt, *pinptr;
    SYM(ph, g_h); SYM(phs, g_hs); SYM(pX, g_X); SYM(pR, g_R); SYM(pP, g_P);
    SYM(pAP, g_AP); SYM(pF, g_F); SYM(pxw1, g_xw1); SYM(po1, g_o1); SYM(pxw2, g_xw2);
    SYM(pden, g_den); SYM(pdeg, g_deg); SYM(prs, g_rs);
    SYM(pcnt, g_cnt); SYM(pptr, g_ptr); SYM(pincnt, g_incnt); SYM(pinptr, g_inptr);

    const int GB = 391;           // ceil(50000/128)
    zero_f_k<<<196, 256>>>(pdeg, N_);
    zero_i_k<<<196, 256>>>(pcnt, N_);

    // h = sigmoid(LN(x@W_in + b_in)); hs = h@W_sheaf
    gemm_k<<<GB, 256>>>(x, W_in, b_in, pF, N_, 128, 512);
    ln_sig_k<<<6250, 256>>>(pF, ln_g, ln_b);
    gemm_k<<<GB, 256>>>(ph, W_sh, nullptr, phs, N_, 128, 128);

    // edge weights + degrees
    edge_w_k<<<64000, 256>>>(row, col);

    // symmetric CSR
    count_adj_k<<<2000, 256>>>(row, col);
    scan_k<<<1, 1024>>>(pcnt, pptr, N_);
    scatter_adj_k<<<2000, 256>>>(row, col);
    // incoming CSR (with self-loops) for GAT
    init_incnt_k<<<196, 256>>>();
    count_in_k<<<2000, 256>>>(col);
    scan_k<<<1, 1024>>>(pincnt, pinptr, N_);
    scatter_in_k<<<2000, 256>>>(row, col);
    scatter_self_k<<<196, 256>>>();

    // CG solve (I + dt L) X = h
    vec_init_k<<<(NH_ + 255) / 256, 256>>>();
    cg_init_k<<<1, 128>>>();
    coldot_k<<<GB, 128>>>(ph, ph, prs);   // rs0 = per-column sum(h*h)
    for (int it = 0; it < MAXIT_; it++) {
        zero128_k<<<1, 128>>>();
        cg_spmv_k<<<6250, 256>>>();
        coldot_k<<<GB, 128>>>(pP, pAP, pden);
        cg_update_xr_k<<<GB, 128>>>();
        cg_finalize_k<<<1, 128>>>();
        cg_update_p_k<<<GB, 128>>>();
    }

    // AFM Chebyshev: T1 -> g_R, T2 -> g_P, T3 -> g_AP
    isd_k<<<196, 256>>>();
    scale_k<<<(NH_ + 255) / 256, 256>>>(ph);
    cheb_k<<<6250, 256>>>(ph, ph, pR, 1.f, 0.f);
    scale_k<<<(NH_ + 255) / 256, 256>>>(pR);
    cheb_k<<<6250, 256>>>(pR, ph, pP, 2.f, -1.f);
    scale_k<<<(NH_ + 255) / 256, 256>>>(pP);
    cheb_k<<<6250, 256>>>(pP, pR, pAP, 2.f, -1.f);
    aq_k<<<1, 32>>>(gamma);
    fuse_k<<<(NH_ + 255) / 256, 256>>>(asvr, aafm);

    // GAT layer 1
    gemm_k<<<GB, 256>>>(pF, W1, nullptr, pxw1, N_, 64, 128);
    gat1_coeff_k<<<(N_ * 8 + 255) / 256, 256>>>(a1s, a1d);
    gat1_agg_k<<<6250, 256>>>(b1);

    // GAT layer 2
    gemm_k<<<GB, 256>>>(po1, W2, nullptr, pxw2, N_, 16, 64);
    gat2_coeff_k<<<196, 256>>>(a2s, a2d);
    gat2_agg_k<<<3125, 256>>>(b2, out);
}

// round 8
// speedup vs baseline: 1.0964x; 1.0964x over previous
#include <cuda_runtime.h>
#include <math.h>

#define N_  50000
#define E_  512000
#define IN_ 512
#define H_  128
#define NH_ (N_*H_)
#define DT_   0.1f
#define EPS_  1e-3f
#define TOL_  1e-4f
#define MAXIT_ 20

// ---------------- device scratch ----------------
__device__ __align__(16) float g_h[NH_];
__device__ __align__(16) float g_hs[NH_];
__device__ __align__(16) float g_X[NH_];
__device__ __align__(16) float g_R[NH_];
__device__ __align__(16) float g_P[NH_];
__device__ __align__(16) float g_AP[NH_];
__device__ __align__(16) float g_F[NH_];
__device__ float g_wL[E_];
__device__ float g_deg[N_];
__device__ float g_isd[N_];
__device__ int   g_cnt[N_];
__device__ int   g_ptr[N_ + 1];
__device__ int   g_adj[2 * E_];
__device__ float g_adjw[2 * E_];
__device__ int   g_incnt[N_];
__device__ int   g_inptr[N_ + 1];
__device__ int   g_insrc[E_ + N_];
__device__ float g_rs[H_], g_den[H_], g_rsn[H_], g_beta[H_];
__device__ int   g_flag;
__device__ float g_aq[4];
__device__ __align__(16) float g_xw1[N_ * 64];
__device__ float g_es1[N_ * 8], g_ed1[N_ * 8];
__device__ __align__(16) float g_o1[N_ * 64];
__device__ __align__(16) float g_xw2[N_ * 16];
__device__ float g_es2[N_], g_ed2[N_];

// ---------------- generic GEMM: C = A[M,K] @ B[K,Nc] (+bias) ----------------
__global__ __launch_bounds__(256) void gemm_k(const float* __restrict__ A,
    const float* __restrict__ B, const float* __restrict__ bias,
    float* __restrict__ C, int M, int Nc, int K)
{
    __shared__ float As[16][136];
    __shared__ float Bs[16][128];
    int tid = threadIdx.x, tx = tid & 15, ty = tid >> 4;
    int m0 = blockIdx.x * 128;
    float acc[8][8];
#pragma unroll
    for (int i = 0; i < 8; i++)
#pragma unroll
        for (int j = 0; j < 8; j++) acc[i][j] = 0.f;
    int ar = tid >> 2, ak = (tid & 3) << 2;
    int bk = tid >> 5, bc = (tid & 31) << 2;
    for (int k0 = 0; k0 < K; k0 += 16) {
#pragma unroll
        for (int h = 0; h < 2; h++) {
            int row = m0 + ar + h * 64;
            float4 v = make_float4(0.f, 0.f, 0.f, 0.f);
            if (row < M) v = *(const float4*)(A + (size_t)row * K + k0 + ak);
            As[ak + 0][ar + h * 64] = v.x; As[ak + 1][ar + h * 64] = v.y;
            As[ak + 2][ar + h * 64] = v.z; As[ak + 3][ar + h * 64] = v.w;
        }
#pragma unroll
        for (int h = 0; h < 2; h++) {
            int kk = bk + h * 8;
            float4 v = make_float4(0.f, 0.f, 0.f, 0.f);
            if (bc < Nc) v = *(const float4*)(B + (size_t)(k0 + kk) * Nc + bc);
            *(float4*)&Bs[kk][bc] = v;
        }
        __syncthreads();
#pragma unroll
        for (int k = 0; k < 16; k++) {
            float a[8], b[8];
            *(float4*)&a[0] = *(const float4*)&As[k][ty * 8];
            *(float4*)&a[4] = *(const float4*)&As[k][ty * 8 + 4];
            *(float4*)&b[0] = *(const float4*)&Bs[k][tx * 8];
            *(float4*)&b[4] = *(const float4*)&Bs[k][tx * 8 + 4];
#pragma unroll
            for (int i = 0; i < 8; i++)
#pragma unroll
                for (int j = 0; j < 8; j++) acc[i][j] += a[i] * b[j];
        }
        __syncthreads();
    }
#pragma unroll
    for (int i = 0; i < 8; i++) {
        int row = m0 + ty * 8 + i;
        if (row >= M) continue;
#pragma unroll
        for (int j = 0; j < 8; j++) {
            int cg = tx * 8 + j;
            if (cg < Nc) {
                float v = acc[i][j];
                if (bias) v += bias[cg];
                C[(size_t)row * Nc + cg] = v;
            }
        }
    }
}

// ------- GEMM1 with fused bias + LayerNorm + sigmoid epilogue -> g_h -------
__global__ __launch_bounds__(256) void gemm_lnsig_k(const float* __restrict__ A,
    const float* __restrict__ B, const float* __restrict__ bias,
    const float* __restrict__ lng, const float* __restrict__ lnb)
{
    const int K = IN_;
    __shared__ float As[16][136];
    __shared__ float Bs[16][128];
    int tid = threadIdx.x, tx = tid & 15, ty = tid >> 4;
    int m0 = blockIdx.x * 128;
    float acc[8][8];
#pragma unroll
    for (int i = 0; i < 8; i++)
#pragma unroll
        for (int j = 0; j < 8; j++) acc[i][j] = 0.f;
    int ar = tid >> 2, ak = (tid & 3) << 2;
    int bk = tid >> 5, bc = (tid & 31) << 2;
    for (int k0 = 0; k0 < K; k0 += 16) {
#pragma unroll
        for (int h = 0; h < 2; h++) {
            int row = m0 + ar + h * 64;
            float4 v = make_float4(0.f, 0.f, 0.f, 0.f);
            if (row < N_) v = *(const float4*)(A + (size_t)row * K + k0 + ak);
            As[ak + 0][ar + h * 64] = v.x; As[ak + 1][ar + h * 64] = v.y;
            As[ak + 2][ar + h * 64] = v.z; As[ak + 3][ar + h * 64] = v.w;
        }
#pragma unroll
        for (int h = 0; h < 2; h++) {
            int kk = bk + h * 8;
            *(float4*)&Bs[kk][bc] = *(const float4*)(B + (size_t)(k0 + kk) * H_ + bc);
        }
        __syncthreads();
#pragma unroll
        for (int k = 0; k < 16; k++) {
            float a[8], b[8];
            *(float4*)&a[0] = *(const float4*)&As[k][ty * 8];
            *(float4*)&a[4] = *(const float4*)&As[k][ty * 8 + 4];
            *(float4*)&b[0] = *(const float4*)&Bs[k][tx * 8];
            *(float4*)&b[4] = *(const float4*)&Bs[k][tx * 8 + 4];
#pragma unroll
            for (int i = 0; i < 8; i++)
#pragma unroll
                for (int j = 0; j < 8; j++) acc[i][j] += a[i] * b[j];
        }
        __syncthreads();
    }
    // epilogue: threads with same ty (16 lanes of a half-warp) hold one row
    float bs[8], gv[8], bv[8];
    *(float4*)&bs[0] = *(const float4*)(bias + tx * 8);
    *(float4*)&bs[4] = *(const float4*)(bias + tx * 8 + 4);
    *(float4*)&gv[0] = *(const float4*)(lng + tx * 8);
    *(float4*)&gv[4] = *(const float4*)(lng + tx * 8 + 4);
    *(float4*)&bv[0] = *(const float4*)(lnb + tx * 8);
    *(float4*)&bv[4] = *(const float4*)(lnb + tx * 8 + 4);
#pragma unroll
    for (int i = 0; i < 8; i++) {
        int row = m0 + ty * 8 + i;
        float v[8];
        float s = 0.f;
#pragma unroll
        for (int j = 0; j < 8; j++) { v[j] = acc[i][j] + bs[j]; s += v[j]; }
#pragma unroll
        for (int o = 8; o; o >>= 1) s += __shfl_xor_sync(~0u, s, o);
        float mean = s * (1.f / 128.f);
        float q = 0.f;
#pragma unroll
        for (int j = 0; j < 8; j++) { float d = v[j] - mean; q += d * d; }
#pragma unroll
        for (int o = 8; o; o >>= 1) q += __shfl_xor_sync(~0u, q, o);
        float rstd = rsqrtf(q * (1.f / 128.f) + 1e-5f);
#pragma unroll
        for (int j = 0; j < 8; j++) {
            float u = (v[j] - mean) * rstd * gv[j] + bv[j];
            v[j] = 1.f / (1.f + expf(-u));
        }
        if (row < N_) {
            *(float4*)(g_h + (size_t)row * H_ + tx * 8)     = *(float4*)&v[0];
            *(float4*)(g_h + (size_t)row * H_ + tx * 8 + 4) = *(float4*)&v[4];
        }
    }
}

// ---------------- edge weights + degree (4 edges per warp) ----------------
__global__ void edge_w_k(const int* __restrict__ row, const int* __restrict__ col)
{
    int w = threadIdx.x >> 5, lane = threadIdx.x & 31;
    int e0 = blockIdx.x * 32 + w * 4;
#pragma unroll
    for (int k = 0; k < 4; k++) {
        int e = e0 + k;
        if (e >= E_) return;
        int r = row[e], c = col[e];
        float4 a = *(const float4*)(g_hs + ((size_t)r << 7) + (lane << 2));
        float4 b = *(const float4*)(g_hs + ((size_t)c << 7) + (lane << 2));
        float d0 = a.x - b.x, d1 = a.y - b.y, d2 = a.z - b.z, d3 = a.w - b.w;
        float sd = d0 * d0 + d1 * d1 + d2 * d2 + d3 * d3;
        float sa = a.x * a.x + a.y * a.y + a.z * a.z + a.w * a.w;
#pragma unroll
        for (int o = 16; o; o >>= 1) {
            sd += __shfl_xor_sync(~0u, sd, o);
            sa += __shfl_xor_sync(~0u, sa, o);
        }
        if (lane == 0) {
            float C  = sd * (1.f / 128.f);
            float ex = expf(-C * (1.f / EPS_));
            float P0 = fminf(fmaxf(ex, 1e-3f), 1.f);
            float Ps = fminf(fmaxf((P0 + 1e-12f) * ex, 1e-3f), 1.f);
            float ww = 0.7f * P0 + 0.3f * Ps;
            float wl = ww * ww * sa * (1.f / 128.f);
            g_wL[e] = wl;
            atomicAdd(&g_deg[r], wl);
            atomicAdd(&g_deg[c], wl);
        }
    }
}

// ---------------- CSR build ----------------
__global__ void zero_i_k(int* p, int n) { int i = blockIdx.x * blockDim.x + threadIdx.x; if (i < n) p[i] = 0; }
__global__ void zero_f_k(float* p, int n) { int i = blockIdx.x * blockDim.x + threadIdx.x; if (i < n) p[i] = 0.f; }

__global__ void count_adj_k(const int* __restrict__ row, const int* __restrict__ col)
{
    int e = blockIdx.x * blockDim.x + threadIdx.x;
    if (e >= E_) return;
    atomicAdd(&g_cnt[row[e]], 1);
    atomicAdd(&g_cnt[col[e]], 1);
}
__global__ void scan_k(int* __restrict__ cnt, int* __restrict__ ptr, int n)
{
    __shared__ int sh[1024];
    int t = threadIdx.x;
    int chunk = (n + 1023) / 1024;
    int lo = t * chunk, hi = min(lo + chunk, n);
    if (lo > n) lo = n;
    int s = 0;
    for (int i = lo; i < hi; i++) s += cnt[i];
    sh[t] = s;
    __syncthreads();
    for (int off = 1; off < 1024; off <<= 1) {
        int v = (t >= off) ? sh[t - off] : 0;
        __syncthreads();
        sh[t] += v;
        __syncthreads();
    }
    int run = sh[t] - s;
    for (int i = lo; i < hi; i++) {
        int c = cnt[i];
        ptr[i] = run; cnt[i] = run; run += c;
    }
    if (t == 1023) ptr[n] = sh[1023];
}
__global__ void scatter_adj_k(const int* __restrict__ row, const int* __restrict__ col)
{
    int e = blockIdx.x * blockDim.x + threadIdx.x;
    if (e >= E_) return;
    int r = row[e], c = col[e];
    float w = g_wL[e];
    int p = atomicAdd(&g_cnt[r], 1); g_adj[p] = c; g_adjw[p] = w;
    int q = atomicAdd(&g_cnt[c], 1); g_adj[q] = r; g_adjw[q] = w;
}
__global__ void init_incnt_k() { int n = blockIdx.x * blockDim.x + threadIdx.x; if (n < N_) g_incnt[n] = 1; }
__global__ void count_in_k(const int* __restrict__ col)
{
    int e = blockIdx.x * blockDim.x + threadIdx.x;
    if (e < E_) atomicAdd(&g_incnt[col[e]], 1);
}
__global__ void scatter_in_k(const int* __restrict__ row, const int* __restrict__ col)
{
    int e = blockIdx.x * blockDim.x + threadIdx.x;
    if (e >= E_) return;
    int p = atomicAdd(&g_incnt[col[e]], 1);
    g_insrc[p] = row[e];
}
__global__ void scatter_self_k()
{
    int n = blockIdx.x * blockDim.x + threadIdx.x;
    if (n >= N_) return;
    int p = atomicAdd(&g_incnt[n], 1);
    g_insrc[p] = n;
}

// ---------------- CG ----------------
__global__ void cg_init_k()
{
    int c = threadIdx.x;
    g_rs[c] = 0.f; g_den[c] = 0.f; g_rsn[c] = 0.f;
    if (c == 0) g_flag = 0;
}
// X=0, R=P=h, rs0 += h*h per column (channel of thread is fixed: t&127)
__global__ void vec_init_k()
{
    __shared__ float srs[128];
    int t = threadIdx.x;
    if (t < 128) srs[t] = 0.f;
    __syncthreads();
    size_t base = (size_t)blockIdx.x * 2048 + t;
    float a = 0.f;
#pragma unroll
    for (int k = 0; k < 8; k++) {
        size_t i = base + k * 256;
        float h = g_h[i];
        g_X[i] = 0.f; g_R[i] = h; g_P[i] = h;
        a += h * h;
    }
    atomicAdd(&srs[t & 127], a);
    __syncthreads();
    if (t < 128) atomicAdd(&g_rs[t], srs[t]);
}
// AP = (I + dt L) P  and  den += P.AP  (4 nodes per warp)
__global__ void cg_spmv_k()
{
    if (g_flag) return;
    __shared__ float sden[128];
    int t = threadIdx.x;
    if (t < 128) sden[t] = 0.f;
    __syncthreads();
    int lane = t & 31, w = t >> 5;
    float d0 = 0.f, d1 = 0.f, d2 = 0.f, d3 = 0.f;
    int n0 = blockIdx.x * 32 + w * 4;
#pragma unroll
    for (int k = 0; k < 4; k++) {
        int node = n0 + k;
        if (node >= N_) break;
        int j0 = g_ptr[node], j1 = g_ptr[node + 1];
        float4 a = make_float4(0.f, 0.f, 0.f, 0.f);
        for (int j = j0; j < j1; j++) {
            int nb = g_adj[j]; float wv = g_adjw[j];
            float4 v = *(const float4*)(g_P + ((size_t)nb << 7) + (lane << 2));
            a.x += wv * v.x; a.y += wv * v.y; a.z += wv * v.z; a.w += wv * v.w;
        }
        float c0 = 1.f + DT_ * g_deg[node];
        size_t base = ((size_t)node << 7) + (lane << 2);
        float4 p = *(const float4*)(g_P + base);
        float4 o;
        o.x = c0 * p.x - DT_ * a.x; o.y = c0 * p.y - DT_ * a.y;
        o.z = c0 * p.z - DT_ * a.z; o.w = c0 * p.w - DT_ * a.w;
        *(float4*)(g_AP + base) = o;
        d0 += p.x * o.x; d1 += p.y * o.y; d2 += p.z * o.z; d3 += p.w * o.w;
    }
    atomicAdd(&sden[lane * 4 + 0], d0);
    atomicAdd(&sden[lane * 4 + 1], d1);
    atomicAdd(&sden[lane * 4 + 2], d2);
    atomicAdd(&sden[lane * 4 + 3], d3);
    __syncthreads();
    if (t < 128) atomicAdd(&g_den[t], sden[t]);
}
__global__ void cg_update_xr_k()
{
    if (g_flag) return;
    int c = threadIdx.x;
    float al = g_rs[c] / (g_den[c] + 1e-16f);
    int r0 = blockIdx.x * 128, r1 = min(r0 + 128, N_);
    float acc = 0.f;
    for (int r = r0; r < r1; r++) {
        size_t i = (size_t)r * H_ + c;
        g_X[i] += al * g_P[i];
        float rr = g_R[i] - al * g_AP[i];
        g_R[i] = rr;
        acc += rr * rr;
    }
    atomicAdd(&g_rsn[c], acc);
}
__global__ void cg_finalize_k()
{
    if (g_flag) return;
    int c = threadIdx.x;
    float rsn = g_rsn[c];
    g_beta[c] = rsn / (g_rs[c] + 1e-16f);
    g_rs[c] = rsn;
    g_den[c] = 0.f; g_rsn[c] = 0.f;   // pre-zero for next iteration
    __shared__ float sm[128];
    sm[c] = rsn;
    __syncthreads();
    for (int o = 64; o; o >>= 1) {
        if (c < o) sm[c] = fmaxf(sm[c], sm[c + o]);
        __syncthreads();
    }
    if (c == 0 && sm[0] < TOL_ * TOL_) g_flag = 1;
}
__global__ void cg_update_p_k()
{
    if (g_flag) return;
    int c = threadIdx.x;
    float be = g_beta[c];
    int r0 = blockIdx.x * 128, r1 = min(r0 + 128, N_);
    for (int r = r0; r < r1; r++) {
        size_t i = (size_t)r * H_ + c;
        g_P[i] = g_R[i] + be * g_P[i];
    }
}

// ---------------- AFM (scale fused into gather) ----------------
__global__ void isd_k()
{
    int n = blockIdx.x * blockDim.x + threadIdx.x;
    if (n < N_) g_isd[n] = rsqrtf(fmaxf(g_deg[n], 1e-8f));
}
// out = cA*(M + isd*(deg*isd*M - sum w*isd[nb]*M[nb])) + cB*Mp
__global__ void cheb_k(const float* __restrict__ M, const float* __restrict__ Mp,
                       float* __restrict__ out, float cA, float cB)
{
    int lane = threadIdx.x & 31, w = threadIdx.x >> 5;
    int n0 = blockIdx.x * 32 + w * 4;
#pragma unroll
    for (int k = 0; k < 4; k++) {
        int node = n0 + k;
        if (node >= N_) return;
        int j0 = g_ptr[node], j1 = g_ptr[node + 1];
        float4 a = make_float4(0.f, 0.f, 0.f, 0.f);
        for (int j = j0; j < j1; j++) {
            int nb = g_adj[j];
            float wv = g_adjw[j] * g_isd[nb];
            float4 v = *(const float4*)(M + ((size_t)nb << 7) + (lane << 2));
            a.x += wv * v.x; a.y += wv * v.y; a.z += wv * v.z; a.w += wv * v.w;
        }
        float is = g_isd[node];
        float c0 = g_deg[node] * is * is;
        size_t base = ((size_t)node << 7) + (lane << 2);
        float4 m  = *(const float4*)(M + base);
        float4 mp = *(const float4*)(Mp + base);
        float4 o;
        o.x = cA * (m.x + is * (c0 * m.x / is - a.x)) + cB * mp.x;
        o.y = cA * (m.y + is * (c0 * m.y / is - a.y)) + cB * mp.y;
        o.z = cA * (m.z + is * (c0 * m.z / is - a.z)) + cB * mp.z;
        o.w = cA * (m.w + is * (c0 * m.w / is - a.w)) + cB * mp.w;
        *(float4*)(out + base) = o;
    }
}
__global__ void aq_k(const float* __restrict__ gamma)
{
    if (threadIdx.x == 0) {
        float m = gamma[0];
        for (int i = 1; i < 4; i++) m = fmaxf(m, gamma[i]);
        float e[4], s = 0.f;
        for (int i = 0; i < 4; i++) { e[i] = expf(gamma[i] - m); s += e[i]; }
        for (int i = 0; i < 4; i++) g_aq[i] = e[i] / s;
    }
}
__global__ void fuse_k(const float* __restrict__ asvr, const float* __restrict__ aafm)
{
    int i = blockIdx.x * blockDim.x + threadIdx.x;
    if (i >= NH_) return;
    float s1 = 1.f / (1.f + expf(-asvr[0]));
    float s2 = 1.f / (1.f + expf(-aafm[0]));
    float hafm = g_aq[0] * g_h[i] + g_aq[1] * g_R[i] + g_aq[2] * g_P[i] + g_aq[3] * g_AP[i];
    g_F[i] = g_h[i] + s1 * g_X[i] + s2 * hafm;
}

// ---------------- GAT 1 ----------------
__global__ void gat1_coeff_k(const float* __restrict__ a1s, const float* __restrict__ a1d)
{
    int i = blockIdx.x * blockDim.x + threadIdx.x;
    if (i >= N_ * 8) return;
    int n = i >> 3, h = i & 7;
    const float* xw = g_xw1 + (size_t)n * 64 + h * 8;
    float es = 0.f, ed = 0.f;
#pragma unroll
    for (int c = 0; c < 8; c++) { float v = xw[c]; es += v * a1s[h * 8 + c]; ed += v * a1d[h * 8 + c]; }
    g_es1[i] = es; g_ed1[i] = ed;
}
__global__ void gat1_agg_k(const float* __restrict__ b1)
{
    int node = blockIdx.x * 8 + (threadIdx.x >> 5);
    if (node >= N_) return;
    int lane = threadIdx.x & 31;
    int head = lane >> 2;
    int c0 = (lane & 3) * 2;
    float edv = g_ed1[(size_t)node * 8 + head];
    int j0 = g_inptr[node], j1 = g_inptr[node + 1];
    float m = -3.4e38f, den = 0.f, a0 = 0.f, a1 = 0.f;
    for (int j = j0; j < j1; j++) {
        int s = g_insrc[j];
        float e = g_es1[(size_t)s * 8 + head] + edv;
        e = e >= 0.f ? e : 0.2f * e;
        float mn = fmaxf(m, e);
        float sc = expf(m - mn);
        float p  = expf(e - mn);
        const float* xw = g_xw1 + (size_t)s * 64 + head * 8 + c0;
        den = den * sc + p;
        a0  = a0 * sc + p * xw[0];
        a1  = a1 * sc + p * xw[1];
        m = mn;
    }
    float inv = 1.f / (den + 1e-16f);
    float v0 = a0 * inv + b1[head * 8 + c0];
    float v1 = a1 * inv + b1[head * 8 + c0 + 1];
    v0 = v0 > 0.f ? v0 : expm1f(v0);
    v1 = v1 > 0.f ? v1 : expm1f(v1);
    float* o = g_o1 + (size_t)node * 64 + head * 8 + c0;
    o[0] = v0; o[1] = v1;
}

// ---------------- GAT 2 ----------------
__global__ void gat2_coeff_k(const float* __restrict__ a2s, const float* __restrict__ a2d)
{
    int n = blockIdx.x * blockDim.x + threadIdx.x;
    if (n >= N_) return;
    float es = 0.f, ed = 0.f;
#pragma unroll
    for (int c = 0; c < 16; c++) { float v = g_xw2[(size_t)n * 16 + c]; es += v * a2s[c]; ed += v * a2d[c]; }
    g_es2[n] = es; g_ed2[n] = ed;
}
__global__ void gat2_agg_k(const float* __restrict__ b2, float* __restrict__ out)
{
    int node = blockIdx.x * 16 + (threadIdx.x >> 4);
    if (node >= N_) return;
    int ch = threadIdx.x & 15;
    float edv = g_ed2[node];
    int j0 = g_inptr[node], j1 = g_inptr[node + 1];
    float m = -3.4e38f, den = 0.f, acc = 0.f;
    for (int j = j0; j < j1; j++) {
        int s = g_insrc[j];
        float e = g_es2[s] + edv;
        e = e >= 0.f ? e : 0.2f * e;
        float mn = fmaxf(m, e);
        float sc = expf(m - mn);
        float p  = expf(e - mn);
        den = den * sc + p;
        acc = acc * sc + p * g_xw2[(size_t)s * 16 + ch];
        m = mn;
    }
    out[(size_t)node * 16 + ch] = acc / (den + 1e-16f) + b2[ch];
}

// ---------------- host ----------------
#define SYM(p, s) do { void* _t; cudaGetSymbolAddress(&_t, s); p = (decltype(p))_t; } while(0)

extern "C" void kernel_launch(void* const* d_in, const int* in_sizes, int n_in,
                              void* d_out, int out_size)
{
    const float* x      = (const float*)d_in[0];
    const int*   ei     = (const int*)d_in[1];
    const float* W_in   = (const float*)d_in[2];
    const float* b_in   = (const float*)d_in[3];
    const float* ln_g   = (const float*)d_in[4];
    const float* ln_b   = (const float*)d_in[5];
    const float* W_sh   = (const float*)d_in[6];
    const float* gamma  = (const float*)d_in[7];
    const float* asvr   = (const float*)d_in[8];
    const float* aafm   = (const float*)d_in[9];
    const float* W1     = (const float*)d_in[10];
    const float* a1s    = (const float*)d_in[11];
    const float* a1d    = (const float*)d_in[12];
    const float* b1     = (const float*)d_in[13];
    const float* W2     = (const float*)d_in[14];
    const float* a2s    = (const float*)d_in[15];
    const float* a2d    = (const float*)d_in[16];
    const float* b2     = (const float*)d_in[17];
    const int* row = ei, * col = ei + E_;
    float* out = (float*)d_out;

    float *ph, *phs, *pX, *pR, *pP, *pAP, *pF, *pxw1, *po1, *pxw2, *pdeg;
    int *pcnt, *pptr, *pincnt, *pinptr;
    SYM(ph, g_h); SYM(phs, g_hs); SYM(pX, g_X); SYM(pR, g_R); SYM(pP, g_P);
    SYM(pAP, g_AP); SYM(pF, g_F); SYM(pxw1, g_xw1); SYM(po1, g_o1); SYM(pxw2, g_xw2);
    SYM(pdeg, g_deg);
    SYM(pcnt, g_cnt); SYM(pptr, g_ptr); SYM(pincnt, g_incnt); SYM(pinptr, g_inptr);

    const int GB = 391;           // ceil(50000/128)
    zero_f_k<<<196, 256>>>(pdeg, N_);
    zero_i_k<<<196, 256>>>(pcnt, N_);

    // h = sigmoid(LN(x@W_in + b_in)) fused; hs = h@W_sheaf
    gemm_lnsig_k<<<GB, 256>>>(x, W_in, b_in, ln_g, ln_b);
    gemm_k<<<GB, 256>>>(ph, W_sh, nullptr, phs, N_, 128, 128);

    // edge weights + degrees
    edge_w_k<<<16000, 256>>>(row, col);

    // symmetric CSR
    count_adj_k<<<2000, 256>>>(row, col);
    scan_k<<<1, 1024>>>(pcnt, pptr, N_);
    scatter_adj_k<<<2000, 256>>>(row, col);
    // incoming CSR (with self-loops) for GAT
    init_incnt_k<<<196, 256>>>();
    count_in_k<<<2000, 256>>>(col);
    scan_k<<<1, 1024>>>(pincnt, pinptr, N_);
    scatter_in_k<<<2000, 256>>>(row, col);
    scatter_self_k<<<196, 256>>>();

    // CG solve (I + dt L) X = h   (4 launches per iteration)
    cg_init_k<<<1, 128>>>();
    vec_init_k<<<3125, 256>>>();
    for (int it = 0; it < MAXIT_; it++) {
        cg_spmv_k<<<1563, 256>>>();       // AP + den
        cg_update_xr_k<<<GB, 128>>>();    // X,R + rsn
        cg_finalize_k<<<1, 128>>>();      // beta, rs, flag, zero den/rsn
        cg_update_p_k<<<GB, 128>>>();
    }

    // AFM Chebyshev (scale fused): T1 -> g_R, T2 -> g_P, T3 -> g_AP
    isd_k<<<196, 256>>>();
    cheb_k<<<1563, 256>>>(ph, ph, pR, 1.f, 0.f);
    cheb_k<<<1563, 256>>>(pR, ph, pP, 2.f, -1.f);
    cheb_k<<<1563, 256>>>(pP, pR, pAP, 2.f, -1.f);
    aq_k<<<1, 32>>>(gamma);
    fuse_k<<<(NH_ + 255) / 256, 256>>>(asvr, aafm);

    // GAT layer 1
    gemm_k<<<GB, 256>>>(pF, W1, nullptr, pxw1, N_, 64, 128);
    gat1_coeff_k<<<(N_ * 8 + 255) / 256, 256>>>(a1s, a1d);
    gat1_agg_k<<<6250, 256>>>(b1);

    // GAT layer 2
    gemm_k<<<GB, 256>>>(po1, W2, nullptr, pxw2, N_, 16, 64);
    gat2_coeff_k<<<196, 256>>>(a2s, a2d);
    gat2_agg_k<<<3125, 256>>>(b2, out);
}

// round 9
// speedup vs baseline: 1.3527x; 1.2338x over previous
#include <cuda_runtime.h>
#include <math.h>

#define N_  50000
#define E_  512000
#define IN_ 512
#define H_  128
#define NH_ (N_*H_)
#define DT_   0.1f
#define EPS_  1e-3f
#define TOL_  1e-4f
#define MAXIT_ 20
#define CGRID_ 444   // 148 SMs * 3 CTAs, guaranteed resident via __launch_bounds__(256,3)

// ---------------- device scratch ----------------
__device__ __align__(16) float g_h[NH_];
__device__ __align__(16) float g_hs[NH_];
__device__ __align__(16) float g_X[NH_];
__device__ __align__(16) float g_R[NH_];
__device__ __align__(16) float g_P[NH_];
__device__ __align__(16) float g_AP[NH_];
__device__ __align__(16) float g_F[NH_];
__device__ float g_wL[E_];
__device__ float g_deg[N_];
__device__ float g_isd[N_];
__device__ int   g_cnt[N_];
__device__ int   g_ptr[N_ + 1];
__device__ int   g_adj[2 * E_];
__device__ float g_adjw[2 * E_];
__device__ int   g_incnt[N_];
__device__ int   g_inptr[N_ + 1];
__device__ int   g_insrc[E_ + N_];
__device__ float g_rsA[MAXIT_ + 1][H_];   // slot 0 = rs0, slot it+1 = rsn of iter it
__device__ float g_denA[MAXIT_][H_];
__device__ int   g_barc;
__device__ volatile int g_barp;
__device__ float g_aq[4];
__device__ __align__(16) float g_xw1[N_ * 64];
__device__ float g_es1[N_ * 8], g_ed1[N_ * 8];
__device__ __align__(16) float g_o1[N_ * 64];
__device__ __align__(16) float g_xw2[N_ * 16];
__device__ float g_es2[N_], g_ed2[N_];

// ---------------- generic GEMM: C = A[M,K] @ B[K,Nc] (+bias) ----------------
__global__ __launch_bounds__(256) void gemm_k(const float* __restrict__ A,
    const float* __restrict__ B, const float* __restrict__ bias,
    float* __restrict__ C, int M, int Nc, int K)
{
    __shared__ float As[16][136];
    __shared__ float Bs[16][128];
    int tid = threadIdx.x, tx = tid & 15, ty = tid >> 4;
    int m0 = blockIdx.x * 128;
    float acc[8][8];
#pragma unroll
    for (int i = 0; i < 8; i++)
#pragma unroll
        for (int j = 0; j < 8; j++) acc[i][j] = 0.f;
    int ar = tid >> 2, ak = (tid & 3) << 2;
    int bk = tid >> 5, bc = (tid & 31) << 2;
    for (int k0 = 0; k0 < K; k0 += 16) {
#pragma unroll
        for (int h = 0; h < 2; h++) {
            int row = m0 + ar + h * 64;
            float4 v = make_float4(0.f, 0.f, 0.f, 0.f);
            if (row < M) v = *(const float4*)(A + (size_t)row * K + k0 + ak);
            As[ak + 0][ar + h * 64] = v.x; As[ak + 1][ar + h * 64] = v.y;
            As[ak + 2][ar + h * 64] = v.z; As[ak + 3][ar + h * 64] = v.w;
        }
#pragma unroll
        for (int h = 0; h < 2; h++) {
            int kk = bk + h * 8;
            float4 v = make_float4(0.f, 0.f, 0.f, 0.f);
            if (bc < Nc) v = *(const float4*)(B + (size_t)(k0 + kk) * Nc + bc);
            *(float4*)&Bs[kk][bc] = v;
        }
        __syncthreads();
#pragma unroll
        for (int k = 0; k < 16; k++) {
            float a[8], b[8];
            *(float4*)&a[0] = *(const float4*)&As[k][ty * 8];
            *(float4*)&a[4] = *(const float4*)&As[k][ty * 8 + 4];
            *(float4*)&b[0] = *(const float4*)&Bs[k][tx * 8];
            *(float4*)&b[4] = *(const float4*)&Bs[k][tx * 8 + 4];
#pragma unroll
            for (int i = 0; i < 8; i++)
#pragma unroll
                for (int j = 0; j < 8; j++) acc[i][j] += a[i] * b[j];
        }
        __syncthreads();
    }
#pragma unroll
    for (int i = 0; i < 8; i++) {
        int row = m0 + ty * 8 + i;
        if (row >= M) continue;
#pragma unroll
        for (int j = 0; j < 8; j++) {
            int cg = tx * 8 + j;
            if (cg < Nc) {
                float v = acc[i][j];
                if (bias) v += bias[cg];
                C[(size_t)row * Nc + cg] = v;
            }
        }
    }
}

// ------- GEMM1 with fused bias + LayerNorm + sigmoid epilogue -> g_h -------
__global__ __launch_bounds__(256) void gemm_lnsig_k(const float* __restrict__ A,
    const float* __restrict__ B, const float* __restrict__ bias,
    const float* __restrict__ lng, const float* __restrict__ lnb)
{
    const int K = IN_;
    __shared__ float As[16][136];
    __shared__ float Bs[16][128];
    int tid = threadIdx.x, tx = tid & 15, ty = tid >> 4;
    int m0 = blockIdx.x * 128;
    float acc[8][8];
#pragma unroll
    for (int i = 0; i < 8; i++)
#pragma unroll
        for (int j = 0; j < 8; j++) acc[i][j] = 0.f;
    int ar = tid >> 2, ak = (tid & 3) << 2;
    int bk = tid >> 5, bc = (tid & 31) << 2;
    for (int k0 = 0; k0 < K; k0 += 16) {
#pragma unroll
        for (int h = 0; h < 2; h++) {
            int row = m0 + ar + h * 64;
            float4 v = make_float4(0.f, 0.f, 0.f, 0.f);
            if (row < N_) v = *(const float4*)(A + (size_t)row * K + k0 + ak);
            As[ak + 0][ar + h * 64] = v.x; As[ak + 1][ar + h * 64] = v.y;
            As[ak + 2][ar + h * 64] = v.z; As[ak + 3][ar + h * 64] = v.w;
        }
#pragma unroll
        for (int h = 0; h < 2; h++) {
            int kk = bk + h * 8;
            *(float4*)&Bs[kk][bc] = *(const float4*)(B + (size_t)(k0 + kk) * H_ + bc);
        }
        __syncthreads();
#pragma unroll
        for (int k = 0; k < 16; k++) {
            float a[8], b[8];
            *(float4*)&a[0] = *(const float4*)&As[k][ty * 8];
            *(float4*)&a[4] = *(const float4*)&As[k][ty * 8 + 4];
            *(float4*)&b[0] = *(const float4*)&Bs[k][tx * 8];
            *(float4*)&b[4] = *(const float4*)&Bs[k][tx * 8 + 4];
#pragma unroll
            for (int i = 0; i < 8; i++)
#pragma unroll
                for (int j = 0; j < 8; j++) acc[i][j] += a[i] * b[j];
        }
        __syncthreads();
    }
    float bs[8], gv[8], bv[8];
    *(float4*)&bs[0] = *(const float4*)(bias + tx * 8);
    *(float4*)&bs[4] = *(const float4*)(bias + tx * 8 + 4);
    *(float4*)&gv[0] = *(const float4*)(lng + tx * 8);
    *(float4*)&gv[4] = *(const float4*)(lng + tx * 8 + 4);
    *(float4*)&bv[0] = *(const float4*)(lnb + tx * 8);
    *(float4*)&bv[4] = *(const float4*)(lnb + tx * 8 + 4);
#pragma unroll
    for (int i = 0; i < 8; i++) {
        int row = m0 + ty * 8 + i;
        float v[8];
        float s = 0.f;
#pragma unroll
        for (int j = 0; j < 8; j++) { v[j] = acc[i][j] + bs[j]; s += v[j]; }
#pragma unroll
        for (int o = 8; o; o >>= 1) s += __shfl_xor_sync(~0u, s, o);
        float mean = s * (1.f / 128.f);
        float q = 0.f;
#pragma unroll
        for (int j = 0; j < 8; j++) { float d = v[j] - mean; q += d * d; }
#pragma unroll
        for (int o = 8; o; o >>= 1) q += __shfl_xor_sync(~0u, q, o);
        float rstd = rsqrtf(q * (1.f / 128.f) + 1e-5f);
#pragma unroll
        for (int j = 0; j < 8; j++) {
            float u = (v[j] - mean) * rstd * gv[j] + bv[j];
            v[j] = 1.f / (1.f + expf(-u));
        }
        if (row < N_) {
            *(float4*)(g_h + (size_t)row * H_ + tx * 8)     = *(float4*)&v[0];
            *(float4*)(g_h + (size_t)row * H_ + tx * 8 + 4) = *(float4*)&v[4];
        }
    }
}

// ------- xw1 GEMM (Nc=64,K=128) with fused GAT1 attention coefficients -------
__global__ __launch_bounds__(256) void gemm_gat1_k(const float* __restrict__ A,
    const float* __restrict__ B, const float* __restrict__ a1s,
    const float* __restrict__ a1d)
{
    const int K = 128, Nc = 64;
    __shared__ float As[16][136];
    __shared__ float Bs[16][128];
    int tid = threadIdx.x, tx = tid & 15, ty = tid >> 4;
    int m0 = blockIdx.x * 128;
    float acc[8][8];
#pragma unroll
    for (int i = 0; i < 8; i++)
#pragma unroll
        for (int j = 0; j < 8; j++) acc[i][j] = 0.f;
    int ar = tid >> 2, ak = (tid & 3) << 2;
    int bk = tid >> 5, bc = (tid & 31) << 2;
    for (int k0 = 0; k0 < K; k0 += 16) {
#pragma unroll
        for (int h = 0; h < 2; h++) {
            int row = m0 + ar + h * 64;
            float4 v = make_float4(0.f, 0.f, 0.f, 0.f);
            if (row < N_) v = *(const float4*)(A + (size_t)row * K + k0 + ak);
            As[ak + 0][ar + h * 64] = v.x; As[ak + 1][ar + h * 64] = v.y;
            As[ak + 2][ar + h * 64] = v.z; As[ak + 3][ar + h * 64] = v.w;
        }
#pragma unroll
        for (int h = 0; h < 2; h++) {
            int kk = bk + h * 8;
            float4 v = make_float4(0.f, 0.f, 0.f, 0.f);
            if (bc < Nc) v = *(const float4*)(B + (size_t)(k0 + kk) * Nc + bc);
            *(float4*)&Bs[kk][bc] = v;
        }
        __syncthreads();
#pragma unroll
        for (int k = 0; k < 16; k++) {
            float a[8], b[8];
            *(float4*)&a[0] = *(const float4*)&As[k][ty * 8];
            *(float4*)&a[4] = *(const float4*)&As[k][ty * 8 + 4];
            *(float4*)&b[0] = *(const float4*)&Bs[k][tx * 8];
            *(float4*)&b[4] = *(const float4*)&Bs[k][tx * 8 + 4];
#pragma unroll
            for (int i = 0; i < 8; i++)
#pragma unroll
                for (int j = 0; j < 8; j++) acc[i][j] += a[i] * b[j];
        }
        __syncthreads();
    }
    if (tx < 8) {   // head = tx; this thread owns exactly head tx's 8 channels
        float as[8], ad[8];
        *(float4*)&as[0] = *(const float4*)(a1s + tx * 8);
        *(float4*)&as[4] = *(const float4*)(a1s + tx * 8 + 4);
        *(float4*)&ad[0] = *(const float4*)(a1d + tx * 8);
        *(float4*)&ad[4] = *(const float4*)(a1d + tx * 8 + 4);
#pragma unroll
        for (int i = 0; i < 8; i++) {
            int row = m0 + ty * 8 + i;
            if (row >= N_) continue;
            float es = 0.f, ed = 0.f;
#pragma unroll
            for (int j = 0; j < 8; j++) { es += acc[i][j] * as[j]; ed += acc[i][j] * ad[j]; }
            g_es1[(size_t)row * 8 + tx] = es;
            g_ed1[(size_t)row * 8 + tx] = ed;
            *(float4*)(g_xw1 + (size_t)row * 64 + tx * 8)     = *(float4*)&acc[i][0];
            *(float4*)(g_xw1 + (size_t)row * 64 + tx * 8 + 4) = *(float4*)&acc[i][4];
        }
    }
}

// ---------------- edge weights + degree (4 edges per warp) ----------------
__global__ void edge_w_k(const int* __restrict__ row, const int* __restrict__ col)
{
    int w = threadIdx.x >> 5, lane = threadIdx.x & 31;
    int e0 = blockIdx.x * 32 + w * 4;
#pragma unroll
    for (int k = 0; k < 4; k++) {
        int e = e0 + k;
        if (e >= E_) return;
        int r = row[e], c = col[e];
        float4 a = *(const float4*)(g_hs + ((size_t)r << 7) + (lane << 2));
        float4 b = *(const float4*)(g_hs + ((size_t)c << 7) + (lane << 2));
        float d0 = a.x - b.x, d1 = a.y - b.y, d2 = a.z - b.z, d3 = a.w - b.w;
        float sd = d0 * d0 + d1 * d1 + d2 * d2 + d3 * d3;
        float sa = a.x * a.x + a.y * a.y + a.z * a.z + a.w * a.w;
#pragma unroll
        for (int o = 16; o; o >>= 1) {
            sd += __shfl_xor_sync(~0u, sd, o);
            sa += __shfl_xor_sync(~0u, sa, o);
        }
        if (lane == 0) {
            float C  = sd * (1.f / 128.f);
            float ex = expf(-C * (1.f / EPS_));
            float P0 = fminf(fmaxf(ex, 1e-3f), 1.f);
            float Ps = fminf(fmaxf((P0 + 1e-12f) * ex, 1e-3f), 1.f);
            float ww = 0.7f * P0 + 0.3f * Ps;
            float wl = ww * ww * sa * (1.f / 128.f);
            g_wL[e] = wl;
            atomicAdd(&g_deg[r], wl);
            atomicAdd(&g_deg[c], wl);
        }
    }
}

// ---------------- CSR build ----------------
__global__ void zero_i_k(int* p, int n) { int i = blockIdx.x * blockDim.x + threadIdx.x; if (i < n) p[i] = 0; }
__global__ void zero_f_k(float* p, int n) { int i = blockIdx.x * blockDim.x + threadIdx.x; if (i < n) p[i] = 0.f; }

__global__ void count_adj_k(const int* __restrict__ row, const int* __restrict__ col)
{
    int e = blockIdx.x * blockDim.x + threadIdx.x;
    if (e >= E_) return;
    atomicAdd(&g_cnt[row[e]], 1);
    atomicAdd(&g_cnt[col[e]], 1);
}
__global__ void scan_k(int* __restrict__ cnt, int* __restrict__ ptr, int n)
{
    __shared__ int sh[1024];
    int t = threadIdx.x;
    int chunk = (n + 1023) / 1024;
    int lo = t * chunk, hi = min(lo + chunk, n);
    if (lo > n) lo = n;
    int s = 0;
    for (int i = lo; i < hi; i++) s += cnt[i];
    sh[t] = s;
    __syncthreads();
    for (int off = 1; off < 1024; off <<= 1) {
        int v = (t >= off) ? sh[t - off] : 0;
        __syncthreads();
        sh[t] += v;
        __syncthreads();
    }
    int run = sh[t] - s;
    for (int i = lo; i < hi; i++) {
        int c = cnt[i];
        ptr[i] = run; cnt[i] = run; run += c;
    }
    if (t == 1023) ptr[n] = sh[1023];
}
__global__ void scatter_adj_k(const int* __restrict__ row, const int* __restrict__ col)
{
    int e = blockIdx.x * blockDim.x + threadIdx.x;
    if (e >= E_) return;
    int r = row[e], c = col[e];
    float w = g_wL[e];
    int p = atomicAdd(&g_cnt[r], 1); g_adj[p] = c; g_adjw[p] = w;
    int q = atomicAdd(&g_cnt[c], 1); g_adj[q] = r; g_adjw[q] = w;
}
__global__ void init_incnt_k() { int n = blockIdx.x * blockDim.x + threadIdx.x; if (n < N_) g_incnt[n] = 1; }
__global__ void count_in_k(const int* __restrict__ col)
{
    int e = blockIdx.x * blockDim.x + threadIdx.x;
    if (e < E_) atomicAdd(&g_incnt[col[e]], 1);
}
__global__ void scatter_in_k(const int* __restrict__ row, const int* __restrict__ col)
{
    int e = blockIdx.x * blockDim.x + threadIdx.x;
    if (e >= E_) return;
    int p = atomicAdd(&g_incnt[col[e]], 1);
    g_insrc[p] = row[e];
}
__global__ void scatter_self_k()
{
    int n = blockIdx.x * blockDim.x + threadIdx.x;
    if (n >= N_) return;
    int p = atomicAdd(&g_incnt[n], 1);
    g_insrc[p] = n;
}

// ---------------- persistent CG ----------------
__global__ void cg_init2_k()
{
    int t = threadIdx.x;
    float* rs = &g_rsA[0][0];
    float* dn = &g_denA[0][0];
    for (int i = t; i < (MAXIT_ + 1) * H_; i += 256) rs[i] = 0.f;
    for (int i = t; i < MAXIT_ * H_; i += 256) dn[i] = 0.f;
    if (t == 0) { g_barc = 0; g_barp = 0; }
}

__device__ __forceinline__ void gridbar()
{
    __threadfence();
    __syncthreads();
    if (threadIdx.x == 0) {
        int ph = g_barp;
        if (atomicAdd(&g_barc, 1) == (int)gridDim.x - 1) {
            g_barc = 0;
            __threadfence();
            g_barp = ph ^ 1;
        } else {
            while (g_barp == ph) __nanosleep(32);
        }
    }
    __syncthreads();
}

__global__ __launch_bounds__(256, 3) void cg_persist_k()
{
    __shared__ float sbin[128];
    int tid = threadIdx.x;
    int gtid = blockIdx.x * 256 + tid;
    int stride = gridDim.x * 256;             // 113664, multiple of 32
    int c0 = (gtid & 31) * 4;                 // fixed 4 columns per thread (element phases)
    int lane = tid & 31, wid = tid >> 5;
    int gwarp = blockIdx.x * 8 + wid;
    int nwarp = gridDim.x * 8;
    const int NV4 = NH_ / 4;

    // phase 0: X=0, R=P=h, rs0
    if (tid < 128) sbin[tid] = 0.f;
    __syncthreads();
    {
        float a0 = 0.f, a1 = 0.f, a2 = 0.f, a3 = 0.f;
        for (int j = gtid; j < NV4; j += stride) {
            float4 h = ((const float4*)g_h)[j];
            ((float4*)g_X)[j] = make_float4(0.f, 0.f, 0.f, 0.f);
            ((float4*)g_R)[j] = h;
            ((float4*)g_P)[j] = h;
            a0 += h.x * h.x; a1 += h.y * h.y; a2 += h.z * h.z; a3 += h.w * h.w;
        }
        atomicAdd(&sbin[c0 + 0], a0); atomicAdd(&sbin[c0 + 1], a1);
        atomicAdd(&sbin[c0 + 2], a2); atomicAdd(&sbin[c0 + 3], a3);
    }
    __syncthreads();
    if (tid < 128) { float v = sbin[tid]; if (v != 0.f) atomicAdd(&g_rsA[0][tid], v); }
    gridbar();

    for (int it = 0; it < MAXIT_; it++) {
        if (it > 0) {
            // done check on rsn of previous iteration (= g_rsA[it]); then P update
            if (tid < 128) sbin[tid] = __ldcg(&g_rsA[it][tid]);
            __syncthreads();
            for (int o = 64; o; o >>= 1) {
                if (tid < o) sbin[tid] = fmaxf(sbin[tid], sbin[tid + o]);
                __syncthreads();
            }
            bool done = sbin[0] < TOL_ * TOL_;
            __syncthreads();
            if (done) break;
            float b0 = __ldcg(&g_rsA[it][c0 + 0]) / (__ldcg(&g_rsA[it - 1][c0 + 0]) + 1e-16f);
            float b1 = __ldcg(&g_rsA[it][c0 + 1]) / (__ldcg(&g_rsA[it - 1][c0 + 1]) + 1e-16f);
            float b2 = __ldcg(&g_rsA[it][c0 + 2]) / (__ldcg(&g_rsA[it - 1][c0 + 2]) + 1e-16f);
            float b3 = __ldcg(&g_rsA[it][c0 + 3]) / (__ldcg(&g_rsA[it - 1][c0 + 3]) + 1e-16f);
            for (int j = gtid; j < NV4; j += stride) {
                float4 r = ((const float4*)g_R)[j];
                float4 p = ((const float4*)g_P)[j];
                p.x = r.x + b0 * p.x; p.y = r.y + b1 * p.y;
                p.z = r.z + b2 * p.z; p.w = r.w + b3 * p.w;
                ((float4*)g_P)[j] = p;
            }
            gridbar();
        }
        // spmv: AP = (I + dt L) P, den[it] += P.AP
        if (tid < 128) sbin[tid] = 0.f;
        __syncthreads();
        {
            float d0 = 0.f, d1 = 0.f, d2 = 0.f, d3 = 0.f;
            for (int wc = gwarp; wc < N_ / 4; wc += nwarp) {
                int nb0 = wc * 4;
#pragma unroll
                for (int k2 = 0; k2 < 4; k2++) {
                    int node = nb0 + k2;
                    int j0 = g_ptr[node], j1 = g_ptr[node + 1];
                    float4 a = make_float4(0.f, 0.f, 0.f, 0.f);
                    for (int j = j0; j < j1; j++) {
                        int nb = g_adj[j]; float wv = g_adjw[j];
                        float4 v = __ldcg((const float4*)g_P + ((size_t)nb << 5) + lane);
                        a.x += wv * v.x; a.y += wv * v.y; a.z += wv * v.z; a.w += wv * v.w;
                    }
                    float cc = 1.f + DT_ * g_deg[node];
                    float4 p = __ldcg((const float4*)g_P + ((size_t)node << 5) + lane);
                    float4 o;
                    o.x = cc * p.x - DT_ * a.x; o.y = cc * p.y - DT_ * a.y;
                    o.z = cc * p.z - DT_ * a.z; o.w = cc * p.w - DT_ * a.w;
                    ((float4*)g_AP)[((size_t)node << 5) + lane] = o;
                    d0 += p.x * o.x; d1 += p.y * o.y; d2 += p.z * o.z; d3 += p.w * o.w;
                }
            }
            atomicAdd(&sbin[lane * 4 + 0], d0); atomicAdd(&sbin[lane * 4 + 1], d1);
            atomicAdd(&sbin[lane * 4 + 2], d2); atomicAdd(&sbin[lane * 4 + 3], d3);
        }
        __syncthreads();
        if (tid < 128) { float v = sbin[tid]; if (v != 0.f) atomicAdd(&g_denA[it][tid], v); }
        gridbar();
        // update X,R; rsn -> g_rsA[it+1]
        if (tid < 128) sbin[tid] = 0.f;
        __syncthreads();
        {
            float al0 = __ldcg(&g_rsA[it][c0 + 0]) / (__ldcg(&g_denA[it][c0 + 0]) + 1e-16f);
            float al1 = __ldcg(&g_rsA[it][c0 + 1]) / (__ldcg(&g_denA[it][c0 + 1]) + 1e-16f);
            float al2 = __ldcg(&g_rsA[it][c0 + 2]) / (__ldcg(&g_denA[it][c0 + 2]) + 1e-16f);
            float al3 = __ldcg(&g_rsA[it][c0 + 3]) / (__ldcg(&g_denA[it][c0 + 3]) + 1e-16f);
            float s0 = 0.f, s1 = 0.f, s2 = 0.f, s3 = 0.f;
            for (int j = gtid; j < NV4; j += stride) {
                float4 p  = ((const float4*)g_P)[j];
                float4 ap = __ldcg((const float4*)g_AP + j);
                float4 x  = ((const float4*)g_X)[j];
                float4 r  = ((const float4*)g_R)[j];
                x.x += al0 * p.x; x.y += al1 * p.y; x.z += al2 * p.z; x.w += al3 * p.w;
                r.x -= al0 * ap.x; r.y -= al1 * ap.y; r.z -= al2 * ap.z; r.w -= al3 * ap.w;
                ((float4*)g_X)[j] = x;
                ((float4*)g_R)[j] = r;
                s0 += r.x * r.x; s1 += r.y * r.y; s2 += r.z * r.z; s3 += r.w * r.w;
            }
            atomicAdd(&sbin[c0 + 0], s0); atomicAdd(&sbin[c0 + 1], s1);
            atomicAdd(&sbin[c0 + 2], s2); atomicAdd(&sbin[c0 + 3], s3);
        }
        __syncthreads();
        if (tid < 128) { float v = sbin[tid]; if (v != 0.f) atomicAdd(&g_rsA[it + 1][tid], v); }
        gridbar();
    }
}

// ---------------- AFM ----------------
__global__ void isd_k()
{
    int n = blockIdx.x * blockDim.x + threadIdx.x;
    if (n < N_) g_isd[n] = rsqrtf(fmaxf(g_deg[n], 1e-8f));
}
__global__ void cheb_k(const float* __restrict__ M, const float* __restrict__ Mp,
                       float* __restrict__ out, float cA, float cB)
{
    int lane = threadIdx.x & 31, w = threadIdx.x >> 5;
    int n0 = blockIdx.x * 32 + w * 4;
#pragma unroll
    for (int k = 0; k < 4; k++) {
        int node = n0 + k;
        if (node >= N_) return;
        int j0 = g_ptr[node], j1 = g_ptr[node + 1];
        float4 a = make_float4(0.f, 0.f, 0.f, 0.f);
        for (int j = j0; j < j1; j++) {
            int nb = g_adj[j];
            float wv = g_adjw[j] * g_isd[nb];
            float4 v = *(const float4*)(M + ((size_t)nb << 7) + (lane << 2));
            a.x += wv * v.x; a.y += wv * v.y; a.z += wv * v.z; a.w += wv * v.w;
        }
        float is = g_isd[node];
        float c0 = g_deg[node] * is * is;
        size_t base = ((size_t)node << 7) + (lane << 2);
        float4 m  = *(const float4*)(M + base);
        float4 mp = *(const float4*)(Mp + base);
        float4 o;
        o.x = cA * (m.x + c0 * m.x - is * a.x) + cB * mp.x;
        o.y = cA * (m.y + c0 * m.y - is * a.y) + cB * mp.y;
        o.z = cA * (m.z + c0 * m.z - is * a.z) + cB * mp.z;
        o.w = cA * (m.w + c0 * m.w - is * a.w) + cB * mp.w;
        *(float4*)(out + base) = o;
    }
}
__global__ void aq_k(const float* __restrict__ gamma)
{
    if (threadIdx.x == 0) {
        float m = gamma[0];
        for (int i = 1; i < 4; i++) m = fmaxf(m, gamma[i]);
        float e[4], s = 0.f;
        for (int i = 0; i < 4; i++) { e[i] = expf(gamma[i] - m); s += e[i]; }
        for (int i = 0; i < 4; i++) g_aq[i] = e[i] / s;
    }
}
__global__ void fuse_k(const float* __restrict__ asvr, const float* __restrict__ aafm)
{
    int i = blockIdx.x * blockDim.x + threadIdx.x;
    if (i >= NH_) return;
    float s1 = 1.f / (1.f + expf(-asvr[0]));
    float s2 = 1.f / (1.f + expf(-aafm[0]));
    float hafm = g_aq[0] * g_h[i] + g_aq[1] * g_R[i] + g_aq[2] * g_P[i] + g_aq[3] * g_AP[i];
    g_F[i] = g_h[i] + s1 * g_X[i] + s2 * hafm;
}

// ---------------- GAT aggregation ----------------
__global__ void gat1_agg_k(const float* __restrict__ b1)
{
    int node = blockIdx.x * 8 + (threadIdx.x >> 5);
    if (node >= N_) return;
    int lane = threadIdx.x & 31;
    int head = lane >> 2;
    int c0 = (lane & 3) * 2;
    float edv = g_ed1[(size_t)node * 8 + head];
    int j0 = g_inptr[node], j1 = g_inptr[node + 1];
    float m = -3.4e38f, den = 0.f, a0 = 0.f, a1 = 0.f;
    for (int j = j0; j < j1; j++) {
        int s = g_insrc[j];
        float e = g_es1[(size_t)s * 8 + head] + edv;
        e = e >= 0.f ? e : 0.2f * e;
        float mn = fmaxf(m, e);
        float sc = expf(m - mn);
        float p  = expf(e - mn);
        const float* xw = g_xw1 + (size_t)s * 64 + head * 8 + c0;
        den = den * sc + p;
        a0  = a0 * sc + p * xw[0];
        a1  = a1 * sc + p * xw[1];
        m = mn;
    }
    float inv = 1.f / (den + 1e-16f);
    float v0 = a0 * inv + b1[head * 8 + c0];
    float v1 = a1 * inv + b1[head * 8 + c0 + 1];
    v0 = v0 > 0.f ? v0 : expm1f(v0);
    v1 = v1 > 0.f ? v1 : expm1f(v1);
    float* o = g_o1 + (size_t)node * 64 + head * 8 + c0;
    o[0] = v0; o[1] = v1;
}
__global__ void gat2_coeff_k(const float* __restrict__ a2s, const float* __restrict__ a2d)
{
    int n = blockIdx.x * blockDim.x + threadIdx.x;
    if (n >= N_) return;
    float es = 0.f, ed = 0.f;
#pragma unroll
    for (int c = 0; c < 16; c++) { float v = g_xw2[(size_t)n * 16 + c]; es += v * a2s[c]; ed += v * a2d[c]; }
    g_es2[n] = es; g_ed2[n] = ed;
}
__global__ void gat2_agg_k(const float* __restrict__ b2, float* __restrict__ out)
{
    int node = blockIdx.x * 16 + (threadIdx.x >> 4);
    if (node >= N_) return;
    int ch = threadIdx.x & 15;
    float edv = g_ed2[node];
    int j0 = g_inptr[node], j1 = g_inptr[node + 1];
    float m = -3.4e38f, den = 0.f, acc = 0.f;
    for (int j = j0; j < j1; j++) {
        int s = g_insrc[j];
        float e = g_es2[s] + edv;
        e = e >= 0.f ? e : 0.2f * e;
        float mn = fmaxf(m, e);
        float sc = expf(m - mn);
        float p  = expf(e - mn);
        den = den * sc + p;
        acc = acc * sc + p * g_xw2[(size_t)s * 16 + ch];
        m = mn;
    }
    out[(size_t)node * 16 + ch] = acc / (den + 1e-16f) + b2[ch];
}

// ---------------- host ----------------
#define SYM(p, s) do { void* _t; cudaGetSymbolAddress(&_t, s); p = (decltype(p))_t; } while(0)

extern "C" void kernel_launch(void* const* d_in, const int* in_sizes, int n_in,
                              void* d_out, int out_size)
{
    const float* x      = (const float*)d_in[0];
    const int*   ei     = (const int*)d_in[1];
    const float* W_in   = (const float*)d_in[2];
    const float* b_in   = (const float*)d_in[3];
    const float* ln_g   = (const float*)d_in[4];
    const float* ln_b   = (const float*)d_in[5];
    const float* W_sh   = (const float*)d_in[6];
    const float* gamma  = (const float*)d_in[7];
    const float* asvr   = (const float*)d_in[8];
    const float* aafm   = (const float*)d_in[9];
    const float* W1     = (const float*)d_in[10];
    const float* a1s    = (const float*)d_in[11];
    const float* a1d    = (const float*)d_in[12];
    const float* b1     = (const float*)d_in[13];
    const float* W2     = (const float*)d_in[14];
    const float* a2s    = (const float*)d_in[15];
    const float* a2d    = (const float*)d_in[16];
    const float* b2     = (const float*)d_in[17];
    const int* row = ei, * col = ei + E_;
    float* out = (float*)d_out;

    float *ph, *phs, *pR, *pP, *pAP, *pF, *po1, *pxw2, *pdeg;
    int *pcnt, *pincnt, *pptr, *pinptr;
    SYM(ph, g_h); SYM(phs, g_hs); SYM(pR, g_R); SYM(pP, g_P);
    SYM(pAP, g_AP); SYM(pF, g_F); SYM(po1, g_o1); SYM(pxw2, g_xw2);
    SYM(pdeg, g_deg);
    SYM(pcnt, g_cnt); SYM(pincnt, g_incnt); SYM(pptr, g_ptr); SYM(pinptr, g_inptr);

    const int GB = 391;           // ceil(50000/128)
    zero_f_k<<<196, 256>>>(pdeg, N_);
    zero_i_k<<<196, 256>>>(pcnt, N_);

    // h = sigmoid(LN(x@W_in + b_in)) fused; hs = h@W_sheaf
    gemm_lnsig_k<<<GB, 256>>>(x, W_in, b_in, ln_g, ln_b);
    gemm_k<<<GB, 256>>>(ph, W_sh, nullptr, phs, N_, 128, 128);

    // edge weights + degrees
    edge_w_k<<<16000, 256>>>(row, col);

    // symmetric CSR
    count_adj_k<<<2000, 256>>>(row, col);
    scan_k<<<1, 1024>>>(pcnt, pptr, N_);
    scatter_adj_k<<<2000, 256>>>(row, col);
    // incoming CSR (with self-loops) for GAT
    init_incnt_k<<<196, 256>>>();
    count_in_k<<<2000, 256>>>(col);
    scan_k<<<1, 1024>>>(pincnt, pinptr, N_);
    scatter_in_k<<<2000, 256>>>(row, col);
    scatter_self_k<<<196, 256>>>();

    // persistent CG: one kernel, real early break
    cg_init2_k<<<1, 256>>>();
    cg_persist_k<<<CGRID_, 256>>>();

    // AFM Chebyshev: T1 -> g_R, T2 -> g_P, T3 -> g_AP
    isd_k<<<196, 256>>>();
    cheb_k<<<1563, 256>>>(ph, ph, pR, 1.f, 0.f);
    cheb_k<<<1563, 256>>>(pR, ph, pP, 2.f, -1.f);
    cheb_k<<<1563, 256>>>(pP, pR, pAP, 2.f, -1.f);
    aq_k<<<1, 32>>>(gamma);
    fuse_k<<<(NH_ + 255) / 256, 256>>>(asvr, aafm);

    // GAT layer 1 (coeffs fused into GEMM epilogue)
    gemm_gat1_k<<<GB, 256>>>(pF, W1, a1s, a1d);
    gat1_agg_k<<<6250, 256>>>(b1);

    // GAT layer 2
    gemm_k<<<GB, 256>>>(po1, W2, nullptr, pxw2, N_, 16, 64);
    gat2_coeff_k<<<196, 256>>>(a2s, a2d);
    gat2_agg_k<<<3125, 256>>>(b2, out);
}

// round 11
// speedup vs baseline: 1.6288x; 1.2041x over previous
#include <cuda_runtime.h>
#include <math.h>
#include <stdint.h>

#define N_  50000
#define E_  512000
#define IN_ 512
#define H_  128
#define NH_ (N_*H_)
#define DT_   0.1f
#define EPS_  1e-3f
#define TOL_  1e-4f
#define MAXIT_ 20
#define CGRID_ 444   // 148 SMs * 3 CTAs, co-resident via __launch_bounds__(256,3)

// ---------------- device scratch ----------------
__device__ __align__(16) float g_h[NH_];
__device__ __align__(16) float g_hs[NH_];
__device__ __align__(16) float g_X[NH_];
__device__ __align__(16) float g_R[NH_];
__device__ __align__(16) float g_P[NH_];
__device__ __align__(16) float g_AP[NH_];
__device__ __align__(16) float g_F[NH_];
__device__ float g_wL[E_];
__device__ float g_deg[N_];
__device__ float g_isd[N_];
__device__ int   g_cnt[N_];
__device__ int   g_ptr[N_ + 1];
__device__ int   g_adj[2 * E_];
__device__ float g_adjw[2 * E_];
__device__ int   g_incnt[N_];
__device__ int   g_inptr[N_ + 1];
__device__ int   g_insrc[E_ + N_];
__device__ float g_rsA[MAXIT_ + 1][H_];
__device__ float g_denA[MAXIT_][H_];
__device__ int   g_barc;
__device__ volatile int g_barp;
__device__ float g_aq[4];
__device__ __align__(16) float g_xw1[N_ * 64];
__device__ float g_es1[N_ * 8], g_ed1[N_ * 8];
__device__ __align__(16) float g_o1[N_ * 64];
__device__ __align__(16) float g_xw2[N_ * 16];
__device__ float g_es2[N_], g_ed2[N_];

// ---------------- helpers ----------------
__device__ __forceinline__ uint32_t f2tf32(float f)
{
    uint32_t u;
    asm("cvt.rna.tf32.f32 %0, %1;" : "=r"(u) : "f"(f));
    return u;
}
__device__ __forceinline__ void mma_tf32(float* c, const uint32_t* a, uint32_t b0, uint32_t b1)
{
    asm volatile(
        "mma.sync.aligned.m16n8k8.row.col.f32.tf32.tf32.f32 "
        "{%0,%1,%2,%3}, {%4,%5,%6,%7}, {%8,%9}, {%0,%1,%2,%3};\n"
        : "+f"(c[0]), "+f"(c[1]), "+f"(c[2]), "+f"(c[3])
        : "r"(a[0]), "r"(a[1]), "r"(a[2]), "r"(a[3]), "r"(b0), "r"(b1));
}

// -------- GEMM1 (tf32 tensor cores) + fused bias + LayerNorm + sigmoid -> g_h --------
// C[128 x 128] block tile, K=512 in chunks of 32, 8 warps in 4(m)x2(n).
__global__ __launch_bounds__(256) void gemm_lnsig_tf32_k(const float* __restrict__ A,
    const float* __restrict__ B, const float* __restrict__ bias,
    const float* __restrict__ lng, const float* __restrict__ lnb)
{
    __shared__ uint32_t As[128 * 36];   // [row][36], tf32 bits
    __shared__ uint32_t Bs[32 * 132];   // [k][132]
    __shared__ float ssum[128], ssq[128];
    int tid = threadIdx.x, lane = tid & 31, wid = tid >> 5;
    int wm = wid & 3, wn = wid >> 2;
    int gid = lane >> 2, ctid = lane & 3;
    int m0 = blockIdx.x * 128;
    float acc[2][8][4];
#pragma unroll
    for (int mt = 0; mt < 2; mt++)
#pragma unroll
        for (int nt = 0; nt < 8; nt++)
#pragma unroll
            for (int c = 0; c < 4; c++) acc[mt][nt][c] = 0.f;

    for (int k0 = 0; k0 < IN_; k0 += 32) {
        // load A tile (128 x 32) -> tf32
#pragma unroll
        for (int i = 0; i < 4; i++) {
            int f4 = tid + i * 256;
            int row = f4 >> 3, kq = f4 & 7;
            float4 v = make_float4(0.f, 0.f, 0.f, 0.f);
            if (m0 + row < N_) v = *(const float4*)(A + (size_t)(m0 + row) * IN_ + k0 + kq * 4);
            uint32_t* d = &As[row * 36 + kq * 4];
            d[0] = f2tf32(v.x); d[1] = f2tf32(v.y); d[2] = f2tf32(v.z); d[3] = f2tf32(v.w);
        }
        // load B tile (32 x 128) -> tf32
#pragma unroll
        for (int i = 0; i < 4; i++) {
            int f4 = tid + i * 256;
            int kr = f4 >> 5, cq = f4 & 31;
            float4 v = *(const float4*)(B + (size_t)(k0 + kr) * H_ + cq * 4);
            uint32_t* d = &Bs[kr * 132 + cq * 4];
            d[0] = f2tf32(v.x); d[1] = f2tf32(v.y); d[2] = f2tf32(v.z); d[3] = f2tf32(v.w);
        }
        __syncthreads();
#pragma unroll
        for (int k8 = 0; k8 < 32; k8 += 8) {
            uint32_t a[2][4];
#pragma unroll
            for (int mt = 0; mt < 2; mt++) {
                int r0 = wm * 32 + mt * 16 + gid;
                a[mt][0] = As[r0 * 36 + k8 + ctid];
                a[mt][1] = As[(r0 + 8) * 36 + k8 + ctid];
                a[mt][2] = As[r0 * 36 + k8 + ctid + 4];
                a[mt][3] = As[(r0 + 8) * 36 + k8 + ctid + 4];
            }
#pragma unroll
            for (int nt = 0; nt < 8; nt++) {
                int col = wn * 64 + nt * 8 + gid;
                uint32_t b0 = Bs[(k8 + ctid) * 132 + col];
                uint32_t b1 = Bs[(k8 + ctid + 4) * 132 + col];
                mma_tf32(acc[0][nt], a[0], b0, b1);
                mma_tf32(acc[1][nt], a[1], b0, b1);
            }
        }
        __syncthreads();
    }
    // ---- epilogue: bias + LN + sigmoid ----
    // thread owns rows r(mt,half) = wm*32+mt*16+gid+8*half, cols wn*64+nt*8+2*ctid+{0,1}
    float b2[8][2], gg[8][2], bb[8][2];
#pragma unroll
    for (int nt = 0; nt < 8; nt++) {
        int col = wn * 64 + nt * 8 + 2 * ctid;
        b2[nt][0] = bias[col]; b2[nt][1] = bias[col + 1];
        gg[nt][0] = lng[col];  gg[nt][1] = lng[col + 1];
        bb[nt][0] = lnb[col];  bb[nt][1] = lnb[col + 1];
    }
    if (tid < 128) { ssum[tid] = 0.f; ssq[tid] = 0.f; }
    __syncthreads();
#pragma unroll
    for (int mt = 0; mt < 2; mt++)
#pragma unroll
        for (int half = 0; half < 2; half++) {
            int r = wm * 32 + mt * 16 + gid + 8 * half;
            float s = 0.f;
#pragma unroll
            for (int nt = 0; nt < 8; nt++)
                s += (acc[mt][nt][2 * half] + b2[nt][0]) + (acc[mt][nt][2 * half + 1] + b2[nt][1]);
            atomicAdd(&ssum[r], s);
        }
    __syncthreads();
#pragma unroll
    for (int mt = 0; mt < 2; mt++)
#pragma unroll
        for (int half = 0; half < 2; half++) {
            int r = wm * 32 + mt * 16 + gid + 8 * half;
            float mean = ssum[r] * (1.f / 128.f);
            float q = 0.f;
#pragma unroll
            for (int nt = 0; nt < 8; nt++) {
                float d0 = acc[mt][nt][2 * half] + b2[nt][0] - mean;
                float d1 = acc[mt][nt][2 * half + 1] + b2[nt][1] - mean;
                q += d0 * d0 + d1 * d1;
            }
            atomicAdd(&ssq[r], q);
        }
    __syncthreads();
#pragma unroll
    for (int mt = 0; mt < 2; mt++)
#pragma unroll
        for (int half = 0; half < 2; half++) {
            int r = wm * 32 + mt * 16 + gid + 8 * half;
            if (m0 + r >= N_) continue;
            float mean = ssum[r] * (1.f / 128.f);
            float rstd = rsqrtf(ssq[r] * (1.f / 128.f) + 1e-5f);
#pragma unroll
            for (int nt = 0; nt < 8; nt++) {
                int col = wn * 64 + nt * 8 + 2 * ctid;
                float u0 = (acc[mt][nt][2 * half]     + b2[nt][0] - mean) * rstd * gg[nt][0] + bb[nt][0];
                float u1 = (acc[mt][nt][2 * half + 1] + b2[nt][1] - mean) * rstd * gg[nt][1] + bb[nt][1];
                float2 o;
                o.x = 1.f / (1.f + expf(-u0));
                o.y = 1.f / (1.f + expf(-u1));
                *(float2*)(g_h + (size_t)(m0 + r) * H_ + col) = o;
            }
        }
}

// ---------------- generic SIMT GEMM (sheaf / xw2) ----------------
__global__ __launch_bounds__(256) void gemm_k(const float* __restrict__ A,
    const float* __restrict__ B, const float* __restrict__ bias,
    float* __restrict__ C, int M, int Nc, int K)
{
    __shared__ float As[16][136];
    __shared__ float Bs[16][128];
    int tid = threadIdx.x, tx = tid & 15, ty = tid >> 4;
    int m0 = blockIdx.x * 128;
    float acc[8][8];
#pragma unroll
    for (int i = 0; i < 8; i++)
#pragma unroll
        for (int j = 0; j < 8; j++) acc[i][j] = 0.f;
    int ar = tid >> 2, ak = (tid & 3) << 2;
    int bk = tid >> 5, bc = (tid & 31) << 2;
    for (int k0 = 0; k0 < K; k0 += 16) {
#pragma unroll
        for (int h = 0; h < 2; h++) {
            int row = m0 + ar + h * 64;
            float4 v = make_float4(0.f, 0.f, 0.f, 0.f);
            if (row < M) v = *(const float4*)(A + (size_t)row * K + k0 + ak);
            As[ak + 0][ar + h * 64] = v.x; As[ak + 1][ar + h * 64] = v.y;
            As[ak + 2][ar + h * 64] = v.z; As[ak + 3][ar + h * 64] = v.w;
        }
#pragma unroll
        for (int h = 0; h < 2; h++) {
            int kk = bk + h * 8;
            float4 v = make_float4(0.f, 0.f, 0.f, 0.f);
            if (bc < Nc) v = *(const float4*)(B + (size_t)(k0 + kk) * Nc + bc);
            *(float4*)&Bs[kk][bc] = v;
        }
        __syncthreads();
#pragma unroll
        for (int k = 0; k < 16; k++) {
            float a[8], b[8];
            *(float4*)&a[0] = *(const float4*)&As[k][ty * 8];
            *(float4*)&a[4] = *(const float4*)&As[k][ty * 8 + 4];
            *(float4*)&b[0] = *(const float4*)&Bs[k][tx * 8];
            *(float4*)&b[4] = *(const float4*)&Bs[k][tx * 8 + 4];
#pragma unroll
            for (int i = 0; i < 8; i++)
#pragma unroll
                for (int j = 0; j < 8; j++) acc[i][j] += a[i] * b[j];
        }
        __syncthreads();
    }
#pragma unroll
    for (int i = 0; i < 8; i++) {
        int row = m0 + ty * 8 + i;
        if (row >= M) continue;
#pragma unroll
        for (int j = 0; j < 8; j++) {
            int cg = tx * 8 + j;
            if (cg < Nc) {
                float v = acc[i][j];
                if (bias) v += bias[cg];
                C[(size_t)row * Nc + cg] = v;
            }
        }
    }
}

// ------- xw1 GEMM (Nc=64,K=128) with fused GAT1 attention coefficients -------
__global__ __launch_bounds__(256) void gemm_gat1_k(const float* __restrict__ A,
    const float* __restrict__ B, const float* __restrict__ a1s,
    const float* __restrict__ a1d)
{
    const int K = 128, Nc = 64;
    __shared__ float As[16][136];
    __shared__ float Bs[16][128];
    int tid = threadIdx.x, tx = tid & 15, ty = tid >> 4;
    int m0 = blockIdx.x * 128;
    float acc[8][8];
#pragma unroll
    for (int i = 0; i < 8; i++)
#pragma unroll
        for (int j = 0; j < 8; j++) acc[i][j] = 0.f;
    int ar = tid >> 2, ak = (tid & 3) << 2;
    int bk = tid >> 5, bc = (tid & 31) << 2;
    for (int k0 = 0; k0 < K; k0 += 16) {
#pragma unroll
        for (int h = 0; h < 2; h++) {
            int row = m0 + ar + h * 64;
            float4 v = make_float4(0.f, 0.f, 0.f, 0.f);
            if (row < N_) v = *(const float4*)(A + (size_t)row * K + k0 + ak);
            As[ak + 0][ar + h * 64] = v.x; As[ak + 1][ar + h * 64] = v.y;
            As[ak + 2][ar + h * 64] = v.z; As[ak + 3][ar + h * 64] = v.w;
        }
#pragma unroll
        for (int h = 0; h < 2; h++) {
            int kk = bk + h * 8;
            float4 v = make_float4(0.f, 0.f, 0.f, 0.f);
            if (bc < Nc) v = *(const float4*)(B + (size_t)(k0 + kk) * Nc + bc);
            *(float4*)&Bs[kk][bc] = v;
        }
        __syncthreads();
#pragma unroll
        for (int k = 0; k < 16; k++) {
            float a[8], b[8];
            *(float4*)&a[0] = *(const float4*)&As[k][ty * 8];
            *(float4*)&a[4] = *(const float4*)&As[k][ty * 8 + 4];
            *(float4*)&b[0] = *(const float4*)&Bs[k][tx * 8];
            *(float4*)&b[4] = *(const float4*)&Bs[k][tx * 8 + 4];
#pragma unroll
            for (int i = 0; i < 8; i++)
#pragma unroll
                for (int j = 0; j < 8; j++) acc[i][j] += a[i] * b[j];
        }
        __syncthreads();
    }
    if (tx < 8) {
        float as[8], ad[8];
        *(float4*)&as[0] = *(const float4*)(a1s + tx * 8);
        *(float4*)&as[4] = *(const float4*)(a1s + tx * 8 + 4);
        *(float4*)&ad[0] = *(const float4*)(a1d + tx * 8);
        *(float4*)&ad[4] = *(const float4*)(a1d + tx * 8 + 4);
#pragma unroll
        for (int i = 0; i < 8; i++) {
            int row = m0 + ty * 8 + i;
            if (row >= N_) continue;
            float es = 0.f, ed = 0.f;
#pragma unroll
            for (int j = 0; j < 8; j++) { es += acc[i][j] * as[j]; ed += acc[i][j] * ad[j]; }
            g_es1[(size_t)row * 8 + tx] = es;
            g_ed1[(size_t)row * 8 + tx] = ed;
            *(float4*)(g_xw1 + (size_t)row * 64 + tx * 8)     = *(float4*)&acc[i][0];
            *(float4*)(g_xw1 + (size_t)row * 64 + tx * 8 + 4) = *(float4*)&acc[i][4];
        }
    }
}

// -------- edge weights + degree + CSR degree count (fused) --------
__global__ void edge_w_k(const int* __restrict__ row, const int* __restrict__ col)
{
    int w = threadIdx.x >> 5, lane = threadIdx.x & 31;
    int e0 = blockIdx.x * 32 + w * 4;
#pragma unroll
    for (int k = 0; k < 4; k++) {
        int e = e0 + k;
        if (e >= E_) return;
        int r = row[e], c = col[e];
        float4 a = *(const float4*)(g_hs + ((size_t)r << 7) + (lane << 2));
        float4 b = *(const float4*)(g_hs + ((size_t)c << 7) + (lane << 2));
        float d0 = a.x - b.x, d1 = a.y - b.y, d2 = a.z - b.z, d3 = a.w - b.w;
        float sd = d0 * d0 + d1 * d1 + d2 * d2 + d3 * d3;
        float sa = a.x * a.x + a.y * a.y + a.z * a.z + a.w * a.w;
#pragma unroll
        for (int o = 16; o; o >>= 1) {
            sd += __shfl_xor_sync(~0u, sd, o);
            sa += __shfl_xor_sync(~0u, sa, o);
        }
        if (lane == 0) {
            float C  = sd * (1.f / 128.f);
            float ex = expf(-C * (1.f / EPS_));
            float P0 = fminf(fmaxf(ex, 1e-3f), 1.f);
            float Ps = fminf(fmaxf((P0 + 1e-12f) * ex, 1e-3f), 1.f);
            float ww = 0.7f * P0 + 0.3f * Ps;
            float wl = ww * ww * sa * (1.f / 128.f);
            g_wL[e] = wl;
            atomicAdd(&g_deg[r], wl);
            atomicAdd(&g_deg[c], wl);
            atomicAdd(&g_cnt[r], 1);
            atomicAdd(&g_cnt[c], 1);
        }
    }
}

// ---------------- CSR build ----------------
__global__ void zero_i_k(int* p, int n) { int i = blockIdx.x * blockDim.x + threadIdx.x; if (i < n) p[i] = 0; }
__global__ void zero_f_k(float* p, int n) { int i = blockIdx.x * blockDim.x + threadIdx.x; if (i < n) p[i] = 0.f; }

__global__ void scan_k(int* __restrict__ cnt, int* __restrict__ ptr, int n)
{
    __shared__ int sh[1024];
    int t = threadIdx.x;
    int chunk = (n + 1023) / 1024;
    int lo = t * chunk, hi = min(lo + chunk, n);
    if (lo > n) lo = n;
    int s = 0;
    for (int i = lo; i < hi; i++) s += cnt[i];
    sh[t] = s;
    __syncthreads();
    for (int off = 1; off < 1024; off <<= 1) {
        int v = (t >= off) ? sh[t - off] : 0;
        __syncthreads();
        sh[t] += v;
        __syncthreads();
    }
    int run = sh[t] - s;
    for (int i = lo; i < hi; i++) {
        int c = cnt[i];
        ptr[i] = run; cnt[i] = run; run += c;
    }
    if (t == 1023) ptr[n] = sh[1023];
}
__global__ void scatter_adj_k(const int* __restrict__ row, const int* __restrict__ col)
{
    int e = blockIdx.x * blockDim.x + threadIdx.x;
    if (e >= E_) return;
    int r = row[e], c = col[e];
    float w = g_wL[e];
    int p = atomicAdd(&g_cnt[r], 1); g_adj[p] = c; g_adjw[p] = w;
    int q = atomicAdd(&g_cnt[c], 1); g_adj[q] = r; g_adjw[q] = w;
}
__global__ void init_incnt_k() { int n = blockIdx.x * blockDim.x + threadIdx.x; if (n < N_) g_incnt[n] = 1; }
__global__ void count_in_k(const int* __restrict__ col)
{
    int e = blockIdx.x * blockDim.x + threadIdx.x;
    if (e < E_) atomicAdd(&g_incnt[col[e]], 1);
}
__global__ void scatter_in_k(const int* __restrict__ row, const int* __restrict__ col)
{
    int e = blockIdx.x * blockDim.x + threadIdx.x;
    if (e >= E_) return;
    int p = atomicAdd(&g_incnt[col[e]], 1);
    g_insrc[p] = row[e];
}
__global__ void scatter_self_k()
{
    int n = blockIdx.x * blockDim.x + threadIdx.x;
    if (n >= N_) return;
    int p = atomicAdd(&g_incnt[n], 1);
    g_insrc[p] = n;
}

// ---------------- grid barrier ----------------
__device__ __forceinline__ void gridbar()
{
    __threadfence();
    __syncthreads();
    if (threadIdx.x == 0) {
        int ph = g_barp;
        if (atomicAdd(&g_barc, 1) == (int)gridDim.x - 1) {
            g_barc = 0;
            __threadfence();
            g_barp = ph ^ 1;
        } else {
            while (g_barp == ph) __nanosleep(32);
        }
    }
    __syncthreads();
}

// ---------------- persistent CG ----------------
__global__ void cg_init2_k()
{
    int t = threadIdx.x;
    float* rs = &g_rsA[0][0];
    float* dn = &g_denA[0][0];
    for (int i = t; i < (MAXIT_ + 1) * H_; i += 256) rs[i] = 0.f;
    for (int i = t; i < MAXIT_ * H_; i += 256) dn[i] = 0.f;
    if (t == 0) { g_barc = 0; g_barp = 0; }
}

__global__ __launch_bounds__(256, 3) void cg_persist_k()
{
    __shared__ float sbin[128];
    int tid = threadIdx.x;
    int gtid = blockIdx.x * 256 + tid;
    int stride = gridDim.x * 256;
    int c0 = (gtid & 31) * 4;
    int lane = tid & 31, wid = tid >> 5;
    int gwarp = blockIdx.x * 8 + wid;
    int nwarp = gridDim.x * 8;
    const int NV4 = NH_ / 4;

    if (tid < 128) sbin[tid] = 0.f;
    __syncthreads();
    {
        float a0 = 0.f, a1 = 0.f, a2 = 0.f, a3 = 0.f;
        for (int j = gtid; j < NV4; j += stride) {
            float4 h = ((const float4*)g_h)[j];
            ((float4*)g_X)[j] = make_float4(0.f, 0.f, 0.f, 0.f);
            ((float4*)g_R)[j] = h;
            ((float4*)g_P)[j] = h;
            a0 += h.x * h.x; a1 += h.y * h.y; a2 += h.z * h.z; a3 += h.w * h.w;
        }
        atomicAdd(&sbin[c0 + 0], a0); atomicAdd(&sbin[c0 + 1], a1);
        atomicAdd(&sbin[c0 + 2], a2); atomicAdd(&sbin[c0 + 3], a3);
    }
    __syncthreads();
    if (tid < 128) { float v = sbin[tid]; if (v != 0.f) atomicAdd(&g_rsA[0][tid], v); }
    gridbar();

    for (int it = 0; it < MAXIT_; it++) {
        if (it > 0) {
            if (tid < 128) sbin[tid] = __ldcg(&g_rsA[it][tid]);
            __syncthreads();
            for (int o = 64; o; o >>= 1) {
                if (tid < o) sbin[tid] = fmaxf(sbin[tid], sbin[tid + o]);
                __syncthreads();
            }
            bool done = sbin[0] < TOL_ * TOL_;
            __syncthreads();
            if (done) break;
            float b0 = __ldcg(&g_rsA[it][c0 + 0]) / (__ldcg(&g_rsA[it - 1][c0 + 0]) + 1e-16f);
            float b1 = __ldcg(&g_rsA[it][c0 + 1]) / (__ldcg(&g_rsA[it - 1][c0 + 1]) + 1e-16f);
            float b2 = __ldcg(&g_rsA[it][c0 + 2]) / (__ldcg(&g_rsA[it - 1][c0 + 2]) + 1e-16f);
            float b3 = __ldcg(&g_rsA[it][c0 + 3]) / (__ldcg(&g_rsA[it - 1][c0 + 3]) + 1e-16f);
            for (int j = gtid; j < NV4; j += stride) {
                float4 r = ((const float4*)g_R)[j];
                float4 p = ((const float4*)g_P)[j];
                p.x = r.x + b0 * p.x; p.y = r.y + b1 * p.y;
                p.z = r.z + b2 * p.z; p.w = r.w + b3 * p.w;
                ((float4*)g_P)[j] = p;
            }
            gridbar();
        }
        if (tid < 128) sbin[tid] = 0.f;
        __syncthreads();
        {
            float d0 = 0.f, d1 = 0.f, d2 = 0.f, d3 = 0.f;
            for (int wc = gwarp; wc < N_ / 4; wc += nwarp) {
                int nb0 = wc * 4;
#pragma unroll
                for (int k2 = 0; k2 < 4; k2++) {
                    int node = nb0 + k2;
                    int j0 = g_ptr[node], j1 = g_ptr[node + 1];
                    float4 a = make_float4(0.f, 0.f, 0.f, 0.f);
                    for (int j = j0; j < j1; j++) {
                        int nb = g_adj[j]; float wv = g_adjw[j];
                        float4 v = __ldcg((const float4*)g_P + ((size_t)nb << 5) + lane);
                        a.x += wv * v.x; a.y += wv * v.y; a.z += wv * v.z; a.w += wv * v.w;
                    }
                    float cc = 1.f + DT_ * g_deg[node];
                    float4 p = __ldcg((const float4*)g_P + ((size_t)node << 5) + lane);
                    float4 o;
                    o.x = cc * p.x - DT_ * a.x; o.y = cc * p.y - DT_ * a.y;
                    o.z = cc * p.z - DT_ * a.z; o.w = cc * p.w - DT_ * a.w;
                    ((float4*)g_AP)[((size_t)node << 5) + lane] = o;
                    d0 += p.x * o.x; d1 += p.y * o.y; d2 += p.z * o.z; d3 += p.w * o.w;
                }
            }
            atomicAdd(&sbin[lane * 4 + 0], d0); atomicAdd(&sbin[lane * 4 + 1], d1);
            atomicAdd(&sbin[lane * 4 + 2], d2); atomicAdd(&sbin[lane * 4 + 3], d3);
        }
        __syncthreads();
        if (tid < 128) { float v = sbin[tid]; if (v != 0.f) atomicAdd(&g_denA[it][tid], v); }
        gridbar();
        if (tid < 128) sbin[tid] = 0.f;
        __syncthreads();
        {
            float al0 = __ldcg(&g_rsA[it][c0 + 0]) / (__ldcg(&g_denA[it][c0 + 0]) + 1e-16f);
            float al1 = __ldcg(&g_rsA[it][c0 + 1]) / (__ldcg(&g_denA[it][c0 + 1]) + 1e-16f);
            float al2 = __ldcg(&g_rsA[it][c0 + 2]) / (__ldcg(&g_denA[it][c0 + 2]) + 1e-16f);
            float al3 = __ldcg(&g_rsA[it][c0 + 3]) / (__ldcg(&g_denA[it][c0 + 3]) + 1e-16f);
            float s0 = 0.f, s1 = 0.f, s2 = 0.f, s3 = 0.f;
            for (int j = gtid; j < NV4; j += stride) {
                float4 p  = ((const float4*)g_P)[j];
                float4 ap = __ldcg((const float4*)g_AP + j);
                float4 x  = ((const float4*)g_X)[j];
                float4 r  = ((const float4*)g_R)[j];
                x.x += al0 * p.x; x.y += al1 * p.y; x.z += al2 * p.z; x.w += al3 * p.w;
                r.x -= al0 * ap.x; r.y -= al1 * ap.y; r.z -= al2 * ap.z; r.w -= al3 * ap.w;
                ((float4*)g_X)[j] = x;
                ((float4*)g_R)[j] = r;
                s0 += r.x * r.x; s1 += r.y * r.y; s2 += r.z * r.z; s3 += r.w * r.w;
            }
            atomicAdd(&sbin[c0 + 0], s0); atomicAdd(&sbin[c0 + 1], s1);
            atomicAdd(&sbin[c0 + 2], s2); atomicAdd(&sbin[c0 + 3], s3);
        }
        __syncthreads();
        if (tid < 128) { float v = sbin[tid]; if (v != 0.f) atomicAdd(&g_rsA[it + 1][tid], v); }
        gridbar();
    }
}

// ---------------- persistent AFM: isd + 3x tildeL + softmax(gamma) + fuse ----------------
__device__ __forceinline__ void tildeL_phase(const float* __restrict__ M,
    const float* __restrict__ Mp, float* __restrict__ out, float cA, float cB)
{
    int lane = threadIdx.x & 31, wid = threadIdx.x >> 5;
    int gwarp = blockIdx.x * 8 + wid, nwarp = gridDim.x * 8;
    for (int wc = gwarp; wc < N_ / 4; wc += nwarp) {
#pragma unroll
        for (int k = 0; k < 4; k++) {
            int node = wc * 4 + k;
            int j0 = g_ptr[node], j1 = g_ptr[node + 1];
            float4 a = make_float4(0.f, 0.f, 0.f, 0.f);
            for (int j = j0; j < j1; j++) {
                int nb = g_adj[j];
                float wv = g_adjw[j] * __ldcg(&g_isd[nb]);
                float4 v = __ldcg((const float4*)M + ((size_t)nb << 5) + lane);
                a.x += wv * v.x; a.y += wv * v.y; a.z += wv * v.z; a.w += wv * v.w;
            }
            float is = __ldcg(&g_isd[node]);
            float c0 = g_deg[node] * is * is;
            size_t base = ((size_t)node << 5) + lane;
            float4 m  = __ldcg((const float4*)M + base);
            float4 mp = __ldcg((const float4*)Mp + base);
            float4 o;
            o.x = cA * (m.x + c0 * m.x - is * a.x) + cB * mp.x;
            o.y = cA * (m.y + c0 * m.y - is * a.y) + cB * mp.y;
            o.z = cA * (m.z + c0 * m.z - is * a.z) + cB * mp.z;
            o.w = cA * (m.w + c0 * m.w - is * a.w) + cB * mp.w;
            ((float4*)out)[base] = o;
        }
    }
}

__global__ __launch_bounds__(256, 3) void afm_persist_k(const float* __restrict__ gamma,
    const float* __restrict__ asvr, const float* __restrict__ aafm)
{
    int tid = threadIdx.x;
    int g0 = blockIdx.x * 256 + tid;
    int stride = gridDim.x * 256;
    // phase A: isd + aq
    for (int n = g0; n < N_; n += stride)
        g_isd[n] = rsqrtf(fmaxf(g_deg[n], 1e-8f));
    if (blockIdx.x == 0 && tid == 0) {
        float m = gamma[0];
        for (int i = 1; i < 4; i++) m = fmaxf(m, gamma[i]);
        float e[4], s = 0.f;
        for (int i = 0; i < 4; i++) { e[i] = expf(gamma[i] - m); s += e[i]; }
        for (int i = 0; i < 4; i++) g_aq[i] = e[i] / s;
    }
    gridbar();
    tildeL_phase(g_h, g_h, g_R, 1.f, 0.f);   // T1
    gridbar();
    tildeL_phase(g_R, g_h, g_P, 2.f, -1.f);  // T2
    gridbar();
    tildeL_phase(g_P, g_R, g_AP, 2.f, -1.f); // T3
    gridbar();
    // fuse
    float s1 = 1.f / (1.f + expf(-asvr[0]));
    float s2 = 1.f / (1.f + expf(-aafm[0]));
    float a0 = __ldcg(&g_aq[0]), a1 = __ldcg(&g_aq[1]);
    float a2 = __ldcg(&g_aq[2]), a3 = __ldcg(&g_aq[3]);
    const int NV4 = NH_ / 4;
    for (int j = g0; j < NV4; j += stride) {
        float4 h = ((const float4*)g_h)[j];
        float4 x = ((const float4*)g_X)[j];
        float4 r  = __ldcg((const float4*)g_R + j);
        float4 p  = __ldcg((const float4*)g_P + j);
        float4 ap = __ldcg((const float4*)g_AP + j);
        float4 o;
        o.x = h.x + s1 * x.x + s2 * (a0 * h.x + a1 * r.x + a2 * p.x + a3 * ap.x);
        o.y = h.y + s1 * x.y + s2 * (a0 * h.y + a1 * r.y + a2 * p.y + a3 * ap.y);
        o.z = h.z + s1 * x.z + s2 * (a0 * h.z + a1 * r.z + a2 * p.z + a3 * ap.z);
        o.w = h.w + s1 * x.w + s2 * (a0 * h.w + a1 * r.w + a2 * p.w + a3 * ap.w);
        ((float4*)g_F)[j] = o;
    }
}

// ---------------- GAT aggregation ----------------
__global__ void gat1_agg_k(const float* __restrict__ b1)
{
    int node = blockIdx.x * 8 + (threadIdx.x >> 5);
    if (node >= N_) return;
    int lane = threadIdx.x & 31;
    int head = lane >> 2;
    int c0 = (lane & 3) * 2;
    float edv = g_ed1[(size_t)node * 8 + head];
    int j0 = g_inptr[node], j1 = g_inptr[node + 1];
    float m = -3.4e38f, den = 0.f, a0 = 0.f, a1 = 0.f;
    for (int j = j0; j < j1; j++) {
        int s = g_insrc[j];
        float e = g_es1[(size_t)s * 8 + head] + edv;
        e = e >= 0.f ? e : 0.2f * e;
        float mn = fmaxf(m, e);
        float sc = expf(m - mn);
        float p  = expf(e - mn);
        const float* xw = g_xw1 + (size_t)s * 64 + head * 8 + c0;
        den = den * sc + p;
        a0  = a0 * sc + p * xw[0];
        a1  = a1 * sc + p * xw[1];
        m = mn;
    }
    float inv = 1.f / (den + 1e-16f);
    float v0 = a0 * inv + b1[head * 8 + c0];
    float v1 = a1 * inv + b1[head * 8 + c0 + 1];
    v0 = v0 > 0.f ? v0 : expm1f(v0);
    v1 = v1 > 0.f ? v1 : expm1f(v1);
    float* o = g_o1 + (size_t)node * 64 + head * 8 + c0;
    o[0] = v0; o[1] = v1;
}
__global__ void gat2_coeff_k(const float* __restrict__ a2s, const float* __restrict__ a2d)
{
    int n = blockIdx.x * blockDim.x + threadIdx.x;
    if (n >= N_) return;
    float es = 0.f, ed = 0.f;
#pragma unroll
    for (int c = 0; c < 16; c++) { float v = g_xw2[(size_t)n * 16 + c]; es += v * a2s[c]; ed += v * a2d[c]; }
    g_es2[n] = es; g_ed2[n] = ed;
}
__global__ void gat2_agg_k(const float* __restrict__ b2, float* __restrict__ out)
{
    int node = blockIdx.x * 16 + (threadIdx.x >> 4);
    if (node >= N_) return;
    int ch = threadIdx.x & 15;
    float edv = g_ed2[node];
    int j0 = g_inptr[node], j1 = g_inptr[node + 1];
    float m = -3.4e38f, den = 0.f, acc = 0.f;
    for (int j = j0; j < j1; j++) {
        int s = g_insrc[j];
        float e = g_es2[s] + edv;
        e = e >= 0.f ? e : 0.2f * e;
        float mn = fmaxf(m, e);
        float sc = expf(m - mn);
        float p  = expf(e - mn);
        den = den * sc + p;
        acc = acc * sc + p * g_xw2[(size_t)s * 16 + ch];
        m = mn;
    }
    out[(size_t)node * 16 + ch] = acc / (den + 1e-16f) + b2[ch];
}

// ---------------- host ----------------
#define SYM(p, s) do { void* _t; cudaGetSymbolAddress(&_t, s); p = (decltype(p))_t; } while(0)

extern "C" void kernel_launch(void* const* d_in, const int* in_sizes, int n_in,
                              void* d_out, int out_size)
{
    const float* x      = (const float*)d_in[0];
    const int*   ei     = (const int*)d_in[1];
    const float* W_in   = (const float*)d_in[2];
    const float* b_in   = (const float*)d_in[3];
    const float* ln_g   = (const float*)d_in[4];
    const float* ln_b   = (const float*)d_in[5];
    const float* W_sh   = (const float*)d_in[6];
    const float* gamma  = (const float*)d_in[7];
    const float* asvr   = (const float*)d_in[8];
    const float* aafm   = (const float*)d_in[9];
    const float* W1     = (const float*)d_in[10];
    const float* a1s    = (const float*)d_in[11];
    const float* a1d    = (const float*)d_in[12];
    const float* b1     = (const float*)d_in[13];
    const float* W2     = (const float*)d_in[14];
    const float* a2s    = (const float*)d_in[15];
    const float* a2d    = (const float*)d_in[16];
    const float* b2     = (const float*)d_in[17];
    const int* row = ei, * col = ei + E_;
    float* out = (float*)d_out;

    float *ph, *phs, *pF, *po1, *pxw2, *pdeg;
    int *pcnt, *pincnt, *pptr, *pinptr;
    SYM(ph, g_h); SYM(phs, g_hs); SYM(pF, g_F); SYM(po1, g_o1); SYM(pxw2, g_xw2);
    SYM(pdeg, g_deg);
    SYM(pcnt, g_cnt); SYM(pincnt, g_incnt); SYM(pptr, g_ptr); SYM(pinptr, g_inptr);

    const int GB = 391;           // ceil(50000/128)
    zero_f_k<<<196, 256>>>(pdeg, N_);
    zero_i_k<<<196, 256>>>(pcnt, N_);

    // h = sigmoid(LN(x@W_in + b_in)) via tf32 tensor cores; hs = h@W_sheaf
    gemm_lnsig_tf32_k<<<GB, 256>>>(x, W_in, b_in, ln_g, ln_b);
    gemm_k<<<GB, 256>>>(ph, W_sh, nullptr, phs, N_, 128, 128);

    // edge weights + degrees + CSR counts (fused)
    edge_w_k<<<16000, 256>>>(row, col);

    // symmetric CSR
    scan_k<<<1, 1024>>>(pcnt, pptr, N_);
    scatter_adj_k<<<2000, 256>>>(row, col);
    // incoming CSR (with self-loops) for GAT
    init_incnt_k<<<196, 256>>>();
    count_in_k<<<2000, 256>>>(col);
    scan_k<<<1, 1024>>>(pincnt, pinptr, N_);
    scatter_in_k<<<2000, 256>>>(row, col);
    scatter_self_k<<<196, 256>>>();

    // persistent CG
    cg_init2_k<<<1, 256>>>();
    cg_persist_k<<<CGRID_, 256>>>();

    // persistent AFM (isd + T1..T3 + softmax + fuse)
    afm_persist_k<<<CGRID_, 256>>>(gamma, asvr, aafm);

    // GAT layer 1 (coeffs fused into GEMM epilogue)
    gemm_gat1_k<<<GB, 256>>>(pF, W1, a1s, a1d);
    gat1_agg_k<<<6250, 256>>>(b1);

    // GAT layer 2
    gemm_k<<<GB, 256>>>(po1, W2, nullptr, pxw2, N_, 16, 64);
    gat2_coeff_k<<<196, 256>>>(a2s, a2d);
    gat2_agg_k<<<3125, 256>>>(b2, out);
}

// round 12
// speedup vs baseline: 1.7931x; 1.1009x over previous
#include <cuda_runtime.h>
#include <math.h>
#include <stdint.h>

#define N_  50000
#define E_  512000
#define IN_ 512
#define H_  128
#define NH_ (N_*H_)
#define DT_   0.1f
#define EPS_  1e-3f
#define TOL_  1e-4f
#define MAXIT_ 20
#define CGRID_ 444

// ---------------- device scratch ----------------
__device__ __align__(16) float g_h[NH_];
__device__ __align__(16) float g_hs[NH_];
__device__ __align__(16) float g_X[NH_];
__device__ __align__(16) float g_R[NH_];
__device__ __align__(16) float g_P[NH_];
__device__ __align__(16) float g_AP[NH_];
__device__ __align__(16) float g_F[NH_];
__device__ float g_wL[E_];
__device__ float g_deg[N_];
__device__ float g_isd[N_];
__device__ int   g_cnt[N_];
__device__ int   g_ptr[N_ + 1];
__device__ int   g_adj[2 * E_];
__device__ float g_adjw[2 * E_];
__device__ int   g_incnt[N_];
__device__ int   g_inptr[N_ + 1];
__device__ int   g_insrc[E_ + N_];
__device__ float g_rsA[MAXIT_ + 1][H_];
__device__ float g_denA[MAXIT_][H_];
__device__ int   g_barc;
__device__ volatile int g_barp;
__device__ float g_aq[4];
__device__ __align__(16) float g_xw1[N_ * 64];
__device__ float g_es1[N_ * 8], g_ed1[N_ * 8];
__device__ __align__(16) float g_o1[N_ * 64];
__device__ __align__(16) float g_xw2[N_ * 16];
__device__ float g_es2[N_], g_ed2[N_];

// ---------------- tf32 helpers ----------------
__device__ __forceinline__ uint32_t f2tf32(float f)
{
    uint32_t u;
    asm("cvt.rna.tf32.f32 %0, %1;" : "=r"(u) : "f"(f));
    return u;
}
__device__ __forceinline__ void mma_tf32(float* c, const uint32_t* a, uint32_t b0, uint32_t b1)
{
    asm volatile(
        "mma.sync.aligned.m16n8k8.row.col.f32.tf32.tf32.f32 "
        "{%0,%1,%2,%3}, {%4,%5,%6,%7}, {%8,%9}, {%0,%1,%2,%3};\n"
        : "+f"(c[0]), "+f"(c[1]), "+f"(c[2]), "+f"(c[3])
        : "r"(a[0]), "r"(a[1]), "r"(a[2]), "r"(a[3]), "r"(b0), "r"(b1));
}

// -------- GEMM1 tf32 + fused bias + LayerNorm + sigmoid -> g_h --------
__global__ __launch_bounds__(256) void gemm_lnsig_tf32_k(const float* __restrict__ A,
    const float* __restrict__ B, const float* __restrict__ bias,
    const float* __restrict__ lng, const float* __restrict__ lnb)
{
    __shared__ uint32_t As[128 * 36];
    __shared__ uint32_t Bs[32 * 132];
    __shared__ float ssum[128], ssq[128];
    int tid = threadIdx.x, lane = tid & 31, wid = tid >> 5;
    int wm = wid & 3, wn = wid >> 2;
    int gid = lane >> 2, ctid = lane & 3;
    int m0 = blockIdx.x * 128;
    float acc[2][8][4];
#pragma unroll
    for (int mt = 0; mt < 2; mt++)
#pragma unroll
        for (int nt = 0; nt < 8; nt++)
#pragma unroll
            for (int c = 0; c < 4; c++) acc[mt][nt][c] = 0.f;

    for (int k0 = 0; k0 < IN_; k0 += 32) {
#pragma unroll
        for (int i = 0; i < 4; i++) {
            int f4 = tid + i * 256;
            int row = f4 >> 3, kq = f4 & 7;
            float4 v = make_float4(0.f, 0.f, 0.f, 0.f);
            if (m0 + row < N_) v = *(const float4*)(A + (size_t)(m0 + row) * IN_ + k0 + kq * 4);
            uint32_t* d = &As[row * 36 + kq * 4];
            d[0] = f2tf32(v.x); d[1] = f2tf32(v.y); d[2] = f2tf32(v.z); d[3] = f2tf32(v.w);
        }
#pragma unroll
        for (int i = 0; i < 4; i++) {
            int f4 = tid + i * 256;
            int kr = f4 >> 5, cq = f4 & 31;
            float4 v = *(const float4*)(B + (size_t)(k0 + kr) * H_ + cq * 4);
            uint32_t* d = &Bs[kr * 132 + cq * 4];
            d[0] = f2tf32(v.x); d[1] = f2tf32(v.y); d[2] = f2tf32(v.z); d[3] = f2tf32(v.w);
        }
        __syncthreads();
#pragma unroll
        for (int k8 = 0; k8 < 32; k8 += 8) {
            uint32_t a[2][4];
#pragma unroll
            for (int mt = 0; mt < 2; mt++) {
                int r0 = wm * 32 + mt * 16 + gid;
                a[mt][0] = As[r0 * 36 + k8 + ctid];
                a[mt][1] = As[(r0 + 8) * 36 + k8 + ctid];
                a[mt][2] = As[r0 * 36 + k8 + ctid + 4];
                a[mt][3] = As[(r0 + 8) * 36 + k8 + ctid + 4];
            }
#pragma unroll
            for (int nt = 0; nt < 8; nt++) {
                int col = wn * 64 + nt * 8 + gid;
                uint32_t b0 = Bs[(k8 + ctid) * 132 + col];
                uint32_t b1 = Bs[(k8 + ctid + 4) * 132 + col];
                mma_tf32(acc[0][nt], a[0], b0, b1);
                mma_tf32(acc[1][nt], a[1], b0, b1);
            }
        }
        __syncthreads();
    }
    float b2[8][2], gg[8][2], bb[8][2];
#pragma unroll
    for (int nt = 0; nt < 8; nt++) {
        int col = wn * 64 + nt * 8 + 2 * ctid;
        b2[nt][0] = bias[col]; b2[nt][1] = bias[col + 1];
        gg[nt][0] = lng[col];  gg[nt][1] = lng[col + 1];
        bb[nt][0] = lnb[col];  bb[nt][1] = lnb[col + 1];
    }
    if (tid < 128) { ssum[tid] = 0.f; ssq[tid] = 0.f; }
    __syncthreads();
#pragma unroll
    for (int mt = 0; mt < 2; mt++)
#pragma unroll
        for (int half = 0; half < 2; half++) {
            int r = wm * 32 + mt * 16 + gid + 8 * half;
            float s = 0.f;
#pragma unroll
            for (int nt = 0; nt < 8; nt++)
                s += (acc[mt][nt][2 * half] + b2[nt][0]) + (acc[mt][nt][2 * half + 1] + b2[nt][1]);
            atomicAdd(&ssum[r], s);
        }
    __syncthreads();
#pragma unroll
    for (int mt = 0; mt < 2; mt++)
#pragma unroll
        for (int half = 0; half < 2; half++) {
            int r = wm * 32 + mt * 16 + gid + 8 * half;
            float mean = ssum[r] * (1.f / 128.f);
            float q = 0.f;
#pragma unroll
            for (int nt = 0; nt < 8; nt++) {
                float d0 = acc[mt][nt][2 * half] + b2[nt][0] - mean;
                float d1 = acc[mt][nt][2 * half + 1] + b2[nt][1] - mean;
                q += d0 * d0 + d1 * d1;
            }
            atomicAdd(&ssq[r], q);
        }
    __syncthreads();
#pragma unroll
    for (int mt = 0; mt < 2; mt++)
#pragma unroll
        for (int half = 0; half < 2; half++) {
            int r = wm * 32 + mt * 16 + gid + 8 * half;
            if (m0 + r >= N_) continue;
            float mean = ssum[r] * (1.f / 128.f);
            float rstd = rsqrtf(ssq[r] * (1.f / 128.f) + 1e-5f);
#pragma unroll
            for (int nt = 0; nt < 8; nt++) {
                int col = wn * 64 + nt * 8 + 2 * ctid;
                float u0 = (acc[mt][nt][2 * half]     + b2[nt][0] - mean) * rstd * gg[nt][0] + bb[nt][0];
                float u1 = (acc[mt][nt][2 * half + 1] + b2[nt][1] - mean) * rstd * gg[nt][1] + bb[nt][1];
                float2 o;
                o.x = 1.f / (1.f + expf(-u0));
                o.y = 1.f / (1.f + expf(-u1));
                *(float2*)(g_h + (size_t)(m0 + r) * H_ + col) = o;
            }
        }
}

// -------- sheaf GEMM tf32: g_hs = g_h @ W_sh (128x128, K=128) --------
__global__ __launch_bounds__(256) void gemm_sheaf_tf32_k(const float* __restrict__ B)
{
    __shared__ uint32_t As[128 * 36];
    __shared__ uint32_t Bs[32 * 132];
    int tid = threadIdx.x, lane = tid & 31, wid = tid >> 5;
    int wm = wid & 3, wn = wid >> 2;
    int gid = lane >> 2, ctid = lane & 3;
    int m0 = blockIdx.x * 128;
    float acc[2][8][4];
#pragma unroll
    for (int mt = 0; mt < 2; mt++)
#pragma unroll
        for (int nt = 0; nt < 8; nt++)
#pragma unroll
            for (int c = 0; c < 4; c++) acc[mt][nt][c] = 0.f;

    for (int k0 = 0; k0 < H_; k0 += 32) {
#pragma unroll
        for (int i = 0; i < 4; i++) {
            int f4 = tid + i * 256;
            int row = f4 >> 3, kq = f4 & 7;
            float4 v = make_float4(0.f, 0.f, 0.f, 0.f);
            if (m0 + row < N_) v = *(const float4*)(g_h + (size_t)(m0 + row) * H_ + k0 + kq * 4);
            uint32_t* d = &As[row * 36 + kq * 4];
            d[0] = f2tf32(v.x); d[1] = f2tf32(v.y); d[2] = f2tf32(v.z); d[3] = f2tf32(v.w);
        }
#pragma unroll
        for (int i = 0; i < 4; i++) {
            int f4 = tid + i * 256;
            int kr = f4 >> 5, cq = f4 & 31;
            float4 v = *(const float4*)(B + (size_t)(k0 + kr) * H_ + cq * 4);
            uint32_t* d = &Bs[kr * 132 + cq * 4];
            d[0] = f2tf32(v.x); d[1] = f2tf32(v.y); d[2] = f2tf32(v.z); d[3] = f2tf32(v.w);
        }
        __syncthreads();
#pragma unroll
        for (int k8 = 0; k8 < 32; k8 += 8) {
            uint32_t a[2][4];
#pragma unroll
            for (int mt = 0; mt < 2; mt++) {
                int r0 = wm * 32 + mt * 16 + gid;
                a[mt][0] = As[r0 * 36 + k8 + ctid];
                a[mt][1] = As[(r0 + 8) * 36 + k8 + ctid];
                a[mt][2] = As[r0 * 36 + k8 + ctid + 4];
                a[mt][3] = As[(r0 + 8) * 36 + k8 + ctid + 4];
            }
#pragma unroll
            for (int nt = 0; nt < 8; nt++) {
                int col = wn * 64 + nt * 8 + gid;
                uint32_t b0 = Bs[(k8 + ctid) * 132 + col];
                uint32_t b1 = Bs[(k8 + ctid + 4) * 132 + col];
                mma_tf32(acc[0][nt], a[0], b0, b1);
                mma_tf32(acc[1][nt], a[1], b0, b1);
            }
        }
        __syncthreads();
    }
#pragma unroll
    for (int mt = 0; mt < 2; mt++)
#pragma unroll
        for (int half = 0; half < 2; half++) {
            int r = wm * 32 + mt * 16 + gid + 8 * half;
            if (m0 + r >= N_) continue;
#pragma unroll
            for (int nt = 0; nt < 8; nt++) {
                int col = wn * 64 + nt * 8 + 2 * ctid;
                float2 o;
                o.x = acc[mt][nt][2 * half];
                o.y = acc[mt][nt][2 * half + 1];
                *(float2*)(g_hs + (size_t)(m0 + r) * H_ + col) = o;
            }
        }
}

// -------- gat1 GEMM tf32: xw1 = F @ W1 (tile 128x64, K=128) + es/ed --------
__global__ __launch_bounds__(256) void gemm_gat1_tf32_k(const float* __restrict__ B,
    const float* __restrict__ a1s, const float* __restrict__ a1d)
{
    __shared__ uint32_t As[128 * 36];
    __shared__ uint32_t Bs[32 * 68];
    int tid = threadIdx.x, lane = tid & 31, wid = tid >> 5;
    int gid = lane >> 2, ctid = lane & 3;
    int m0 = blockIdx.x * 128;
    float acc[8][4];
#pragma unroll
    for (int nt = 0; nt < 8; nt++)
#pragma unroll
        for (int c = 0; c < 4; c++) acc[nt][c] = 0.f;

    for (int k0 = 0; k0 < 128; k0 += 32) {
#pragma unroll
        for (int i = 0; i < 4; i++) {
            int f4 = tid + i * 256;
            int row = f4 >> 3, kq = f4 & 7;
            float4 v = make_float4(0.f, 0.f, 0.f, 0.f);
            if (m0 + row < N_) v = *(const float4*)(g_F + (size_t)(m0 + row) * H_ + k0 + kq * 4);
            uint32_t* d = &As[row * 36 + kq * 4];
            d[0] = f2tf32(v.x); d[1] = f2tf32(v.y); d[2] = f2tf32(v.z); d[3] = f2tf32(v.w);
        }
        // B tile 32 x 64 : 512 float4 / 256 threads = 2 iters
#pragma unroll
        for (int i = 0; i < 2; i++) {
            int f4 = tid + i * 256;
            int kr = f4 >> 4, cq = f4 & 15;
            float4 v = *(const float4*)(B + (size_t)(k0 + kr) * 64 + cq * 4);
            uint32_t* d = &Bs[kr * 68 + cq * 4];
            d[0] = f2tf32(v.x); d[1] = f2tf32(v.y); d[2] = f2tf32(v.z); d[3] = f2tf32(v.w);
        }
        __syncthreads();
#pragma unroll
        for (int k8 = 0; k8 < 32; k8 += 8) {
            uint32_t a[4];
            int r0 = wid * 16 + gid;
            a[0] = As[r0 * 36 + k8 + ctid];
            a[1] = As[(r0 + 8) * 36 + k8 + ctid];
            a[2] = As[r0 * 36 + k8 + ctid + 4];
            a[3] = As[(r0 + 8) * 36 + k8 + ctid + 4];
#pragma unroll
            for (int nt = 0; nt < 8; nt++) {
                int col = nt * 8 + gid;
                uint32_t b0 = Bs[(k8 + ctid) * 68 + col];
                uint32_t b1 = Bs[(k8 + ctid + 4) * 68 + col];
                mma_tf32(acc[nt], a, b0, b1);
            }
        }
        __syncthreads();
    }
    // store xw1 + fused es/ed (head = nt; cols 2*ctid,2*ctid+1 inside head)
    float as[8][2], ad[8][2];
#pragma unroll
    for (int nt = 0; nt < 8; nt++) {
        int c = nt * 8 + 2 * ctid;
        as[nt][0] = a1s[c]; as[nt][1] = a1s[c + 1];
        ad[nt][0] = a1d[c]; ad[nt][1] = a1d[c + 1];
    }
#pragma unroll
    for (int half = 0; half < 2; half++) {
        int r = wid * 16 + gid + 8 * half;
        bool ok = (m0 + r < N_);
#pragma unroll
        for (int nt = 0; nt < 8; nt++) {
            float v0 = acc[nt][2 * half], v1 = acc[nt][2 * half + 1];
            if (ok) {
                float2 o; o.x = v0; o.y = v1;
                *(float2*)(g_xw1 + (size_t)(m0 + r) * 64 + nt * 8 + 2 * ctid) = o;
            }
            float es = v0 * as[nt][0] + v1 * as[nt][1];
            float ed = v0 * ad[nt][0] + v1 * ad[nt][1];
            es += __shfl_xor_sync(~0u, es, 1); es += __shfl_xor_sync(~0u, es, 2);
            ed += __shfl_xor_sync(~0u, ed, 1); ed += __shfl_xor_sync(~0u, ed, 2);
            if (ok && ctid == 0) {
                g_es1[(size_t)(m0 + r) * 8 + nt] = es;
                g_ed1[(size_t)(m0 + r) * 8 + nt] = ed;
            }
        }
    }
}

// -------- xw2 = o1 @ W2 (50000x16, K=64) + fused es2/ed2 --------
__global__ __launch_bounds__(256) void xw2_coeff_k(const float* __restrict__ W2,
    const float* __restrict__ a2s, const float* __restrict__ a2d)
{
    __shared__ float W2s[64][17];
    int tid = threadIdx.x;
    // load W2 (64x16)
    for (int i = tid; i < 64 * 16; i += 256)
        W2s[i >> 4][i & 15] = W2[i];
    __syncthreads();
    int wid = tid >> 5, lane = tid & 31;
    int sub = lane >> 4;            // 0/1: which node in warp
    int col = lane & 15;
    int node = blockIdx.x * 16 + wid * 2 + sub;
    if (node >= N_) return;
    const float* o1 = g_o1 + (size_t)node * 64;
    float acc = 0.f;
#pragma unroll
    for (int k4 = 0; k4 < 64; k4 += 4) {
        float4 v = *(const float4*)(o1 + k4);
        acc += v.x * W2s[k4][col] + v.y * W2s[k4 + 1][col]
             + v.z * W2s[k4 + 2][col] + v.w * W2s[k4 + 3][col];
    }
    g_xw2[(size_t)node * 16 + col] = acc;
    float es = acc * a2s[col], ed = acc * a2d[col];
#pragma unroll
    for (int o = 8; o; o >>= 1) {
        es += __shfl_xor_sync(~0u, es, o);
        ed += __shfl_xor_sync(~0u, ed, o);
    }
    if (col == 0) { g_es2[node] = es; g_ed2[node] = ed; }
}

// -------- edge weights + degree + CSR count (fused) --------
__global__ void edge_w_k(const int* __restrict__ row, const int* __restrict__ col)
{
    int w = threadIdx.x >> 5, lane = threadIdx.x & 31;
    int e0 = blockIdx.x * 32 + w * 4;
#pragma unroll
    for (int k = 0; k < 4; k++) {
        int e = e0 + k;
        if (e >= E_) return;
        int r = row[e], c = col[e];
        float4 a = *(const float4*)(g_hs + ((size_t)r << 7) + (lane << 2));
        float4 b = *(const float4*)(g_hs + ((size_t)c << 7) + (lane << 2));
        float d0 = a.x - b.x, d1 = a.y - b.y, d2 = a.z - b.z, d3 = a.w - b.w;
        float sd = d0 * d0 + d1 * d1 + d2 * d2 + d3 * d3;
        float sa = a.x * a.x + a.y * a.y + a.z * a.z + a.w * a.w;
#pragma unroll
        for (int o = 16; o; o >>= 1) {
            sd += __shfl_xor_sync(~0u, sd, o);
            sa += __shfl_xor_sync(~0u, sa, o);
        }
        if (lane == 0) {
            float C  = sd * (1.f / 128.f);
            float ex = expf(-C * (1.f / EPS_));
            float P0 = fminf(fmaxf(ex, 1e-3f), 1.f);
            float Ps = fminf(fmaxf((P0 + 1e-12f) * ex, 1e-3f), 1.f);
            float ww = 0.7f * P0 + 0.3f * Ps;
            float wl = ww * ww * sa * (1.f / 128.f);
            g_wL[e] = wl;
            atomicAdd(&g_deg[r], wl);
            atomicAdd(&g_deg[c], wl);
            atomicAdd(&g_cnt[r], 1);
            atomicAdd(&g_cnt[c], 1);
        }
    }
}

// ---------------- CSR build ----------------
__global__ void zero_i_k(int* p, int n) { int i = blockIdx.x * blockDim.x + threadIdx.x; if (i < n) p[i] = 0; }
__global__ void zero_f_k(float* p, int n) { int i = blockIdx.x * blockDim.x + threadIdx.x; if (i < n) p[i] = 0.f; }

__global__ void scan_k(int* __restrict__ cnt, int* __restrict__ ptr, int n)
{
    __shared__ int sh[1024];
    int t = threadIdx.x;
    int chunk = (n + 1023) / 1024;
    int lo = t * chunk, hi = min(lo + chunk, n);
    if (lo > n) lo = n;
    int s = 0;
    for (int i = lo; i < hi; i++) s += cnt[i];
    sh[t] = s;
    __syncthreads();
    for (int off = 1; off < 1024; off <<= 1) {
        int v = (t >= off) ? sh[t - off] : 0;
        __syncthreads();
        sh[t] += v;
        __syncthreads();
    }
    int run = sh[t] - s;
    for (int i = lo; i < hi; i++) {
        int c = cnt[i];
        ptr[i] = run; cnt[i] = run; run += c;
    }
    if (t == 1023) ptr[n] = sh[1023];
}
__global__ void scatter_adj_k(const int* __restrict__ row, const int* __restrict__ col)
{
    int e = blockIdx.x * blockDim.x + threadIdx.x;
    if (e >= E_) return;
    int r = row[e], c = col[e];
    float w = g_wL[e];
    int p = atomicAdd(&g_cnt[r], 1); g_adj[p] = c; g_adjw[p] = w;
    int q = atomicAdd(&g_cnt[c], 1); g_adj[q] = r; g_adjw[q] = w;
}
__global__ void init_incnt_k() { int n = blockIdx.x * blockDim.x + threadIdx.x; if (n < N_) g_incnt[n] = 1; }
__global__ void count_in_k(const int* __restrict__ col)
{
    int e = blockIdx.x * blockDim.x + threadIdx.x;
    if (e < E_) atomicAdd(&g_incnt[col[e]], 1);
}
__global__ void scatter_in_k(const int* __restrict__ row, const int* __restrict__ col)
{
    int e = blockIdx.x * blockDim.x + threadIdx.x;
    if (e >= E_) return;
    int p = atomicAdd(&g_incnt[col[e]], 1);
    g_insrc[p] = row[e];
}
__global__ void scatter_self_k()
{
    int n = blockIdx.x * blockDim.x + threadIdx.x;
    if (n >= N_) return;
    int p = atomicAdd(&g_incnt[n], 1);
    g_insrc[p] = n;
}

// ---------------- grid barrier ----------------
__device__ __forceinline__ void gridbar()
{
    __threadfence();
    __syncthreads();
    if (threadIdx.x == 0) {
        int ph = g_barp;
        if (atomicAdd(&g_barc, 1) == (int)gridDim.x - 1) {
            g_barc = 0;
            __threadfence();
            g_barp = ph ^ 1;
        } else {
            while (g_barp == ph) __nanosleep(32);
        }
    }
    __syncthreads();
}

__global__ void cg_init2_k()
{
    int t = threadIdx.x;
    float* rs = &g_rsA[0][0];
    float* dn = &g_denA[0][0];
    for (int i = t; i < (MAXIT_ + 1) * H_; i += 256) rs[i] = 0.f;
    for (int i = t; i < MAXIT_ * H_; i += 256) dn[i] = 0.f;
    if (t == 0) { g_barc = 0; g_barp = 0; }
}

// ---------------- merged persistent CG + AFM ----------------
__device__ __forceinline__ void tildeL_phase(const float* __restrict__ M,
    const float* __restrict__ Mp, float* __restrict__ out, float cA, float cB)
{
    int lane = threadIdx.x & 31, wid = threadIdx.x >> 5;
    int gwarp = blockIdx.x * 8 + wid, nwarp = gridDim.x * 8;
    for (int wc = gwarp; wc < N_ / 4; wc += nwarp) {
#pragma unroll
        for (int k = 0; k < 4; k++) {
            int node = wc * 4 + k;
            int j0 = g_ptr[node], j1 = g_ptr[node + 1];
            float4 a = make_float4(0.f, 0.f, 0.f, 0.f);
            for (int j = j0; j < j1; j++) {
                int nb = g_adj[j];
                float wv = g_adjw[j] * __ldcg(&g_isd[nb]);
                float4 v = __ldcg((const float4*)M + ((size_t)nb << 5) + lane);
                a.x += wv * v.x; a.y += wv * v.y; a.z += wv * v.z; a.w += wv * v.w;
            }
            float is = __ldcg(&g_isd[node]);
            float c0 = g_deg[node] * is * is;
            size_t base = ((size_t)node << 5) + lane;
            float4 m  = __ldcg((const float4*)M + base);
            float4 mp = __ldcg((const float4*)Mp + base);
            float4 o;
            o.x = cA * (m.x + c0 * m.x - is * a.x) + cB * mp.x;
            o.y = cA * (m.y + c0 * m.y - is * a.y) + cB * mp.y;
            o.z = cA * (m.z + c0 * m.z - is * a.z) + cB * mp.z;
            o.w = cA * (m.w + c0 * m.w - is * a.w) + cB * mp.w;
            ((float4*)out)[base] = o;
        }
    }
}

__global__ __launch_bounds__(256, 3) void cgafm_persist_k(const float* __restrict__ gamma,
    const float* __restrict__ asvr, const float* __restrict__ aafm)
{
    __shared__ float sbin[128];
    int tid = threadIdx.x;
    int gtid = blockIdx.x * 256 + tid;
    int stride = gridDim.x * 256;
    int c0 = (gtid & 31) * 4;
    int lane = tid & 31, wid = tid >> 5;
    int gwarp = blockIdx.x * 8 + wid;
    int nwarp = gridDim.x * 8;
    const int NV4 = NH_ / 4;

    if (tid < 128) sbin[tid] = 0.f;
    __syncthreads();
    {
        float a0 = 0.f, a1 = 0.f, a2 = 0.f, a3 = 0.f;
        for (int j = gtid; j < NV4; j += stride) {
            float4 h = ((const float4*)g_h)[j];
            ((float4*)g_X)[j] = make_float4(0.f, 0.f, 0.f, 0.f);
            ((float4*)g_R)[j] = h;
            ((float4*)g_P)[j] = h;
            a0 += h.x * h.x; a1 += h.y * h.y; a2 += h.z * h.z; a3 += h.w * h.w;
        }
        atomicAdd(&sbin[c0 + 0], a0); atomicAdd(&sbin[c0 + 1], a1);
        atomicAdd(&sbin[c0 + 2], a2); atomicAdd(&sbin[c0 + 3], a3);
    }
    __syncthreads();
    if (tid < 128) { float v = sbin[tid]; if (v != 0.f) atomicAdd(&g_rsA[0][tid], v); }
    gridbar();

    for (int it = 0; it < MAXIT_; it++) {
        if (it > 0) {
            if (tid < 128) sbin[tid] = __ldcg(&g_rsA[it][tid]);
            __syncthreads();
            for (int o = 64; o; o >>= 1) {
                if (tid < o) sbin[tid] = fmaxf(sbin[tid], sbin[tid + o]);
                __syncthreads();
            }
            bool done = sbin[0] < TOL_ * TOL_;
            __syncthreads();
            if (done) break;
            float b0 = __ldcg(&g_rsA[it][c0 + 0]) / (__ldcg(&g_rsA[it - 1][c0 + 0]) + 1e-16f);
            float b1 = __ldcg(&g_rsA[it][c0 + 1]) / (__ldcg(&g_rsA[it - 1][c0 + 1]) + 1e-16f);
            float b2 = __ldcg(&g_rsA[it][c0 + 2]) / (__ldcg(&g_rsA[it - 1][c0 + 2]) + 1e-16f);
            float b3 = __ldcg(&g_rsA[it][c0 + 3]) / (__ldcg(&g_rsA[it - 1][c0 + 3]) + 1e-16f);
            for (int j = gtid; j < NV4; j += stride) {
                float4 r = ((const float4*)g_R)[j];
                float4 p = ((const float4*)g_P)[j];
                p.x = r.x + b0 * p.x; p.y = r.y + b1 * p.y;
                p.z = r.z + b2 * p.z; p.w = r.w + b3 * p.w;
                ((float4*)g_P)[j] = p;
            }
            gridbar();
        }
        if (tid < 128) sbin[tid] = 0.f;
        __syncthreads();
        {
            float d0 = 0.f, d1 = 0.f, d2 = 0.f, d3 = 0.f;
            for (int wc = gwarp; wc < N_ / 4; wc += nwarp) {
                int nb0 = wc * 4;
#pragma unroll
                for (int k2 = 0; k2 < 4; k2++) {
                    int node = nb0 + k2;
                    int j0 = g_ptr[node], j1 = g_ptr[node + 1];
                    float4 a = make_float4(0.f, 0.f, 0.f, 0.f);
                    for (int j = j0; j < j1; j++) {
                        int nb = g_adj[j]; float wv = g_adjw[j];
                        float4 v = __ldcg((const float4*)g_P + ((size_t)nb << 5) + lane);
                        a.x += wv * v.x; a.y += wv * v.y; a.z += wv * v.z; a.w += wv * v.w;
                    }
                    float cc = 1.f + DT_ * g_deg[node];
                    float4 p = __ldcg((const float4*)g_P + ((size_t)node << 5) + lane);
                    float4 o;
                    o.x = cc * p.x - DT_ * a.x; o.y = cc * p.y - DT_ * a.y;
                    o.z = cc * p.z - DT_ * a.z; o.w = cc * p.w - DT_ * a.w;
                    ((float4*)g_AP)[((size_t)node << 5) + lane] = o;
                    d0 += p.x * o.x; d1 += p.y * o.y; d2 += p.z * o.z; d3 += p.w * o.w;
                }
            }
            atomicAdd(&sbin[lane * 4 + 0], d0); atomicAdd(&sbin[lane * 4 + 1], d1);
            atomicAdd(&sbin[lane * 4 + 2], d2); atomicAdd(&sbin[lane * 4 + 3], d3);
        }
        __syncthreads();
        if (tid < 128) { float v = sbin[tid]; if (v != 0.f) atomicAdd(&g_denA[it][tid], v); }
        gridbar();
        if (tid < 128) sbin[tid] = 0.f;
        __syncthreads();
        {
            float al0 = __ldcg(&g_rsA[it][c0 + 0]) / (__ldcg(&g_denA[it][c0 + 0]) + 1e-16f);
            float al1 = __ldcg(&g_rsA[it][c0 + 1]) / (__ldcg(&g_denA[it][c0 + 1]) + 1e-16f);
            float al2 = __ldcg(&g_rsA[it][c0 + 2]) / (__ldcg(&g_denA[it][c0 + 2]) + 1e-16f);
            float al3 = __ldcg(&g_rsA[it][c0 + 3]) / (__ldcg(&g_denA[it][c0 + 3]) + 1e-16f);
            float s0 = 0.f, s1 = 0.f, s2 = 0.f, s3 = 0.f;
            for (int j = gtid; j < NV4; j += stride) {
                float4 p  = ((const float4*)g_P)[j];
                float4 ap = __ldcg((const float4*)g_AP + j);
                float4 x  = ((const float4*)g_X)[j];
                float4 r  = ((const float4*)g_R)[j];
                x.x += al0 * p.x; x.y += al1 * p.y; x.z += al2 * p.z; x.w += al3 * p.w;
                r.x -= al0 * ap.x; r.y -= al1 * ap.y; r.z -= al2 * ap.z; r.w -= al3 * ap.w;
                ((float4*)g_X)[j] = x;
                ((float4*)g_R)[j] = r;
                s0 += r.x * r.x; s1 += r.y * r.y; s2 += r.z * r.z; s3 += r.w * r.w;
            }
            atomicAdd(&sbin[c0 + 0], s0); atomicAdd(&sbin[c0 + 1], s1);
            atomicAdd(&sbin[c0 + 2], s2); atomicAdd(&sbin[c0 + 3], s3);
        }
        __syncthreads();
        if (tid < 128) { float v = sbin[tid]; if (v != 0.f) atomicAdd(&g_rsA[it + 1][tid], v); }
        gridbar();
    }

    // ---- AFM phases (reuse grid + barrier) ----
    for (int n = gtid; n < N_; n += stride)
        g_isd[n] = rsqrtf(fmaxf(g_deg[n], 1e-8f));
    if (blockIdx.x == 0 && tid == 0) {
        float m = gamma[0];
        for (int i = 1; i < 4; i++) m = fmaxf(m, gamma[i]);
        float e[4], s = 0.f;
        for (int i = 0; i < 4; i++) { e[i] = expf(gamma[i] - m); s += e[i]; }
        for (int i = 0; i < 4; i++) g_aq[i] = e[i] / s;
    }
    gridbar();
    tildeL_phase(g_h, g_h, g_R, 1.f, 0.f);
    gridbar();
    tildeL_phase(g_R, g_h, g_P, 2.f, -1.f);
    gridbar();
    tildeL_phase(g_P, g_R, g_AP, 2.f, -1.f);
    gridbar();
    float s1 = 1.f / (1.f + expf(-asvr[0]));
    float s2 = 1.f / (1.f + expf(-aafm[0]));
    float a0 = __ldcg(&g_aq[0]), a1 = __ldcg(&g_aq[1]);
    float a2 = __ldcg(&g_aq[2]), a3 = __ldcg(&g_aq[3]);
    for (int j = gtid; j < NV4; j += stride) {
        float4 h = ((const float4*)g_h)[j];
        float4 x  = __ldcg((const float4*)g_X + j);
        float4 r  = __ldcg((const float4*)g_R + j);
        float4 p  = __ldcg((const float4*)g_P + j);
        float4 ap = __ldcg((const float4*)g_AP + j);
        float4 o;
        o.x = h.x + s1 * x.x + s2 * (a0 * h.x + a1 * r.x + a2 * p.x + a3 * ap.x);
        o.y = h.y + s1 * x.y + s2 * (a0 * h.y + a1 * r.y + a2 * p.y + a3 * ap.y);
        o.z = h.z + s1 * x.z + s2 * (a0 * h.z + a1 * r.z + a2 * p.z + a3 * ap.z);
        o.w = h.w + s1 * x.w + s2 * (a0 * h.w + a1 * r.w + a2 * p.w + a3 * ap.w);
        ((float4*)g_F)[j] = o;
    }
}

// ---------------- GAT aggregation ----------------
__global__ void gat1_agg_k(const float* __restrict__ b1)
{
    int node = blockIdx.x * 8 + (threadIdx.x >> 5);
    if (node >= N_) return;
    int lane = threadIdx.x & 31;
    int head = lane >> 2;
    int c0 = (lane & 3) * 2;
    float edv = g_ed1[(size_t)node * 8 + head];
    int j0 = g_inptr[node], j1 = g_inptr[node + 1];
    float m = -3.4e38f, den = 0.f, a0 = 0.f, a1 = 0.f;
    for (int j = j0; j < j1; j++) {
        int s = g_insrc[j];
        float e = g_es1[(size_t)s * 8 + head] + edv;
        e = e >= 0.f ? e : 0.2f * e;
        float mn = fmaxf(m, e);
        float sc = expf(m - mn);
        float p  = expf(e - mn);
        const float* xw = g_xw1 + (size_t)s * 64 + head * 8 + c0;
        den = den * sc + p;
        a0  = a0 * sc + p * xw[0];
        a1  = a1 * sc + p * xw[1];
        m = mn;
    }
    float inv = 1.f / (den + 1e-16f);
    float v0 = a0 * inv + b1[head * 8 + c0];
    float v1 = a1 * inv + b1[head * 8 + c0 + 1];
    v0 = v0 > 0.f ? v0 : expm1f(v0);
    v1 = v1 > 0.f ? v1 : expm1f(v1);
    float* o = g_o1 + (size_t)node * 64 + head * 8 + c0;
    o[0] = v0; o[1] = v1;
}
__global__ void gat2_agg_k(const float* __restrict__ b2, float* __restrict__ out)
{
    int node = blockIdx.x * 16 + (threadIdx.x >> 4);
    if (node >= N_) return;
    int ch = threadIdx.x & 15;
    float edv = g_ed2[node];
    int j0 = g_inptr[node], j1 = g_inptr[node + 1];
    float m = -3.4e38f, den = 0.f, acc = 0.f;
    for (int j = j0; j < j1; j++) {
        int s = g_insrc[j];
        float e = g_es2[s] + edv;
        e = e >= 0.f ? e : 0.2f * e;
        float mn = fmaxf(m, e);
        float sc = expf(m - mn);
        float p  = expf(e - mn);
        den = den * sc + p;
        acc = acc * sc + p * g_xw2[(size_t)s * 16 + ch];
        m = mn;
    }
    out[(size_t)node * 16 + ch] = acc / (den + 1e-16f) + b2[ch];
}

// ---------------- host ----------------
#define SYM(p, s) do { void* _t; cudaGetSymbolAddress(&_t, s); p = (decltype(p))_t; } while(0)

extern "C" void kernel_launch(void* const* d_in, const int* in_sizes, int n_in,
                              void* d_out, int out_size)
{
    const float* x      = (const float*)d_in[0];
    const int*   ei     = (const int*)d_in[1];
    const float* W_in   = (const float*)d_in[2];
    const float* b_in   = (const float*)d_in[3];
    const float* ln_g   = (const float*)d_in[4];
    const float* ln_b   = (const float*)d_in[5];
    const float* W_sh   = (const float*)d_in[6];
    const float* gamma  = (const float*)d_in[7];
    const float* asvr   = (const float*)d_in[8];
    const float* aafm   = (const float*)d_in[9];
    const float* W1     = (const float*)d_in[10];
    const float* a1s    = (const float*)d_in[11];
    const float* a1d    = (const float*)d_in[12];
    const float* b1     = (const float*)d_in[13];
    const float* W2     = (const float*)d_in[14];
    const float* a2s    = (const float*)d_in[15];
    const float* a2d    = (const float*)d_in[16];
    const float* b2     = (const float*)d_in[17];
    const int* row = ei, * col = ei + E_;
    float* out = (float*)d_out;

    float *pdeg;
    int *pcnt, *pincnt, *pptr, *pinptr;
    SYM(pdeg, g_deg);
    SYM(pcnt, g_cnt); SYM(pincnt, g_incnt); SYM(pptr, g_ptr); SYM(pinptr, g_inptr);

    const int GB = 391;
    zero_f_k<<<196, 256>>>(pdeg, N_);
    zero_i_k<<<196, 256>>>(pcnt, N_);

    // h = sigmoid(LN(x@W_in+b)) (tf32); hs = h@W_sheaf (tf32)
    gemm_lnsig_tf32_k<<<GB, 256>>>(x, W_in, b_in, ln_g, ln_b);
    gemm_sheaf_tf32_k<<<GB, 256>>>(W_sh);

    // edge weights + degrees + CSR counts
    edge_w_k<<<16000, 256>>>(row, col);

    // symmetric CSR
    scan_k<<<1, 1024>>>(pcnt, pptr, N_);
    scatter_adj_k<<<2000, 256>>>(row, col);
    // incoming CSR (self-loops) for GAT
    init_incnt_k<<<196, 256>>>();
    count_in_k<<<2000, 256>>>(col);
    scan_k<<<1, 1024>>>(pincnt, pinptr, N_);
    scatter_in_k<<<2000, 256>>>(row, col);
    scatter_self_k<<<196, 256>>>();

    // persistent CG + AFM (merged)
    cg_init2_k<<<1, 256>>>();
    cgafm_persist_k<<<CGRID_, 256>>>(gamma, asvr, aafm);

    // GAT layer 1 (tf32 GEMM + fused coeffs)
    gemm_gat1_tf32_k<<<GB, 256>>>(W1, a1s, a1d);
    gat1_agg_k<<<6250, 256>>>(b1);

    // GAT layer 2 (fused small GEMM + coeffs)
    xw2_coeff_k<<<3125, 256>>>(W2, a2s, a2d);
    gat2_agg_k<<<3125, 256>>>(b2, out);
}

// round 15
// speedup vs baseline: 1.8294x; 1.0202x over previous
#include <cuda_runtime.h>
#include <math.h>
#include <stdint.h>

#define N_  50000
#define E_  512000
#define IN_ 512
#define H_  128
#define NH_ (N_*H_)
#define DT_   0.1f
#define EPS_  1e-3f
#define TOL_  1e-4f
#define MAXIT_ 20
#define CGRID_ 444

// ---------------- device scratch ----------------
__device__ __align__(16) float g_h[NH_];
__device__ __align__(16) float g_hs[NH_];
__device__ __align__(16) float g_X[NH_];
__device__ __align__(16) float g_R[NH_];
__device__ __align__(16) float g_P[NH_];
__device__ __align__(16) float g_AP[NH_];
__device__ __align__(16) float g_F[NH_];
__device__ float g_wL[E_];
__device__ float g_deg[N_];
__device__ float g_isd[N_];
__device__ int   g_cnt[N_];
__device__ int   g_ptr[N_ + 1];
__device__ int   g_adj[2 * E_];
__device__ float g_adjw[2 * E_];
__device__ int   g_incnt[N_];
__device__ int   g_inptr[N_ + 1];
__device__ int   g_insrc[E_ + N_];
__device__ float g_rsA[MAXIT_ + 1][H_];
__device__ float g_denA[MAXIT_][H_];
__device__ int   g_barc;
__device__ volatile int g_barp;
__device__ float g_aq[4];
__device__ __align__(16) float g_xw1[N_ * 64];
__device__ float g_es1[N_ * 8], g_ed1[N_ * 8];
__device__ __align__(16) float g_o1[N_ * 64];
__device__ __align__(16) float g_xw2[N_ * 16];
__device__ float g_es2[N_], g_ed2[N_];

// ---------------- tf32 / cp.async helpers ----------------
__device__ __forceinline__ uint32_t f2tf32(float f)
{
    uint32_t u;
    asm("cvt.rna.tf32.f32 %0, %1;" : "=r"(u) : "f"(f));
    return u;
}
__device__ __forceinline__ void mma_tf32(float* c, const uint32_t* a, uint32_t b0, uint32_t b1)
{
    asm volatile(
        "mma.sync.aligned.m16n8k8.row.col.f32.tf32.tf32.f32 "
        "{%0,%1,%2,%3}, {%4,%5,%6,%7}, {%8,%9}, {%0,%1,%2,%3};\n"
        : "+f"(c[0]), "+f"(c[1]), "+f"(c[2]), "+f"(c[3])
        : "r"(a[0]), "r"(a[1]), "r"(a[2]), "r"(a[3]), "r"(b0), "r"(b1));
}
__device__ __forceinline__ void cpa16(uint32_t d, const float* s, int ok)
{
    asm volatile("cp.async.ca.shared.global [%0], [%1], 16, %2;\n"
                 :: "r"(d), "l"(s), "r"(ok ? 16 : 0));
}
#define CP_COMMIT() asm volatile("cp.async.commit_group;\n" ::)
#define CP_WAIT1()  asm volatile("cp.async.wait_group 1;\n" ::)
#define CP_WAIT0()  asm volatile("cp.async.wait_group 0;\n" ::)

// pipelined 128x128 tf32 mainloop; A is [*,K] row-major, B is [K,128] row-major
// As: 2*128*20 floats, Bs: 2*16*132 floats
template<int K>
__device__ __forceinline__ void tf32_loop(const float* __restrict__ A,
    const float* __restrict__ B, int m0, float acc[2][8][4],
    float* As, float* Bs)
{
    int tid = threadIdx.x, lane = tid & 31, wid = tid >> 5;
    int wm = wid & 3, wn = wid >> 2;
    int gid = lane >> 2, ctid = lane & 3;
    uint32_t asb = (uint32_t)__cvta_generic_to_shared(As);
    uint32_t bsb = (uint32_t)__cvta_generic_to_shared(Bs);
    const int ABUF = 128 * 20 * 4, BBUF = 16 * 132 * 4;
    int ar0 = tid >> 2, ak0 = tid & 3;
    int ar1 = (tid + 256) >> 2, ak1 = (tid + 256) & 3;
    int br0 = tid >> 5, bc0 = tid & 31;
    int br1 = (tid + 256) >> 5, bc1 = (tid + 256) & 31;

    // prologue: chunk 0 -> buf 0
    cpa16(asb + (ar0 * 20 + ak0 * 4) * 4, A + (size_t)(m0 + ar0) * K + ak0 * 4, m0 + ar0 < N_);
    cpa16(asb + (ar1 * 20 + ak1 * 4) * 4, A + (size_t)(m0 + ar1) * K + ak1 * 4, m0 + ar1 < N_);
    cpa16(bsb + (br0 * 132 + bc0 * 4) * 4, B + (size_t)br0 * H_ + bc0 * 4, 1);
    cpa16(bsb + (br1 * 132 + bc1 * 4) * 4, B + (size_t)br1 * H_ + bc1 * 4, 1);
    CP_COMMIT();

    const int NC = K / 16;
    for (int c = 0; c < NC; c++) {
        int buf = c & 1;
        if (c + 1 < NC) {
            int k0 = (c + 1) * 16, nb = buf ^ 1;
            cpa16(asb + nb * ABUF + (ar0 * 20 + ak0 * 4) * 4, A + (size_t)(m0 + ar0) * K + k0 + ak0 * 4, m0 + ar0 < N_);
            cpa16(asb + nb * ABUF + (ar1 * 20 + ak1 * 4) * 4, A + (size_t)(m0 + ar1) * K + k0 + ak1 * 4, m0 + ar1 < N_);
            cpa16(bsb + nb * BBUF + (br0 * 132 + bc0 * 4) * 4, B + (size_t)(k0 + br0) * H_ + bc0 * 4, 1);
            cpa16(bsb + nb * BBUF + (br1 * 132 + bc1 * 4) * 4, B + (size_t)(k0 + br1) * H_ + bc1 * 4, 1);
            CP_COMMIT();
            CP_WAIT1();
        } else {
            CP_WAIT0();
        }
        __syncthreads();
        const float* Af = As + buf * (128 * 20);
        const float* Bf = Bs + buf * (16 * 132);
#pragma unroll
        for (int k8 = 0; k8 < 16; k8 += 8) {
            uint32_t a[2][4];
#pragma unroll
            for (int mt = 0; mt < 2; mt++) {
                int r0 = wm * 32 + mt * 16 + gid;
                a[mt][0] = f2tf32(Af[r0 * 20 + k8 + ctid]);
                a[mt][1] = f2tf32(Af[(r0 + 8) * 20 + k8 + ctid]);
                a[mt][2] = f2tf32(Af[r0 * 20 + k8 + ctid + 4]);
                a[mt][3] = f2tf32(Af[(r0 + 8) * 20 + k8 + ctid + 4]);
            }
#pragma unroll
            for (int nt = 0; nt < 8; nt++) {
                int col = wn * 64 + nt * 8 + gid;
                uint32_t b0 = f2tf32(Bf[(k8 + ctid) * 132 + col]);
                uint32_t b1 = f2tf32(Bf[(k8 + ctid + 4) * 132 + col]);
                mma_tf32(acc[0][nt], a[0], b0, b1);
                mma_tf32(acc[1][nt], a[1], b0, b1);
            }
        }
        __syncthreads();
    }
}

// -------- GEMM1 tf32 pipelined + fused bias + LayerNorm + sigmoid -> g_h --------
__global__ __launch_bounds__(256) void gemm_lnsig_tf32_k(const float* __restrict__ A,
    const float* __restrict__ B, const float* __restrict__ bias,
    const float* __restrict__ lng, const float* __restrict__ lnb)
{
    __shared__ float As[2 * 128 * 20];
    __shared__ float Bs[2 * 16 * 132];
    __shared__ float ssum[128], ssq[128];
    int tid = threadIdx.x, lane = tid & 31, wid = tid >> 5;
    int wm = wid & 3, wn = wid >> 2;
    int gid = lane >> 2, ctid = lane & 3;
    int m0 = blockIdx.x * 128;
    float acc[2][8][4];
#pragma unroll
    for (int mt = 0; mt < 2; mt++)
#pragma unroll
        for (int nt = 0; nt < 8; nt++)
#pragma unroll
            for (int c = 0; c < 4; c++) acc[mt][nt][c] = 0.f;

    tf32_loop<IN_>(A, B, m0, acc, As, Bs);

    float b2[8][2], gg[8][2], bb[8][2];
#pragma unroll
    for (int nt = 0; nt < 8; nt++) {
        int col = wn * 64 + nt * 8 + 2 * ctid;
        b2[nt][0] = bias[col]; b2[nt][1] = bias[col + 1];
        gg[nt][0] = lng[col];  gg[nt][1] = lng[col + 1];
        bb[nt][0] = lnb[col];  bb[nt][1] = lnb[col + 1];
    }
    if (tid < 128) { ssum[tid] = 0.f; ssq[tid] = 0.f; }
    __syncthreads();
#pragma unroll
    for (int mt = 0; mt < 2; mt++)
#pragma unroll
        for (int half = 0; half < 2; half++) {
            int r = wm * 32 + mt * 16 + gid + 8 * half;
            float s = 0.f;
#pragma unroll
            for (int nt = 0; nt < 8; nt++)
                s += (acc[mt][nt][2 * half] + b2[nt][0]) + (acc[mt][nt][2 * half + 1] + b2[nt][1]);
            atomicAdd(&ssum[r], s);
        }
    __syncthreads();
#pragma unroll
    for (int mt = 0; mt < 2; mt++)
#pragma unroll
        for (int half = 0; half < 2; half++) {
            int r = wm * 32 + mt * 16 + gid + 8 * half;
            float mean = ssum[r] * (1.f / 128.f);
            float q = 0.f;
#pragma unroll
            for (int nt = 0; nt < 8; nt++) {
                float d0 = acc[mt][nt][2 * half] + b2[nt][0] - mean;
                float d1 = acc[mt][nt][2 * half + 1] + b2[nt][1] - mean;
                q += d0 * d0 + d1 * d1;
            }
            atomicAdd(&ssq[r], q);
        }
    __syncthreads();
#pragma unroll
    for (int mt = 0; mt < 2; mt++)
#pragma unroll
        for (int half = 0; half < 2; half++) {
            int r = wm * 32 + mt * 16 + gid + 8 * half;
            if (m0 + r >= N_) continue;
            float mean = ssum[r] * (1.f / 128.f);
            float rstd = rsqrtf(ssq[r] * (1.f / 128.f) + 1e-5f);
#pragma unroll
            for (int nt = 0; nt < 8; nt++) {
                int col = wn * 64 + nt * 8 + 2 * ctid;
                float u0 = (acc[mt][nt][2 * half]     + b2[nt][0] - mean) * rstd * gg[nt][0] + bb[nt][0];
                float u1 = (acc[mt][nt][2 * half + 1] + b2[nt][1] - mean) * rstd * gg[nt][1] + bb[nt][1];
                float2 o;
                o.x = 1.f / (1.f + expf(-u0));
                o.y = 1.f / (1.f + expf(-u1));
                *(float2*)(g_h + (size_t)(m0 + r) * H_ + col) = o;
            }
        }
}

// -------- sheaf GEMM tf32 pipelined: g_hs = g_h @ W_sh --------
__global__ __launch_bounds__(256) void gemm_sheaf_tf32_k(const float* __restrict__ B)
{
    __shared__ float As[2 * 128 * 20];
    __shared__ float Bs[2 * 16 * 132];
    int tid = threadIdx.x, lane = tid & 31, wid = tid >> 5;
    int wm = wid & 3, wn = wid >> 2;
    int gid = lane >> 2, ctid = lane & 3;
    int m0 = blockIdx.x * 128;
    float acc[2][8][4];
#pragma unroll
    for (int mt = 0; mt < 2; mt++)
#pragma unroll
        for (int nt = 0; nt < 8; nt++)
#pragma unroll
            for (int c = 0; c < 4; c++) acc[mt][nt][c] = 0.f;

    tf32_loop<H_>(g_h, B, m0, acc, As, Bs);

#pragma unroll
    for (int mt = 0; mt < 2; mt++)
#pragma unroll
        for (int half = 0; half < 2; half++) {
            int r = wm * 32 + mt * 16 + gid + 8 * half;
            if (m0 + r >= N_) continue;
#pragma unroll
            for (int nt = 0; nt < 8; nt++) {
                int col = wn * 64 + nt * 8 + 2 * ctid;
                float2 o;
                o.x = acc[mt][nt][2 * half];
                o.y = acc[mt][nt][2 * half + 1];
                *(float2*)(g_hs + (size_t)(m0 + r) * H_ + col) = o;
            }
        }
}

// -------- gat1 GEMM tf32: xw1 = F @ W1 (tile 128x64, K=128) + es/ed --------
__global__ __launch_bounds__(256) void gemm_gat1_tf32_k(const float* __restrict__ B,
    const float* __restrict__ a1s, const float* __restrict__ a1d)
{
    __shared__ uint32_t As[128 * 36];
    __shared__ uint32_t Bs[32 * 68];
    int tid = threadIdx.x, lane = tid & 31, wid = tid >> 5;
    int gid = lane >> 2, ctid = lane & 3;
    int m0 = blockIdx.x * 128;
    float acc[8][4];
#pragma unroll
    for (int nt = 0; nt < 8; nt++)
#pragma unroll
        for (int c = 0; c < 4; c++) acc[nt][c] = 0.f;

    for (int k0 = 0; k0 < 128; k0 += 32) {
#pragma unroll
        for (int i = 0; i < 4; i++) {
            int f4 = tid + i * 256;
            int row = f4 >> 3, kq = f4 & 7;
            float4 v = make_float4(0.f, 0.f, 0.f, 0.f);
            if (m0 + row < N_) v = *(const float4*)(g_F + (size_t)(m0 + row) * H_ + k0 + kq * 4);
            uint32_t* d = &As[row * 36 + kq * 4];
            d[0] = f2tf32(v.x); d[1] = f2tf32(v.y); d[2] = f2tf32(v.z); d[3] = f2tf32(v.w);
        }
#pragma unroll
        for (int i = 0; i < 2; i++) {
            int f4 = tid + i * 256;
            int kr = f4 >> 4, cq = f4 & 15;
            float4 v = *(const float4*)(B + (size_t)(k0 + kr) * 64 + cq * 4);
            uint32_t* d = &Bs[kr * 68 + cq * 4];
            d[0] = f2tf32(v.x); d[1] = f2tf32(v.y); d[2] = f2tf32(v.z); d[3] = f2tf32(v.w);
        }
        __syncthreads();
#pragma unroll
        for (int k8 = 0; k8 < 32; k8 += 8) {
            uint32_t a[4];
            int r0 = wid * 16 + gid;
            a[0] = As[r0 * 36 + k8 + ctid];
            a[1] = As[(r0 + 8) * 36 + k8 + ctid];
            a[2] = As[r0 * 36 + k8 + ctid + 4];
            a[3] = As[(r0 + 8) * 36 + k8 + ctid + 4];
#pragma unroll
            for (int nt = 0; nt < 8; nt++) {
                int col = nt * 8 + gid;
                uint32_t b0 = Bs[(k8 + ctid) * 68 + col];
                uint32_t b1 = Bs[(k8 + ctid + 4) * 68 + col];
                mma_tf32(acc[nt], a, b0, b1);
            }
        }
        __syncthreads();
    }
    float as[8][2], ad[8][2];
#pragma unroll
    for (int nt = 0; nt < 8; nt++) {
        int c = nt * 8 + 2 * ctid;
        as[nt][0] = a1s[c]; as[nt][1] = a1s[c + 1];
        ad[nt][0] = a1d[c]; ad[nt][1] = a1d[c + 1];
    }
#pragma unroll
    for (int half = 0; half < 2; half++) {
        int r = wid * 16 + gid + 8 * half;
        bool ok = (m0 + r < N_);
#pragma unroll
        for (int nt = 0; nt < 8; nt++) {
            float v0 = acc[nt][2 * half], v1 = acc[nt][2 * half + 1];
            if (ok) {
                float2 o; o.x = v0; o.y = v1;
                *(float2*)(g_xw1 + (size_t)(m0 + r) * 64 + nt * 8 + 2 * ctid) = o;
            }
            float es = v0 * as[nt][0] + v1 * as[nt][1];
            float ed = v0 * ad[nt][0] + v1 * ad[nt][1];
            es += __shfl_xor_sync(~0u, es, 1); es += __shfl_xor_sync(~0u, es, 2);
            ed += __shfl_xor_sync(~0u, ed, 1); ed += __shfl_xor_sync(~0u, ed, 2);
            if (ok && ctid == 0) {
                g_es1[(size_t)(m0 + r) * 8 + nt] = es;
                g_ed1[(size_t)(m0 + r) * 8 + nt] = ed;
            }
        }
    }
}

// -------- xw2 = o1 @ W2 (K=64, Nc=16) + fused es2/ed2 --------
__global__ __launch_bounds__(256) void xw2_coeff_k(const float* __restrict__ W2,
    const float* __restrict__ a2s, const float* __restrict__ a2d)
{
    __shared__ float W2s[64][17];
    int tid = threadIdx.x;
    for (int i = tid; i < 64 * 16; i += 256)
        W2s[i >> 4][i & 15] = W2[i];
    __syncthreads();
    int wid = tid >> 5, lane = tid & 31;
    int sub = lane >> 4;
    int col = lane & 15;
    int node = blockIdx.x * 16 + wid * 2 + sub;
    if (node >= N_) return;
    const float* o1 = g_o1 + (size_t)node * 64;
    float acc = 0.f;
#pragma unroll
    for (int k4 = 0; k4 < 64; k4 += 4) {
        float4 v = *(const float4*)(o1 + k4);
        acc += v.x * W2s[k4][col] + v.y * W2s[k4 + 1][col]
             + v.z * W2s[k4 + 2][col] + v.w * W2s[k4 + 3][col];
    }
    g_xw2[(size_t)node * 16 + col] = acc;
    float es = acc * a2s[col], ed = acc * a2d[col];
#pragma unroll
    for (int o = 8; o; o >>= 1) {
        es += __shfl_xor_sync(~0u, es, o);
        ed += __shfl_xor_sync(~0u, ed, o);
    }
    if (col == 0) { g_es2[node] = es; g_ed2[node] = ed; }
}

// -------- edge weights + degree + BOTH CSR counts (fused) --------
__global__ void edge_w_k(const int* __restrict__ row, const int* __restrict__ col)
{
    int w = threadIdx.x >> 5, lane = threadIdx.x & 31;
    int e0 = blockIdx.x * 32 + w * 4;
#pragma unroll
    for (int k = 0; k < 4; k++) {
        int e = e0 + k;
        if (e >= E_) return;
        int r = row[e], c = col[e];
        float4 a = *(const float4*)(g_hs + ((size_t)r << 7) + (lane << 2));
        float4 b = *(const float4*)(g_hs + ((size_t)c << 7) + (lane << 2));
        float d0 = a.x - b.x, d1 = a.y - b.y, d2 = a.z - b.z, d3 = a.w - b.w;
        float sd = d0 * d0 + d1 * d1 + d2 * d2 + d3 * d3;
        float sa = a.x * a.x + a.y * a.y + a.z * a.z + a.w * a.w;
#pragma unroll
        for (int o = 16; o; o >>= 1) {
            sd += __shfl_xor_sync(~0u, sd, o);
            sa += __shfl_xor_sync(~0u, sa, o);
        }
        if (lane == 0) {
            float C  = sd * (1.f / 128.f);
            float ex = expf(-C * (1.f / EPS_));
            float P0 = fminf(fmaxf(ex, 1e-3f), 1.f);
            float Ps = fminf(fmaxf((P0 + 1e-12f) * ex, 1e-3f), 1.f);
            float ww = 0.7f * P0 + 0.3f * Ps;
            float wl = ww * ww * sa * (1.f / 128.f);
            g_wL[e] = wl;
            atomicAdd(&g_deg[r], wl);
            atomicAdd(&g_deg[c], wl);
            atomicAdd(&g_cnt[r], 1);
            atomicAdd(&g_cnt[c], 1);
            atomicAdd(&g_incnt[c], 1);
        }
    }
}

// ---------------- CSR build ----------------
__global__ void zero3_k()
{
    int i = blockIdx.x * blockDim.x + threadIdx.x;
    if (i < N_) { g_deg[i] = 0.f; g_cnt[i] = 0; g_incnt[i] = 0; }
}

__device__ __forceinline__ void scan_body(int* cnt, int* ptr, int n, int selfpad, int* sh)
{
    int t = threadIdx.x;
    int chunk = (n + 1023) / 1024;
    int lo = t * chunk, hi = min(lo + chunk, n);
    if (lo > n) lo = n;
    int s = 0;
    for (int i = lo; i < hi; i++) s += cnt[i];
    sh[t] = s;
    __syncthreads();
    for (int off = 1; off < 1024; off <<= 1) {
        int v = (t >= off) ? sh[t - off] : 0;
        __syncthreads();
        sh[t] += v;
        __syncthreads();
    }
    int run = sh[t] - s;
    for (int i = lo; i < hi; i++) {
        int c = cnt[i];
        int base = run + selfpad * i;
        ptr[i] = base; cnt[i] = base; run += c;
    }
    if (t == 1023) ptr[n] = sh[1023] + selfpad * n;
    __syncthreads();
}
// both scans + CG scalar init in one launch
__global__ void scan2_k()
{
    __shared__ int sh[1024];
    scan_body(g_cnt, g_ptr, N_, 0, sh);
    scan_body(g_incnt, g_inptr, N_, 1, sh);
    int t = threadIdx.x;
    float* rs = &g_rsA[0][0];
    float* dn = &g_denA[0][0];
    for (int i = t; i < (MAXIT_ + 1) * H_; i += 1024) rs[i] = 0.f;
    for (int i = t; i < MAXIT_ * H_; i += 1024) dn[i] = 0.f;
    if (t == 0) { g_barc = 0; g_barp = 0; }
}
__global__ void scatter_adj_k(const int* __restrict__ row, const int* __restrict__ col)
{
    int e = blockIdx.x * blockDim.x + threadIdx.x;
    if (e >= E_) return;
    int r = row[e], c = col[e];
    float w = g_wL[e];
    int p = atomicAdd(&g_cnt[r], 1); g_adj[p] = c; g_adjw[p] = w;
    int q = atomicAdd(&g_cnt[c], 1); g_adj[q] = r; g_adjw[q] = w;
}
__global__ void scatter_in_self_k(const int* __restrict__ row, const int* __restrict__ col)
{
    int i = blockIdx.x * blockDim.x + threadIdx.x;
    if (i < E_) {
        int p = atomicAdd(&g_incnt[col[i]], 1);
        g_insrc[p] = row[i];
    } else if (i < E_ + N_) {
        int n = i - E_;
        int p = atomicAdd(&g_incnt[n], 1);
        g_insrc[p] = n;
    }
}

// ---------------- grid barrier ----------------
__device__ __forceinline__ void gridbar()
{
    __threadfence();
    __syncthreads();
    if (threadIdx.x == 0) {
        int ph = g_barp;
        if (atomicAdd(&g_barc, 1) == (int)gridDim.x - 1) {
            g_barc = 0;
            __threadfence();
            g_barp = ph ^ 1;
        } else {
            while (g_barp == ph) __nanosleep(32);
        }
    }
    __syncthreads();
}

// ---------------- merged persistent CG + AFM ----------------
__device__ __forceinline__ void tildeL_phase(const float* __restrict__ M,
    const float* __restrict__ Mp, float* __restrict__ out, float cA, float cB)
{
    int lane = threadIdx.x & 31, wid = threadIdx.x >> 5;
    int gwarp = blockIdx.x * 8 + wid, nwarp = gridDim.x * 8;
    for (int wc = gwarp; wc < N_ / 4; wc += nwarp) {
#pragma unroll
        for (int k = 0; k < 4; k++) {
            int node = wc * 4 + k;
            int j0 = g_ptr[node], j1 = g_ptr[node + 1];
            float4 a = make_float4(0.f, 0.f, 0.f, 0.f);
            for (int j = j0; j < j1; j++) {
                int nb = g_adj[j];
                float wv = g_adjw[j] * __ldcg(&g_isd[nb]);
                float4 v = __ldcg((const float4*)M + ((size_t)nb << 5) + lane);
                a.x += wv * v.x; a.y += wv * v.y; a.z += wv * v.z; a.w += wv * v.w;
            }
            float is = __ldcg(&g_isd[node]);
            float c0 = g_deg[node] * is * is;
            size_t base = ((size_t)node << 5) + lane;
            float4 m  = __ldcg((const float4*)M + base);
            float4 mp = __ldcg((const float4*)Mp + base);
            float4 o;
            o.x = cA * (m.x + c0 * m.x - is * a.x) + cB * mp.x;
            o.y = cA * (m.y + c0 * m.y - is * a.y) + cB * mp.y;
            o.z = cA * (m.z + c0 * m.z - is * a.z) + cB * mp.z;
            o.w = cA * (m.w + c0 * m.w - is * a.w) + cB * mp.w;
            ((float4*)out)[base] = o;
        }
    }
}

__global__ __launch_bounds__(256, 3) void cgafm_persist_k(const float* __restrict__ gamma,
    const float* __restrict__ asvr, const float* __restrict__ aafm)
{
    __shared__ float sbin[128];
    int tid = threadIdx.x;
    int gtid = blockIdx.x * 256 + tid;
    int stride = gridDim.x * 256;
    int c0 = (gtid & 31) * 4;
    int lane = tid & 31, wid = tid >> 5;
    int gwarp = blockIdx.x * 8 + wid;
    int nwarp = gridDim.x * 8;
    const int NV4 = NH_ / 4;

    if (tid < 128) sbin[tid] = 0.f;
    __syncthreads();
    {
        float a0 = 0.f, a1 = 0.f, a2 = 0.f, a3 = 0.f;
        for (int j = gtid; j < NV4; j += stride) {
            float4 h = ((const float4*)g_h)[j];
            ((float4*)g_X)[j] = make_float4(0.f, 0.f, 0.f, 0.f);
            ((float4*)g_R)[j] = h;
            ((float4*)g_P)[j] = h;
            a0 += h.x * h.x; a1 += h.y * h.y; a2 += h.z * h.z; a3 += h.w * h.w;
        }
        atomicAdd(&sbin[c0 + 0], a0); atomicAdd(&sbin[c0 + 1], a1);
        atomicAdd(&sbin[c0 + 2], a2); atomicAdd(&sbin[c0 + 3], a3);
    }
    __syncthreads();
    if (tid < 128) { float v = sbin[tid]; if (v != 0.f) atomicAdd(&g_rsA[0][tid], v); }
    gridbar();

    for (int it = 0; it < MAXIT_; it++) {
        if (it > 0) {
            if (tid < 128) sbin[tid] = __ldcg(&g_rsA[it][tid]);
            __syncthreads();
            for (int o = 64; o; o >>= 1) {
                if (tid < o) sbin[tid] = fmaxf(sbin[tid], sbin[tid + o]);
                __syncthreads();
            }
            bool done = sbin[0] < TOL_ * TOL_;
            __syncthreads();
            if (done) break;
            float b0 = __ldcg(&g_rsA[it][c0 + 0]) / (__ldcg(&g_rsA[it - 1][c0 + 0]) + 1e-16f);
            float b1 = __ldcg(&g_rsA[it][c0 + 1]) / (__ldcg(&g_rsA[it - 1][c0 + 1]) + 1e-16f);
            float b2 = __ldcg(&g_rsA[it][c0 + 2]) / (__ldcg(&g_rsA[it - 1][c0 + 2]) + 1e-16f);
            float b3 = __ldcg(&g_rsA[it][c0 + 3]) / (__ldcg(&g_rsA[it - 1][c0 + 3]) + 1e-16f);
            for (int j = gtid; j < NV4; j += stride) {
                float4 r = ((const float4*)g_R)[j];
                float4 p = ((const float4*)g_P)[j];
                p.x = r.x + b0 * p.x; p.y = r.y + b1 * p.y;
                p.z = r.z + b2 * p.z; p.w = r.w + b3 * p.w;
                ((float4*)g_P)[j] = p;
            }
            gridbar();
        }
        if (tid < 128) sbin[tid] = 0.f;
        __syncthreads();
        {
            float d0 = 0.f, d1 = 0.f, d2 = 0.f, d3 = 0.f;
            for (int wc = gwarp; wc < N_ / 4; wc += nwarp) {
                int nb0 = wc * 4;
#pragma unroll
                for (int k2 = 0; k2 < 4; k2++) {
                    int node = nb0 + k2;
                    int j0 = g_ptr[node], j1 = g_ptr[node + 1];
                    float4 a = make_float4(0.f, 0.f, 0.f, 0.f);
                    for (int j = j0; j < j1; j++) {
                        int nb = g_adj[j]; float wv = g_adjw[j];
                        float4 v = __ldcg((const float4*)g_P + ((size_t)nb << 5) + lane);
                        a.x += wv * v.x; a.y += wv * v.y; a.z += wv * v.z; a.w += wv * v.w;
                    }
                    float cc = 1.f + DT_ * g_deg[node];
                    float4 p = __ldcg((const float4*)g_P + ((size_t)node << 5) + lane);
                    float4 o;
                    o.x = cc * p.x - DT_ * a.x; o.y = cc * p.y - DT_ * a.y;
                    o.z = cc * p.z - DT_ * a.z; o.w = cc * p.w - DT_ * a.w;
                    ((float4*)g_AP)[((size_t)node << 5) + lane] = o;
                    d0 += p.x * o.x; d1 += p.y * o.y; d2 += p.z * o.z; d3 += p.w * o.w;
                }
            }
            atomicAdd(&sbin[lane * 4 + 0], d0); atomicAdd(&sbin[lane * 4 + 1], d1);
            atomicAdd(&sbin[lane * 4 + 2], d2); atomicAdd(&sbin[lane * 4 + 3], d3);
        }
        __syncthreads();
        if (tid < 128) { float v = sbin[tid]; if (v != 0.f) atomicAdd(&g_denA[it][tid], v); }
        gridbar();
        if (tid < 128) sbin[tid] = 0.f;
        __syncthreads();
        {
            float al0 = __ldcg(&g_rsA[it][c0 + 0]) / (__ldcg(&g_denA[it][c0 + 0]) + 1e-16f);
            float al1 = __ldcg(&g_rsA[it][c0 + 1]) / (__ldcg(&g_denA[it][c0 + 1]) + 1e-16f);
            float al2 = __ldcg(&g_rsA[it][c0 + 2]) / (__ldcg(&g_denA[it][c0 + 2]) + 1e-16f);
            float al3 = __ldcg(&g_rsA[it][c0 + 3]) / (__ldcg(&g_denA[it][c0 + 3]) + 1e-16f);
            float s0 = 0.f, s1 = 0.f, s2 = 0.f, s3 = 0.f;
            for (int j = gtid; j < NV4; j += stride) {
                float4 p  = ((const float4*)g_P)[j];
                float4 ap = __ldcg((const float4*)g_AP + j);
                float4 x  = ((const float4*)g_X)[j];
                float4 r  = ((const float4*)g_R)[j];
                x.x += al0 * p.x; x.y += al1 * p.y; x.z += al2 * p.z; x.w += al3 * p.w;
                r.x -= al0 * ap.x; r.y -= al1 * ap.y; r.z -= al2 * ap.z; r.w -= al3 * ap.w;
                ((float4*)g_X)[j] = x;
                ((float4*)g_R)[j] = r;
                s0 += r.x * r.x; s1 += r.y * r.y; s2 += r.z * r.z; s3 += r.w * r.w;
            }
            atomicAdd(&sbin[c0 + 0], s0); atomicAdd(&sbin[c0 + 1], s1);
            atomicAdd(&sbin[c0 + 2], s2); atomicAdd(&sbin[c0 + 3], s3);
        }
        __syncthreads();
        if (tid < 128) { float v = sbin[tid]; if (v != 0.f) atomicAdd(&g_rsA[it + 1][tid], v); }
        gridbar();
    }

    // ---- AFM phases ----
    for (int n = gtid; n < N_; n += stride)
        g_isd[n] = rsqrtf(fmaxf(g_deg[n], 1e-8f));
    if (blockIdx.x == 0 && tid == 0) {
        float m = gamma[0];
        for (int i = 1; i < 4; i++) m = fmaxf(m, gamma[i]);
        float e[4], s = 0.f;
        for (int i = 0; i < 4; i++) { e[i] = expf(gamma[i] - m); s += e[i]; }
        for (int i = 0; i < 4; i++) g_aq[i] = e[i] / s;
    }
    gridbar();
    tildeL_phase(g_h, g_h, g_R, 1.f, 0.f);
    gridbar();
    tildeL_phase(g_R, g_h, g_P, 2.f, -1.f);
    gridbar();
    tildeL_phase(g_P, g_R, g_AP, 2.f, -1.f);
    gridbar();
    float s1 = 1.f / (1.f + expf(-asvr[0]));
    float s2 = 1.f / (1.f + expf(-aafm[0]));
    float a0 = __ldcg(&g_aq[0]), a1 = __ldcg(&g_aq[1]);
    float a2 = __ldcg(&g_aq[2]), a3 = __ldcg(&g_aq[3]);
    for (int j = gtid; j < NV4; j += stride) {
        float4 h = ((const float4*)g_h)[j];
        float4 x  = __ldcg((const float4*)g_X + j);
        float4 r  = __ldcg((const float4*)g_R + j);
        float4 p  = __ldcg((const float4*)g_P + j);
        float4 ap = __ldcg((const float4*)g_AP + j);
        float4 o;
        o.x = h.x + s1 * x.x + s2 * (a0 * h.x + a1 * r.x + a2 * p.x + a3 * ap.x);
        o.y = h.y + s1 * x.y + s2 * (a0 * h.y + a1 * r.y + a2 * p.y + a3 * ap.y);
        o.z = h.z + s1 * x.z + s2 * (a0 * h.z + a1 * r.z + a2 * p.z + a3 * ap.z);
        o.w = h.w + s1 * x.w + s2 * (a0 * h.w + a1 * r.w + a2 * p.w + a3 * ap.w);
        ((float4*)g_F)[j] = o;
    }
}

// ---------------- GAT aggregation ----------------
__global__ void gat1_agg_k(const float* __restrict__ b1)
{
    int node = blockIdx.x * 8 + (threadIdx.x >> 5);
    if (node >= N_) return;
    int lane = threadIdx.x & 31;
    int head = lane >> 2;
    int c0 = (lane & 3) * 2;
    float edv = g_ed1[(size_t)node * 8 + head];
    int j0 = g_inptr[node], j1 = g_inptr[node + 1];
    float m = -3.4e38f, den = 0.f, a0 = 0.f, a1 = 0.f;
    for (int j = j0; j < j1; j++) {
        int s = g_insrc[j];
        float e = g_es1[(size_t)s * 8 + head] + edv;
        e = e >= 0.f ? e : 0.2f * e;
        float mn = fmaxf(m, e);
        float sc = expf(m - mn);
        float p  = expf(e - mn);
        const float* xw = g_xw1 + (size_t)s * 64 + head * 8 + c0;
        den = den * sc + p;
        a0  = a0 * sc + p * xw[0];
        a1  = a1 * sc + p * xw[1];
        m = mn;
    }
    float inv = 1.f / (den + 1e-16f);
    float v0 = a0 * inv + b1[head * 8 + c0];
    float v1 = a1 * inv + b1[head * 8 + c0 + 1];
    v0 = v0 > 0.f ? v0 : expm1f(v0);
    v1 = v1 > 0.f ? v1 : expm1f(v1);
    float* o = g_o1 + (size_t)node * 64 + head * 8 + c0;
    o[0] = v0; o[1] = v1;
}
__global__ void gat2_agg_k(const float* __restrict__ b2, float* __restrict__ out)
{
    int node = blockIdx.x * 16 + (threadIdx.x >> 4);
    if (node >= N_) return;
    int ch = threadIdx.x & 15;
    float edv = g_ed2[node];
    int j0 = g_inptr[node], j1 = g_inptr[node + 1];
    float m = -3.4e38f, den = 0.f, acc = 0.f;
    for (int j = j0; j < j1; j++) {
        int s = g_insrc[j];
        float e = g_es2[s] + edv;
        e = e >= 0.f ? e : 0.2f * e;
        float mn = fmaxf(m, e);
        float sc = expf(m - mn);
        float p  = expf(e - mn);
        den = den * sc + p;
        acc = acc * sc + p * g_xw2[(size_t)s * 16 + ch];
        m = mn;
    }
    out[(size_t)node * 16 + ch] = acc / (den + 1e-16f) + b2[ch];
}

// ---------------- host ----------------
extern "C" void kernel_launch(void* const* d_in, const int* in_sizes, int n_in,
                              void* d_out, int out_size)
{
    const float* x      = (const float*)d_in[0];
    const int*   ei     = (const int*)d_in[1];
    const float* W_in   = (const float*)d_in[2];
    const float* b_in   = (const float*)d_in[3];
    const float* ln_g   = (const float*)d_in[4];
    const float* ln_b   = (const float*)d_in[5];
    const float* W_sh   = (const float*)d_in[6];
    const float* gamma  = (const float*)d_in[7];
    const float* asvr   = (const float*)d_in[8];
    const float* aafm   = (const float*)d_in[9];
    const float* W1     = (const float*)d_in[10];
    const float* a1s    = (const float*)d_in[11];
    const float* a1d    = (const float*)d_in[12];
    const float* b1     = (const float*)d_in[13];
    const float* W2     = (const float*)d_in[14];
    const float* a2s    = (const float*)d_in[15];
    const float* a2d    = (const float*)d_in[16];
    const float* b2     = (const float*)d_in[17];
    const int* row = ei, * col = ei + E_;
    float* out = (float*)d_out;

    const int GB = 391;

    zero3_k<<<196, 256>>>();

    // h = sigmoid(LN(x@W_in+b)); hs = h@W_sheaf  (pipelined tf32)
    gemm_lnsig_tf32_k<<<GB, 256>>>(x, W_in, b_in, ln_g, ln_b);
    gemm_sheaf_tf32_k<<<GB, 256>>>(W_sh);

    // edge weights + degrees + both CSR counts
    edge_w_k<<<16000, 256>>>(row, col);

    // CSR build: both scans + CG init in one kernel, then scatters
    scan2_k<<<1, 1024>>>();
    scatter_adj_k<<<2000, 256>>>(row, col);
    scatter_in_self_k<<<(E_ + N_ + 255) / 256, 256>>>(row, col);

    // persistent CG + AFM
    cgafm_persist_k<<<CGRID_, 256>>>(gamma, asvr, aafm);

    // GAT layer 1
    gemm_gat1_tf32_k<<<GB, 256>>>(W1, a1s, a1d);
    gat1_agg_k<<<6250, 256>>>(b1);

    // GAT layer 2
    xw2_coeff_k<<<3125, 256>>>(W2, a2s, a2d);
    gat2_agg_k<<<3125, 256>>>(b2, out);
}